// round 8
// baseline (speedup 1.0000x reference)
#include <cuda_runtime.h>
#include <cuda_bf16.h>
#include <cstdint>

// ---------------- problem constants ----------------
#define NU 100000
#define NI 100000
#define NN 100000   // NU == NI
#define FU 96
#define FI 160
#define HD 128
#define OD 64
#define EMAX 600000
#define NBLK 391   // ceil(100000/256)

// ---------------- scratch (device globals) ----------------
__device__ float g_hu   [NN * HD];
__device__ float g_hi   [NN * HD];
__device__ float g_hu1  [NN * HD];
__device__ float g_hi1  [NN * HD];
__device__ float g_proj_u[NN * OD];
__device__ float g_root_u[NN * OD];
__device__ float g_proj_i[NN * OD];
__device__ float g_root_i[NN * OD];
__device__ int   g_cnt [2 * NN];
__device__ int   g_off [2 * NN];
__device__ int   g_pos [2 * NN];
__device__ int   g_csr_iu[EMAX];
__device__ int   g_csr_ui[EMAX];
__device__ int   g_part[2 * 512];

// transposed/split bf16 weights: layout [N rows, Kpad cols], zero padded
__device__ __nv_bfloat16 g_wpu_h[128 * 128],  g_wpu_l[128 * 128];
__device__ __nv_bfloat16 g_wpi_h[128 * 192],  g_wpi_l[128 * 192];
__device__ __nv_bfloat16 g_wl0ui_h[128 * 128], g_wl0ui_l[128 * 128];
__device__ __nv_bfloat16 g_wr0ui_h[128 * 128], g_wr0ui_l[128 * 128];
__device__ __nv_bfloat16 g_wl0iu_h[128 * 128], g_wl0iu_l[128 * 128];
__device__ __nv_bfloat16 g_wr0iu_h[128 * 128], g_wr0iu_l[128 * 128];
__device__ __nv_bfloat16 g_w1u_h[128 * 128],  g_w1u_l[128 * 128];   // [Wl1_ui | Wr1_iu]
__device__ __nv_bfloat16 g_w1i_h[128 * 128],  g_w1i_l[128 * 128];   // [Wl1_iu | Wr1_ui]

// ---------------- helpers ----------------
__device__ __forceinline__ uint32_t smem_u32(const void* p) {
    uint32_t a;
    asm("{ .reg .u64 t; cvta.to.shared.u64 t, %1; cvt.u32.u64 %0, t; }" : "=r"(a) : "l"(p));
    return a;
}
#define SWZ(x) ((x) ^ (((x) >> 3) & 0x70))

#define CPA16(dst, src) \
    asm volatile("cp.async.ca.shared.global [%0], [%1], 16;" :: "r"(dst), "l"(src) : "memory")
#define CPA_COMMIT() asm volatile("cp.async.commit_group;" ::: "memory")
#define CPA_WAIT1()  asm volatile("cp.async.wait_group 1;" ::: "memory")
#define CPA_WAIT0()  asm volatile("cp.async.wait_group 0;" ::: "memory")

__device__ __forceinline__ void ldm4(uint32_t* r, uint32_t addr) {
    asm volatile("ldmatrix.sync.aligned.m8n8.x4.shared.b16 {%0,%1,%2,%3}, [%4];"
        : "=r"(r[0]), "=r"(r[1]), "=r"(r[2]), "=r"(r[3]) : "r"(addr));
}
__device__ __forceinline__ void mma_bf16(float* c, const uint32_t* a, uint32_t b0, uint32_t b1) {
    asm volatile("mma.sync.aligned.m16n8k16.row.col.f32.bf16.bf16.f32 "
        "{%0,%1,%2,%3}, {%4,%5,%6,%7}, {%8,%9}, {%0,%1,%2,%3};"
        : "+f"(c[0]), "+f"(c[1]), "+f"(c[2]), "+f"(c[3])
        : "r"(a[0]), "r"(a[1]), "r"(a[2]), "r"(a[3]), "r"(b0), "r"(b1));
}
__device__ __forceinline__ uint32_t pack_bf16x2(float x0, float x1) {
    __nv_bfloat16 b0 = __float2bfloat16(x0);
    __nv_bfloat16 b1 = __float2bfloat16(x1);
    return (uint32_t)__bfloat16_as_ushort(b0) | ((uint32_t)__bfloat16_as_ushort(b1) << 16);
}

// ---------------- CSR build chain ----------------
__global__ void zero_cnt_kernel(int* __restrict__ cnt) {
    int i = blockIdx.x * blockDim.x + threadIdx.x;
    if (i < 2 * NN) cnt[i] = 0;
}

__global__ void count_kernel(const int* __restrict__ dst0, const int* __restrict__ dst1,
                             int E, int* __restrict__ cnt) {
    int t = blockIdx.y;
    const int* dst = t ? dst1 : dst0;
    int* c = cnt + t * NN;
    int e = blockIdx.x * blockDim.x + threadIdx.x;
    if (e < E) atomicAdd(&c[dst[e]], 1);
}

__global__ void scan_part_kernel(const int* __restrict__ cnt, int* __restrict__ part) {
    __shared__ int sh[256];
    const int* c = cnt + blockIdx.y * NN;
    int* p = part + blockIdx.y * 512;
    int i = blockIdx.x * 256 + threadIdx.x;
    sh[threadIdx.x] = (i < NN) ? c[i] : 0;
    __syncthreads();
    for (int s = 128; s > 0; s >>= 1) {
        if (threadIdx.x < s) sh[threadIdx.x] += sh[threadIdx.x + s];
        __syncthreads();
    }
    if (threadIdx.x == 0) p[blockIdx.x] = sh[0];
}

__global__ void scan_partials_kernel(int* __restrict__ part, int nb) {
    __shared__ int sh[512];
    int* p = part + blockIdx.y * 512;
    int t = threadIdx.x;
    int v = (t < nb) ? p[t] : 0;
    sh[t] = v;
    __syncthreads();
    for (int o = 1; o < 512; o <<= 1) {
        int x = (t >= o) ? sh[t - o] : 0;
        __syncthreads();
        sh[t] += x;
        __syncthreads();
    }
    if (t < nb) p[t] = sh[t] - v;  // exclusive
}

__global__ void scan_final_kernel(const int* __restrict__ cnt, const int* __restrict__ part,
                                  int* __restrict__ off, int* __restrict__ pos) {
    __shared__ int sh[256];
    const int* c = cnt + blockIdx.y * NN;
    const int* p = part + blockIdx.y * 512;
    int* of = off + blockIdx.y * NN;
    int* ps = pos + blockIdx.y * NN;
    int t = threadIdx.x;
    int i = blockIdx.x * 256 + t;
    int v = (i < NN) ? c[i] : 0;
    sh[t] = v;
    __syncthreads();
    for (int o = 1; o < 256; o <<= 1) {
        int x = (t >= o) ? sh[t - o] : 0;
        __syncthreads();
        sh[t] += x;
        __syncthreads();
    }
    if (i < NN) {
        int e = sh[t] - v + p[blockIdx.x];
        of[i] = e;
        ps[i] = e;
    }
}

__global__ void build_csr_kernel(const int* __restrict__ e0, const int* __restrict__ e1,
                                 int E, int* __restrict__ pos,
                                 int* __restrict__ c0, int* __restrict__ c1) {
    int t = blockIdx.y;
    const int* edge = t ? e1 : e0;
    int* ps = pos + t * NN;
    int* csr = t ? c1 : c0;
    int e = blockIdx.x * blockDim.x + threadIdx.x;
    if (e < E) {
        int s = edge[e];
        int d = edge[E + e];
        int idx = atomicAdd(&ps[d], 1);
        csr[idx] = s;
    }
}

// ---------------- fused layer-1 gather + final LN ----------------
// warp per dst row: acc = mean over neighbors of proj_src (stride 64), v = acc + root[row] + bias, out = LN(v)
struct FSide { const float* proj_src; const float* root; const int* csr;
               const float* bias; const float* g; const float* b; float* out; };
__global__ void final_fused_kernel(FSide f0, FSide f1, const int* __restrict__ off, const int* __restrict__ cnt) {
    const int t = blockIdx.y;
    FSide s = t ? f1 : f0;
    const int* of = off + t * NN;
    const int* cn = cnt + t * NN;
    const int warp = threadIdx.x >> 5;
    const int lane = threadIdx.x & 31;
    const int row = blockIdx.x * 8 + warp;
    if (row >= NN) return;
    const int c = lane * 2;
    const int beg = __ldg(&of[row]);
    const int deg = __ldg(&cn[row]);

    float x0 = 0.f, y0 = 0.f, x1 = 0.f, y1 = 0.f;
    int e = 0;
    for (; e + 1 < deg; e += 2) {
        int s0 = __ldg(&s.csr[beg + e]);
        int s1 = __ldg(&s.csr[beg + e + 1]);
        float2 v0 = *(const float2*)(s.proj_src + (size_t)s0 * OD + c);
        float2 v1 = *(const float2*)(s.proj_src + (size_t)s1 * OD + c);
        x0 += v0.x; y0 += v0.y;
        x1 += v1.x; y1 += v1.y;
    }
    if (e < deg) {
        int s0 = __ldg(&s.csr[beg + e]);
        float2 v0 = *(const float2*)(s.proj_src + (size_t)s0 * OD + c);
        x0 += v0.x; y0 += v0.y;
    }
    const float sc = 1.0f / fmaxf((float)deg, 1.0f);
    float2 rv = *(const float2*)(s.root + (size_t)row * OD + c);
    float2 bv = __ldg((const float2*)(s.bias + c));
    float v0 = (x0 + x1) * sc + rv.x + bv.x;
    float v1 = (y0 + y1) * sc + rv.y + bv.y;

    float s1v = v0 + v1;
    float s2v = v0 * v0 + v1 * v1;
#pragma unroll
    for (int o = 16; o > 0; o >>= 1) {
        s1v += __shfl_xor_sync(0xFFFFFFFFu, s1v, o);
        s2v += __shfl_xor_sync(0xFFFFFFFFu, s2v, o);
    }
    float mean = s1v * (1.0f / 64.0f);
    float var = s2v * (1.0f / 64.0f) - mean * mean;
    float rstd = rsqrtf(var + 1e-5f);
    float2 gv = __ldg((const float2*)(s.g + c));
    float2 bb = __ldg((const float2*)(s.b + c));
    float2 o2;
    o2.x = (v0 - mean) * rstd * gv.x + bb.x;
    o2.y = (v1 - mean) * rstd * gv.y + bb.y;
    *(float2*)(s.out + (size_t)row * 64 + c) = o2;
}

// weight transpose + bf16 hi/lo split
struct WCon { const float* w; __nv_bfloat16* h; __nv_bfloat16* l; int K, N, Kpad; };
struct WCon10 { WCon s[10]; };
__global__ void wconv_kernel(WCon10 P) {
    WCon w = P.s[blockIdx.y];
    int idx = blockIdx.x * blockDim.x + threadIdx.x;
    if (idx >= w.N * w.Kpad) return;
    int n = idx / w.Kpad, k = idx % w.Kpad;
    float x = (k < w.K) ? w.w[(size_t)k * w.N + n] : 0.0f;
    __nv_bfloat16 h = __float2bfloat16(x);
    w.h[idx] = h;
    w.l[idx] = __float2bfloat16(x - __bfloat162float(h));
}

// ---------------- HMMA (mma.sync) GEMM, BN=128, 4x2 warp tiling, paired via gridDim.y ----------------
// B tiles double-buffered via cp.async. A staged synchronously (fp32 -> bf16 hi/lo split).
// GATHER: A1 chunks are CSR gather-mean of gfeat (fuses the aggregation).
// SPLIT: epilogue writes cols 0-63 -> out (stride 64), cols 64-127 -> out2 (stride 64).
#define BN 128

struct GSide {
    const float* A1; const __nv_bfloat16* W1h; const __nv_bfloat16* W1l; int K1; int K1pad;
    const float* A2; const __nv_bfloat16* W2h; const __nv_bfloat16* W2l; int K2; int K2pad;
    const float* gfeat; const int* gcsr; const int* goff; const int* gcnt;
    const float* bias; const float* gamma; const float* beta; float* out; float* out2;
};

template <bool FUSE2, bool GATHER, bool SPLIT, bool DO_LN, bool DO_RELU>
__global__ __launch_bounds__(256, 2)
void mma_gemm(GSide s0, GSide s1, int M) {
    const GSide& S = blockIdx.y ? s1 : s0;

    extern __shared__ char smem[];
    const uint32_t sb = smem_u32(smem);
    const uint32_t aHiB = sb;
    const uint32_t aLoB = sb + 16384;
    const uint32_t bBuf0 = sb + 32768;   // bHi at +0, bLo at +16384; buffer stride 32768

    const int tid = threadIdx.x;
    const int warp = tid >> 5;
    const int lane = tid & 31;
    const int wm = warp & 3;
    const int wn = warp >> 2;
    const int r0 = blockIdx.x * 128;

    float acc[2][8][4];
#pragma unroll
    for (int mt = 0; mt < 2; mt++)
#pragma unroll
        for (int nt = 0; nt < 8; nt++)
#pragma unroll
            for (int j = 0; j < 4; j++) acc[mt][nt][j] = 0.0f;

    // staging mapping
    const int ar = tid >> 1;
    const int acb = (tid & 1) * 32;
    const int bn = tid >> 1;
    const int bq = tid & 1;

    // compute-phase lane constants
    const uint32_t a_off0 = (uint32_t)(wm * 32 + (lane & 15)) * 128;
    const uint32_t a_off1 = a_off0 + 16 * 128;
    const uint32_t a_xm = (lane & 7) * 16;
    const uint32_t a_khalf = ((lane >> 4) & 1) * 16;
    const uint32_t b_rowbase = (uint32_t)(wn * 64 + (lane & 7) + ((lane >> 4) & 1) * 8) * 128;
    const uint32_t b_xm = (lane & 7) * 16;
    const uint32_t b_khalf = ((lane >> 3) & 1) * 16;

    const int nch1 = S.K1pad >> 6;
    const int nch = nch1 + (FUSE2 ? (S.K2pad >> 6) : 0);

    auto issueB = [&](int c, int buf) {
        const __nv_bfloat16 *Wh, *Wl;
        int k0, Kpad;
        if (!FUSE2 || c < nch1) { Wh = S.W1h; Wl = S.W1l; k0 = c * 64; Kpad = S.K1pad; }
        else                    { Wh = S.W2h; Wl = S.W2l; k0 = (c - nch1) * 64; Kpad = S.K2pad; }
        const uint32_t bH = bBuf0 + (uint32_t)buf * 32768;
        const uint32_t bL = bH + 16384;
#pragma unroll
        for (int i = 0; i < 4; i++) {
            const int ck = bq * 32 + i * 8;
            const size_t so = (size_t)bn * Kpad + k0 + ck;
            const uint32_t off = SWZ(bn * 128 + ck * 2);
            CPA16(bH + off, Wh + so);
            CPA16(bL + off, Wl + so);
        }
        CPA_COMMIT();
    };

    issueB(0, 0);

    for (int c = 0; c < nch; c++) {
        if (c) __syncthreads();

        // ---- stage A ----
        if (GATHER && c < nch1) {
            // fused CSR gather-mean of gfeat cols [k0+acb, k0+acb+32)
            const int grow = r0 + ar;
            const int k0 = c * 64;
            int beg = 0, deg = 0;
            if (grow < M) { beg = __ldg(&S.goff[grow]); deg = __ldg(&S.gcnt[grow]); }
            const float sc = 1.0f / fmaxf((float)deg, 1.0f);
#pragma unroll
            for (int pass = 0; pass < 2; pass++) {
                const int cc = acb + pass * 16;
                const float* fb = S.gfeat + k0 + cc;
                float4 a4[4];
                a4[0] = make_float4(0.f, 0.f, 0.f, 0.f);
                a4[1] = a4[0]; a4[2] = a4[0]; a4[3] = a4[0];
                for (int e = 0; e < deg; e++) {
                    const float4* p = (const float4*)(fb + (size_t)__ldg(&S.gcsr[beg + e]) * HD);
                    float4 v0 = p[0], v1 = p[1], v2 = p[2], v3 = p[3];
                    a4[0].x += v0.x; a4[0].y += v0.y; a4[0].z += v0.z; a4[0].w += v0.w;
                    a4[1].x += v1.x; a4[1].y += v1.y; a4[1].z += v1.z; a4[1].w += v1.w;
                    a4[2].x += v2.x; a4[2].y += v2.y; a4[2].z += v2.z; a4[2].w += v2.w;
                    a4[3].x += v3.x; a4[3].y += v3.y; a4[3].z += v3.z; a4[3].w += v3.w;
                }
                uint32_t h8[8], l8[8];
                const float* af = (const float*)a4;
#pragma unroll
                for (int j = 0; j < 8; j++) {
                    float x0 = af[2 * j] * sc;
                    float x1 = af[2 * j + 1] * sc;
                    __nv_bfloat16 b0 = __float2bfloat16(x0);
                    __nv_bfloat16 b1 = __float2bfloat16(x1);
                    h8[j] = (uint32_t)__bfloat16_as_ushort(b0) | ((uint32_t)__bfloat16_as_ushort(b1) << 16);
                    l8[j] = pack_bf16x2(x0 - __bfloat162float(b0), x1 - __bfloat162float(b1));
                }
                const uint32_t base = ar * 128 + cc * 2;
                const uint32_t o0 = SWZ(base), o1 = SWZ(base + 16);
                asm volatile("st.shared.v4.b32 [%0], {%1, %2, %3, %4};" :: "r"(aHiB + o0), "r"(h8[0]), "r"(h8[1]), "r"(h8[2]), "r"(h8[3]) : "memory");
                asm volatile("st.shared.v4.b32 [%0], {%1, %2, %3, %4};" :: "r"(aHiB + o1), "r"(h8[4]), "r"(h8[5]), "r"(h8[6]), "r"(h8[7]) : "memory");
                asm volatile("st.shared.v4.b32 [%0], {%1, %2, %3, %4};" :: "r"(aLoB + o0), "r"(l8[0]), "r"(l8[1]), "r"(l8[2]), "r"(l8[3]) : "memory");
                asm volatile("st.shared.v4.b32 [%0], {%1, %2, %3, %4};" :: "r"(aLoB + o1), "r"(l8[4]), "r"(l8[5]), "r"(l8[6]), "r"(l8[7]) : "memory");
            }
        } else {
            const float* A;
            int k0, K;
            if (!FUSE2 || c < nch1) { A = S.A1; k0 = c * 64; K = S.K1; }
            else                    { A = S.A2; k0 = (c - nch1) * 64; K = S.K2; }
            const int grow = r0 + ar;
            const float* arow = A + (size_t)grow * K;
#pragma unroll
            for (int i = 0; i < 4; i++) {
                const int cc = acb + i * 8;
                float x[8];
#pragma unroll
                for (int j = 0; j < 8; j++) x[j] = 0.0f;
                if (grow < M && (k0 + cc) < K) {
                    float4 v0 = *(const float4*)(arow + k0 + cc);
                    float4 v1 = *(const float4*)(arow + k0 + cc + 4);
                    x[0] = v0.x; x[1] = v0.y; x[2] = v0.z; x[3] = v0.w;
                    x[4] = v1.x; x[5] = v1.y; x[6] = v1.z; x[7] = v1.w;
                }
                uint32_t hi[4], lo[4];
#pragma unroll
                for (int j = 0; j < 4; j++) {
                    __nv_bfloat16 h0 = __float2bfloat16(x[2 * j]);
                    __nv_bfloat16 h1 = __float2bfloat16(x[2 * j + 1]);
                    hi[j] = (uint32_t)__bfloat16_as_ushort(h0) | ((uint32_t)__bfloat16_as_ushort(h1) << 16);
                    lo[j] = pack_bf16x2(x[2 * j] - __bfloat162float(h0), x[2 * j + 1] - __bfloat162float(h1));
                }
                const uint32_t off = SWZ(ar * 128 + cc * 2);
                asm volatile("st.shared.v4.b32 [%0], {%1, %2, %3, %4};" :: "r"(aHiB + off), "r"(hi[0]), "r"(hi[1]), "r"(hi[2]), "r"(hi[3]) : "memory");
                asm volatile("st.shared.v4.b32 [%0], {%1, %2, %3, %4};" :: "r"(aLoB + off), "r"(lo[0]), "r"(lo[1]), "r"(lo[2]), "r"(lo[3]) : "memory");
            }
        }

        // ---- prefetch next B, then wait for current B ----
        if (c + 1 < nch) {
            issueB(c + 1, (c + 1) & 1);
            CPA_WAIT1();
        } else {
            CPA_WAIT0();
        }
        __syncthreads();

        // ---- compute ----
        const uint32_t bHiC = bBuf0 + (uint32_t)(c & 1) * 32768;
        const uint32_t bLoC = bHiC + 16384;
#pragma unroll
        for (int ks = 0; ks < 4; ks++) {
            const uint32_t akb = ((uint32_t)(ks * 32) + a_khalf) ^ a_xm;
            uint32_t ah[2][4], al[2][4];
            ldm4(ah[0], aHiB + a_off0 + akb);
            ldm4(ah[1], aHiB + a_off1 + akb);
            ldm4(al[0], aLoB + a_off0 + akb);
            ldm4(al[1], aLoB + a_off1 + akb);
            const uint32_t bkb = ((uint32_t)(ks * 32) + b_khalf) ^ b_xm;
#pragma unroll
            for (int j = 0; j < 4; j++) {
                uint32_t bh[4], bl[4];
                const uint32_t boff = b_rowbase + (uint32_t)j * 2048;
                ldm4(bh, bHiC + boff + bkb);
                ldm4(bl, bLoC + boff + bkb);
#pragma unroll
                for (int mt = 0; mt < 2; mt++) {
                    mma_bf16(acc[mt][2 * j],     ah[mt], bh[0], bh[1]);
                    mma_bf16(acc[mt][2 * j],     ah[mt], bl[0], bl[1]);
                    mma_bf16(acc[mt][2 * j],     al[mt], bh[0], bh[1]);
                    mma_bf16(acc[mt][2 * j + 1], ah[mt], bh[2], bh[3]);
                    mma_bf16(acc[mt][2 * j + 1], ah[mt], bl[2], bl[3]);
                    mma_bf16(acc[mt][2 * j + 1], al[mt], bh[2], bh[3]);
                }
            }
        }
    }

    // ---- epilogue ----
    const int rq = lane >> 2;
    const int cq = (lane & 3) * 2;

    if (S.bias) {
#pragma unroll
        for (int nt = 0; nt < 8; nt++) {
            float2 bv = __ldg((const float2*)(S.bias + wn * 64 + nt * 8 + cq));
#pragma unroll
            for (int mt = 0; mt < 2; mt++) {
                acc[mt][nt][0] += bv.x; acc[mt][nt][1] += bv.y;
                acc[mt][nt][2] += bv.x; acc[mt][nt][3] += bv.y;
            }
        }
    }
    if (DO_LN) {
        float s1[2][2], s2[2][2];
#pragma unroll
        for (int mt = 0; mt < 2; mt++)
#pragma unroll
            for (int h = 0; h < 2; h++) { s1[mt][h] = 0.f; s2[mt][h] = 0.f; }
#pragma unroll
        for (int mt = 0; mt < 2; mt++)
#pragma unroll
            for (int nt = 0; nt < 8; nt++) {
                s1[mt][0] += acc[mt][nt][0] + acc[mt][nt][1];
                s2[mt][0] += acc[mt][nt][0] * acc[mt][nt][0] + acc[mt][nt][1] * acc[mt][nt][1];
                s1[mt][1] += acc[mt][nt][2] + acc[mt][nt][3];
                s2[mt][1] += acc[mt][nt][2] * acc[mt][nt][2] + acc[mt][nt][3] * acc[mt][nt][3];
            }
#pragma unroll
        for (int o = 1; o < 4; o <<= 1) {
#pragma unroll
            for (int mt = 0; mt < 2; mt++)
#pragma unroll
                for (int h = 0; h < 2; h++) {
                    s1[mt][h] += __shfl_xor_sync(0xFFFFFFFFu, s1[mt][h], o);
                    s2[mt][h] += __shfl_xor_sync(0xFFFFFFFFu, s2[mt][h], o);
                }
        }
        float* sc = (float*)smem;
        __syncthreads();
        if ((lane & 3) == 0) {
#pragma unroll
            for (int mt = 0; mt < 2; mt++)
#pragma unroll
                for (int h = 0; h < 2; h++) {
                    int rl = wm * 32 + mt * 16 + h * 8 + rq;
                    sc[wn * 128 + rl] = s1[mt][h];
                    sc[256 + wn * 128 + rl] = s2[mt][h];
                }
        }
        __syncthreads();
#pragma unroll
        for (int mt = 0; mt < 2; mt++)
#pragma unroll
            for (int h = 0; h < 2; h++) {
                int rl = wm * 32 + mt * 16 + h * 8 + rq;
                float S1 = sc[rl] + sc[128 + rl];
                float S2 = sc[256 + rl] + sc[384 + rl];
                float mean = S1 * (1.0f / 128.0f);
                float var = S2 * (1.0f / 128.0f) - mean * mean;
                float rstd = rsqrtf(var + 1e-5f);
                s1[mt][h] = mean;
                s2[mt][h] = rstd;
            }
#pragma unroll
        for (int nt = 0; nt < 8; nt++) {
            float2 g = __ldg((const float2*)(S.gamma + wn * 64 + nt * 8 + cq));
            float2 b = __ldg((const float2*)(S.beta + wn * 64 + nt * 8 + cq));
#pragma unroll
            for (int mt = 0; mt < 2; mt++) {
                acc[mt][nt][0] = (acc[mt][nt][0] - s1[mt][0]) * s2[mt][0] * g.x + b.x;
                acc[mt][nt][1] = (acc[mt][nt][1] - s1[mt][0]) * s2[mt][0] * g.y + b.y;
                acc[mt][nt][2] = (acc[mt][nt][2] - s1[mt][1]) * s2[mt][1] * g.x + b.x;
                acc[mt][nt][3] = (acc[mt][nt][3] - s1[mt][1]) * s2[mt][1] * g.y + b.y;
            }
        }
    }
    if (DO_RELU) {
#pragma unroll
        for (int mt = 0; mt < 2; mt++)
#pragma unroll
            for (int nt = 0; nt < 8; nt++)
#pragma unroll
                for (int j = 0; j < 4; j++) acc[mt][nt][j] = fmaxf(acc[mt][nt][j], 0.0f);
    }
    if (SPLIT) {
        float* dst = wn ? S.out2 : S.out;
#pragma unroll
        for (int mt = 0; mt < 2; mt++)
#pragma unroll
            for (int h = 0; h < 2; h++) {
                int row = r0 + wm * 32 + mt * 16 + h * 8 + rq;
                if (row < M) {
#pragma unroll
                    for (int nt = 0; nt < 8; nt++)
                        *(float2*)(dst + (size_t)row * 64 + nt * 8 + cq) =
                            make_float2(acc[mt][nt][2 * h], acc[mt][nt][2 * h + 1]);
                }
            }
    } else {
#pragma unroll
        for (int mt = 0; mt < 2; mt++)
#pragma unroll
            for (int h = 0; h < 2; h++) {
                int row = r0 + wm * 32 + mt * 16 + h * 8 + rq;
                if (row < M) {
#pragma unroll
                    for (int nt = 0; nt < 8; nt++)
                        *(float2*)(S.out + (size_t)row * BN + wn * 64 + nt * 8 + cq) =
                            make_float2(acc[mt][nt][2 * h], acc[mt][nt][2 * h + 1]);
                }
            }
    }
}

// ---------------- host launcher ----------------
extern "C" void kernel_launch(void* const* d_in, const int* in_sizes, int n_in,
                              void* d_out, int out_size) {
    const float* x_user = (const float*)d_in[0];
    const float* x_item = (const float*)d_in[1];
    const int* edge_ui = (const int*)d_in[2];
    const int* edge_iu = (const int*)d_in[3];
    const float* Wp_u = (const float*)d_in[4];
    const float* bp_u = (const float*)d_in[5];
    const float* Wp_i = (const float*)d_in[6];
    const float* bp_i = (const float*)d_in[7];
    const float* Wl0_ui = (const float*)d_in[8];
    const float* bl0_ui = (const float*)d_in[9];
    const float* Wr0_ui = (const float*)d_in[10];
    const float* Wl0_iu = (const float*)d_in[11];
    const float* bl0_iu = (const float*)d_in[12];
    const float* Wr0_iu = (const float*)d_in[13];
    const float* g0_u = (const float*)d_in[14];
    const float* b0_u = (const float*)d_in[15];
    const float* g0_i = (const float*)d_in[16];
    const float* b0_i = (const float*)d_in[17];
    const float* Wl1_ui = (const float*)d_in[18];
    const float* bl1_ui = (const float*)d_in[19];
    const float* Wr1_ui = (const float*)d_in[20];
    const float* Wl1_iu = (const float*)d_in[21];
    const float* bl1_iu = (const float*)d_in[22];
    const float* Wr1_iu = (const float*)d_in[23];
    const float* g1_u = (const float*)d_in[24];
    const float* b1_u = (const float*)d_in[25];
    const float* g1_i = (const float*)d_in[26];
    const float* b1_i = (const float*)d_in[27];

    const int E = in_sizes[2] / 2;

    float *hu, *hi, *hu1, *hi1, *proj_u, *root_u, *proj_i, *root_i;
    int *cnt, *off, *pos, *csr_iu, *csr_ui, *part;
    cudaGetSymbolAddress((void**)&hu, g_hu);
    cudaGetSymbolAddress((void**)&hi, g_hi);
    cudaGetSymbolAddress((void**)&hu1, g_hu1);
    cudaGetSymbolAddress((void**)&hi1, g_hi1);
    cudaGetSymbolAddress((void**)&proj_u, g_proj_u);
    cudaGetSymbolAddress((void**)&root_u, g_root_u);
    cudaGetSymbolAddress((void**)&proj_i, g_proj_i);
    cudaGetSymbolAddress((void**)&root_i, g_root_i);
    cudaGetSymbolAddress((void**)&cnt, g_cnt);
    cudaGetSymbolAddress((void**)&off, g_off);
    cudaGetSymbolAddress((void**)&pos, g_pos);
    cudaGetSymbolAddress((void**)&csr_iu, g_csr_iu);
    cudaGetSymbolAddress((void**)&csr_ui, g_csr_ui);
    cudaGetSymbolAddress((void**)&part, g_part);

    __nv_bfloat16 *wpu_h, *wpu_l, *wpi_h, *wpi_l;
    __nv_bfloat16 *wl0ui_h, *wl0ui_l, *wr0ui_h, *wr0ui_l, *wl0iu_h, *wl0iu_l, *wr0iu_h, *wr0iu_l;
    __nv_bfloat16 *w1u_h, *w1u_l, *w1i_h, *w1i_l;
    cudaGetSymbolAddress((void**)&wpu_h, g_wpu_h);   cudaGetSymbolAddress((void**)&wpu_l, g_wpu_l);
    cudaGetSymbolAddress((void**)&wpi_h, g_wpi_h);   cudaGetSymbolAddress((void**)&wpi_l, g_wpi_l);
    cudaGetSymbolAddress((void**)&wl0ui_h, g_wl0ui_h); cudaGetSymbolAddress((void**)&wl0ui_l, g_wl0ui_l);
    cudaGetSymbolAddress((void**)&wr0ui_h, g_wr0ui_h); cudaGetSymbolAddress((void**)&wr0ui_l, g_wr0ui_l);
    cudaGetSymbolAddress((void**)&wl0iu_h, g_wl0iu_h); cudaGetSymbolAddress((void**)&wl0iu_l, g_wl0iu_l);
    cudaGetSymbolAddress((void**)&wr0iu_h, g_wr0iu_h); cudaGetSymbolAddress((void**)&wr0iu_l, g_wr0iu_l);
    cudaGetSymbolAddress((void**)&w1u_h, g_w1u_h);   cudaGetSymbolAddress((void**)&w1u_l, g_w1u_l);
    cudaGetSymbolAddress((void**)&w1i_h, g_w1i_h);   cudaGetSymbolAddress((void**)&w1i_l, g_w1i_l);

    float* out_u = (float*)d_out;
    float* out_i = (float*)d_out + (size_t)NN * OD;

    const int SM = 98304;  // A 32KB + B 2x32KB
    cudaFuncSetAttribute(mma_gemm<false, false, false, false, true>, cudaFuncAttributeMaxDynamicSharedMemorySize, SM);
    cudaFuncSetAttribute(mma_gemm<true, true, false, true, true>, cudaFuncAttributeMaxDynamicSharedMemorySize, SM);
    cudaFuncSetAttribute(mma_gemm<false, false, true, false, false>, cudaFuncAttributeMaxDynamicSharedMemorySize, SM);

    const int GM = (NN + 127) / 128;

    // fork a side stream for the CSR chain (independent of weights/proj)
    cudaStream_t sB;
    cudaEvent_t eFork, eJoin;
    cudaStreamCreateWithFlags(&sB, cudaStreamNonBlocking);
    cudaEventCreateWithFlags(&eFork, cudaEventDisableTiming);
    cudaEventCreateWithFlags(&eJoin, cudaEventDisableTiming);

    cudaEventRecord(eFork, 0);
    cudaStreamWaitEvent(sB, eFork, 0);

    // side stream: degree + CSR build
    {
        dim3 ge((E + 255) / 256, 2);
        zero_cnt_kernel<<<(2 * NN + 255) / 256, 256, 0, sB>>>(cnt);
        count_kernel<<<ge, 256, 0, sB>>>(edge_iu + E, edge_ui + E, E, cnt);
        scan_part_kernel<<<dim3(NBLK, 2), 256, 0, sB>>>(cnt, part);
        scan_partials_kernel<<<dim3(1, 2), 512, 0, sB>>>(part, NBLK);
        scan_final_kernel<<<dim3(NBLK, 2), 256, 0, sB>>>(cnt, part, off, pos);
        build_csr_kernel<<<ge, 256, 0, sB>>>(edge_iu, edge_ui, E, pos, csr_iu, csr_ui);
        cudaEventRecord(eJoin, sB);
    }

    // main stream: weight convert + projection GEMM pair
    {
        WCon10 P;
        P.s[0] = { Wp_u,   wpu_h,   wpu_l,   FU, HD, 128 };
        P.s[1] = { Wp_i,   wpi_h,   wpi_l,   FI, HD, 192 };
        P.s[2] = { Wl0_ui, wl0ui_h, wl0ui_l, HD, HD, 128 };
        P.s[3] = { Wr0_ui, wr0ui_h, wr0ui_l, HD, HD, 128 };
        P.s[4] = { Wl0_iu, wl0iu_h, wl0iu_l, HD, HD, 128 };
        P.s[5] = { Wr0_iu, wr0iu_h, wr0iu_l, HD, HD, 128 };
        P.s[6] = { Wl1_ui, w1u_h,             w1u_l,             HD, OD, 128 };
        P.s[7] = { Wr1_iu, w1u_h + 64 * 128,  w1u_l + 64 * 128,  HD, OD, 128 };
        P.s[8] = { Wl1_iu, w1i_h,             w1i_l,             HD, OD, 128 };
        P.s[9] = { Wr1_ui, w1i_h + 64 * 128,  w1i_l + 64 * 128,  HD, OD, 128 };
        dim3 g((192 * 128 + 255) / 256, 10);
        wconv_kernel<<<g, 256>>>(P);
    }
    {
        GSide su = { x_user, wpu_h, wpu_l, FU, 128, nullptr, nullptr, nullptr, 0, 0,
                     nullptr, nullptr, nullptr, nullptr,
                     bp_u, nullptr, nullptr, hu, nullptr };
        GSide si = { x_item, wpi_h, wpi_l, FI, 192, nullptr, nullptr, nullptr, 0, 0,
                     nullptr, nullptr, nullptr, nullptr,
                     bp_i, nullptr, nullptr, hi, nullptr };
        mma_gemm<false, false, false, false, true><<<dim3(GM, 2), 256, SM>>>(su, si, NN);
    }

    // join: layer0 GEMM gathers via CSR
    cudaStreamWaitEvent(0, eJoin, 0);

    // layer 0: fused gather + dual-GEMM + bias + LN + ReLU
    // side i: A1 = gather(hu via csr_ui, off+NN, cnt+NN), A2 = hi
    // side u: A1 = gather(hi via csr_iu, off, cnt),       A2 = hu
    {
        GSide si = { nullptr, wl0ui_h, wl0ui_l, HD, 128, hi, wr0ui_h, wr0ui_l, HD, 128,
                     hu, csr_ui, off + NN, cnt + NN,
                     bl0_ui, g0_i, b0_i, hi1, nullptr };
        GSide su = { nullptr, wl0iu_h, wl0iu_l, HD, 128, hu, wr0iu_h, wr0iu_l, HD, 128,
                     hi, csr_iu, off, cnt,
                     bl0_iu, g0_u, b0_u, hu1, nullptr };
        mma_gemm<true, true, false, true, true><<<dim3(GM, 2), 256, SM>>>(si, su, NN);
    }

    // layer 1 combined GEMM pair: [proj|root] = h1 @ [Wl1 | Wr1], split into stride-64 arrays
    {
        GSide su = { hu1, w1u_h, w1u_l, HD, 128, nullptr, nullptr, nullptr, 0, 0,
                     nullptr, nullptr, nullptr, nullptr,
                     nullptr, nullptr, nullptr, proj_u, root_u };
        GSide si = { hi1, w1i_h, w1i_l, HD, 128, nullptr, nullptr, nullptr, 0, 0,
                     nullptr, nullptr, nullptr, nullptr,
                     nullptr, nullptr, nullptr, proj_i, root_i };
        mma_gemm<false, false, true, false, false><<<dim3(GM, 2), 256, SM>>>(su, si, NN);
    }

    // fused layer-1 gather + final LN
    {
        FSide fu = { proj_i, root_u, csr_iu, bl1_iu, g1_u, b1_u, out_u };
        FSide fi = { proj_u, root_i, csr_ui, bl1_ui, g1_i, b1_i, out_i };
        dim3 gf((NN + 7) / 8, 2);
        final_fused_kernel<<<gf, 256>>>(fu, fi, off, cnt);
    }

    (void)n_in; (void)out_size; (void)in_sizes;
}

// round 9
// speedup vs baseline: 1.1418x; 1.1418x over previous
#include <cuda_runtime.h>
#include <cuda_bf16.h>
#include <cstdint>

// ---------------- problem constants ----------------
#define NU 100000
#define NI 100000
#define NN 100000   // NU == NI
#define FU 96
#define FI 160
#define HD 128
#define OD 64
#define EMAX 600000
#define NBLK 391   // ceil(100000/256)

// ---------------- scratch (device globals) ----------------
__device__ float g_hu   [NN * HD];
__device__ float g_hi   [NN * HD];
__device__ float g_agg_u[NN * HD];
__device__ float g_agg_i[NN * HD];
__device__ float g_hu1  [NN * HD];
__device__ float g_hi1  [NN * HD];
__device__ float g_proj_u[NN * OD];
__device__ float g_root_u[NN * OD];
__device__ float g_proj_i[NN * OD];
__device__ float g_root_i[NN * OD];
__device__ int   g_cnt [2 * NN];
__device__ int   g_off [2 * NN];
__device__ int   g_pos [2 * NN];
__device__ int   g_csr_iu[EMAX];
__device__ int   g_csr_ui[EMAX];
__device__ int   g_part[2 * 512];

// transposed/split bf16 weights: layout [N rows, Kpad cols], zero padded
__device__ __nv_bfloat16 g_wpu_h[128 * 128],  g_wpu_l[128 * 128];
__device__ __nv_bfloat16 g_wpi_h[128 * 192],  g_wpi_l[128 * 192];
__device__ __nv_bfloat16 g_wl0ui_h[128 * 128], g_wl0ui_l[128 * 128];
__device__ __nv_bfloat16 g_wr0ui_h[128 * 128], g_wr0ui_l[128 * 128];
__device__ __nv_bfloat16 g_wl0iu_h[128 * 128], g_wl0iu_l[128 * 128];
__device__ __nv_bfloat16 g_wr0iu_h[128 * 128], g_wr0iu_l[128 * 128];
__device__ __nv_bfloat16 g_w1u_h[128 * 128],  g_w1u_l[128 * 128];   // [Wl1_ui | Wr1_iu]
__device__ __nv_bfloat16 g_w1i_h[128 * 128],  g_w1i_l[128 * 128];   // [Wl1_iu | Wr1_ui]

// ---------------- helpers ----------------
__device__ __forceinline__ uint32_t smem_u32(const void* p) {
    uint32_t a;
    asm("{ .reg .u64 t; cvta.to.shared.u64 t, %1; cvt.u32.u64 %0, t; }" : "=r"(a) : "l"(p));
    return a;
}
#define SWZ(x) ((x) ^ (((x) >> 3) & 0x70))

#define CPA16(dst, src) \
    asm volatile("cp.async.ca.shared.global [%0], [%1], 16;" :: "r"(dst), "l"(src) : "memory")
#define CPA_COMMIT() asm volatile("cp.async.commit_group;" ::: "memory")
#define CPA_WAIT1()  asm volatile("cp.async.wait_group 1;" ::: "memory")
#define CPA_WAIT0()  asm volatile("cp.async.wait_group 0;" ::: "memory")

__device__ __forceinline__ void ldm4(uint32_t* r, uint32_t addr) {
    asm volatile("ldmatrix.sync.aligned.m8n8.x4.shared.b16 {%0,%1,%2,%3}, [%4];"
        : "=r"(r[0]), "=r"(r[1]), "=r"(r[2]), "=r"(r[3]) : "r"(addr));
}
__device__ __forceinline__ void mma_bf16(float* c, const uint32_t* a, uint32_t b0, uint32_t b1) {
    asm volatile("mma.sync.aligned.m16n8k16.row.col.f32.bf16.bf16.f32 "
        "{%0,%1,%2,%3}, {%4,%5,%6,%7}, {%8,%9}, {%0,%1,%2,%3};"
        : "+f"(c[0]), "+f"(c[1]), "+f"(c[2]), "+f"(c[3])
        : "r"(a[0]), "r"(a[1]), "r"(a[2]), "r"(a[3]), "r"(b0), "r"(b1));
}
__device__ __forceinline__ uint32_t pack_bf16x2(float x0, float x1) {
    __nv_bfloat16 b0 = __float2bfloat16(x0);
    __nv_bfloat16 b1 = __float2bfloat16(x1);
    return (uint32_t)__bfloat16_as_ushort(b0) | ((uint32_t)__bfloat16_as_ushort(b1) << 16);
}

// ---------------- CSR build chain ----------------
__global__ void zero_cnt_kernel(int* __restrict__ cnt) {
    int i = blockIdx.x * blockDim.x + threadIdx.x;
    if (i < 2 * NN) cnt[i] = 0;
}

__global__ void count_kernel(const int* __restrict__ dst0, const int* __restrict__ dst1,
                             int E, int* __restrict__ cnt) {
    int t = blockIdx.y;
    const int* dst = t ? dst1 : dst0;
    int* c = cnt + t * NN;
    int e = blockIdx.x * blockDim.x + threadIdx.x;
    if (e < E) atomicAdd(&c[dst[e]], 1);
}

__global__ void scan_part_kernel(const int* __restrict__ cnt, int* __restrict__ part) {
    __shared__ int sh[256];
    const int* c = cnt + blockIdx.y * NN;
    int* p = part + blockIdx.y * 512;
    int i = blockIdx.x * 256 + threadIdx.x;
    sh[threadIdx.x] = (i < NN) ? c[i] : 0;
    __syncthreads();
    for (int s = 128; s > 0; s >>= 1) {
        if (threadIdx.x < s) sh[threadIdx.x] += sh[threadIdx.x + s];
        __syncthreads();
    }
    if (threadIdx.x == 0) p[blockIdx.x] = sh[0];
}

__global__ void scan_partials_kernel(int* __restrict__ part, int nb) {
    __shared__ int sh[512];
    int* p = part + blockIdx.y * 512;
    int t = threadIdx.x;
    int v = (t < nb) ? p[t] : 0;
    sh[t] = v;
    __syncthreads();
    for (int o = 1; o < 512; o <<= 1) {
        int x = (t >= o) ? sh[t - o] : 0;
        __syncthreads();
        sh[t] += x;
        __syncthreads();
    }
    if (t < nb) p[t] = sh[t] - v;  // exclusive
}

__global__ void scan_final_kernel(const int* __restrict__ cnt, const int* __restrict__ part,
                                  int* __restrict__ off, int* __restrict__ pos) {
    __shared__ int sh[256];
    const int* c = cnt + blockIdx.y * NN;
    const int* p = part + blockIdx.y * 512;
    int* of = off + blockIdx.y * NN;
    int* ps = pos + blockIdx.y * NN;
    int t = threadIdx.x;
    int i = blockIdx.x * 256 + t;
    int v = (i < NN) ? c[i] : 0;
    sh[t] = v;
    __syncthreads();
    for (int o = 1; o < 256; o <<= 1) {
        int x = (t >= o) ? sh[t - o] : 0;
        __syncthreads();
        sh[t] += x;
        __syncthreads();
    }
    if (i < NN) {
        int e = sh[t] - v + p[blockIdx.x];
        of[i] = e;
        ps[i] = e;
    }
}

__global__ void build_csr_kernel(const int* __restrict__ e0, const int* __restrict__ e1,
                                 int E, int* __restrict__ pos,
                                 int* __restrict__ c0, int* __restrict__ c1) {
    int t = blockIdx.y;
    const int* edge = t ? e1 : e0;
    int* ps = pos + t * NN;
    int* csr = t ? c1 : c0;
    int e = blockIdx.x * blockDim.x + threadIdx.x;
    if (e < E) {
        int s = edge[e];
        int d = edge[E + e];
        int idx = atomicAdd(&ps[d], 1);
        csr[idx] = s;
    }
}

// ---------------- gather-mean aggregation (layer 0, C=128), dual via gridDim.y ----------------
__global__ void gather_mean_kernel(const float* __restrict__ fA, const int* __restrict__ csrA, float* __restrict__ oA,
                                   const float* __restrict__ fB, const int* __restrict__ csrB, float* __restrict__ oB,
                                   const int* __restrict__ off, const int* __restrict__ cnt) {
    constexpr int G = 32;
    const int t = blockIdx.y;
    const float* feat = t ? fB : fA;
    const int* csr = t ? csrB : csrA;
    float* out = t ? oB : oA;
    const int* of = off + t * NN;
    const int* cn = cnt + t * NN;

    int gid = (int)((blockIdx.x * (size_t)blockDim.x + threadIdx.x) / G);
    if (gid >= NN) return;
    const int c4 = (threadIdx.x & (G - 1)) * 4;
    const int beg = __ldg(&of[gid]);
    const int deg = __ldg(&cn[gid]);

    float4 a0 = make_float4(0.f, 0.f, 0.f, 0.f);
    float4 a1 = make_float4(0.f, 0.f, 0.f, 0.f);
    float4 a2 = make_float4(0.f, 0.f, 0.f, 0.f);
    float4 a3 = make_float4(0.f, 0.f, 0.f, 0.f);
    int e = 0;
    for (; e + 3 < deg; e += 4) {
        int s0 = __ldg(&csr[beg + e]);
        int s1 = __ldg(&csr[beg + e + 1]);
        int s2 = __ldg(&csr[beg + e + 2]);
        int s3 = __ldg(&csr[beg + e + 3]);
        float4 v0 = *(const float4*)(feat + (size_t)s0 * HD + c4);
        float4 v1 = *(const float4*)(feat + (size_t)s1 * HD + c4);
        float4 v2 = *(const float4*)(feat + (size_t)s2 * HD + c4);
        float4 v3 = *(const float4*)(feat + (size_t)s3 * HD + c4);
        a0.x += v0.x; a0.y += v0.y; a0.z += v0.z; a0.w += v0.w;
        a1.x += v1.x; a1.y += v1.y; a1.z += v1.z; a1.w += v1.w;
        a2.x += v2.x; a2.y += v2.y; a2.z += v2.z; a2.w += v2.w;
        a3.x += v3.x; a3.y += v3.y; a3.z += v3.z; a3.w += v3.w;
    }
    for (; e < deg; e++) {
        int s0 = __ldg(&csr[beg + e]);
        float4 v0 = *(const float4*)(feat + (size_t)s0 * HD + c4);
        a0.x += v0.x; a0.y += v0.y; a0.z += v0.z; a0.w += v0.w;
    }
    const float sc = 1.0f / fmaxf((float)deg, 1.0f);
    float4 r;
    r.x = (a0.x + a1.x + a2.x + a3.x) * sc;
    r.y = (a0.y + a1.y + a2.y + a3.y) * sc;
    r.z = (a0.z + a1.z + a2.z + a3.z) * sc;
    r.w = (a0.w + a1.w + a2.w + a3.w) * sc;
    *(float4*)(out + (size_t)gid * HD + c4) = r;
}

// ---------------- fused layer-1 gather + final LN ----------------
// warp per dst row: acc = mean over neighbors of proj_src (stride 64), v = acc + root[row] + bias, out = LN(v)
struct FSide { const float* proj_src; const float* root; const int* csr;
               const float* bias; const float* g; const float* b; float* out; };
__global__ void final_fused_kernel(FSide f0, FSide f1, const int* __restrict__ off, const int* __restrict__ cnt) {
    const int t = blockIdx.y;
    FSide s = t ? f1 : f0;
    const int* of = off + t * NN;
    const int* cn = cnt + t * NN;
    const int warp = threadIdx.x >> 5;
    const int lane = threadIdx.x & 31;
    const int row = blockIdx.x * 8 + warp;
    if (row >= NN) return;
    const int c = lane * 2;
    const int beg = __ldg(&of[row]);
    const int deg = __ldg(&cn[row]);

    float x0 = 0.f, y0 = 0.f, x1 = 0.f, y1 = 0.f;
    int e = 0;
    for (; e + 1 < deg; e += 2) {
        int s0 = __ldg(&s.csr[beg + e]);
        int s1 = __ldg(&s.csr[beg + e + 1]);
        float2 v0 = *(const float2*)(s.proj_src + (size_t)s0 * OD + c);
        float2 v1 = *(const float2*)(s.proj_src + (size_t)s1 * OD + c);
        x0 += v0.x; y0 += v0.y;
        x1 += v1.x; y1 += v1.y;
    }
    if (e < deg) {
        int s0 = __ldg(&s.csr[beg + e]);
        float2 v0 = *(const float2*)(s.proj_src + (size_t)s0 * OD + c);
        x0 += v0.x; y0 += v0.y;
    }
    const float sc = 1.0f / fmaxf((float)deg, 1.0f);
    float2 rv = *(const float2*)(s.root + (size_t)row * OD + c);
    float2 bv = __ldg((const float2*)(s.bias + c));
    float v0 = (x0 + x1) * sc + rv.x + bv.x;
    float v1 = (y0 + y1) * sc + rv.y + bv.y;

    float s1v = v0 + v1;
    float s2v = v0 * v0 + v1 * v1;
#pragma unroll
    for (int o = 16; o > 0; o >>= 1) {
        s1v += __shfl_xor_sync(0xFFFFFFFFu, s1v, o);
        s2v += __shfl_xor_sync(0xFFFFFFFFu, s2v, o);
    }
    float mean = s1v * (1.0f / 64.0f);
    float var = s2v * (1.0f / 64.0f) - mean * mean;
    float rstd = rsqrtf(var + 1e-5f);
    float2 gv = __ldg((const float2*)(s.g + c));
    float2 bb = __ldg((const float2*)(s.b + c));
    float2 o2;
    o2.x = (v0 - mean) * rstd * gv.x + bb.x;
    o2.y = (v1 - mean) * rstd * gv.y + bb.y;
    *(float2*)(s.out + (size_t)row * 64 + c) = o2;
}

// weight transpose + bf16 hi/lo split
struct WCon { const float* w; __nv_bfloat16* h; __nv_bfloat16* l; int K, N, Kpad; };
struct WCon10 { WCon s[10]; };
__global__ void wconv_kernel(WCon10 P) {
    WCon w = P.s[blockIdx.y];
    int idx = blockIdx.x * blockDim.x + threadIdx.x;
    if (idx >= w.N * w.Kpad) return;
    int n = idx / w.Kpad, k = idx % w.Kpad;
    float x = (k < w.K) ? w.w[(size_t)k * w.N + n] : 0.0f;
    __nv_bfloat16 h = __float2bfloat16(x);
    w.h[idx] = h;
    w.l[idx] = __float2bfloat16(x - __bfloat162float(h));
}

// ---------------- HMMA (mma.sync) GEMM, BN=128, 4x2 warp tiling, paired via gridDim.y ----------------
// B tiles double-buffered via cp.async; A staged synchronously (fp32 -> bf16 hi/lo split).
// SPLIT: epilogue writes cols 0-63 -> out (stride 64), cols 64-127 -> out2 (stride 64).
#define BN 128

struct GSide {
    const float* A1; const __nv_bfloat16* W1h; const __nv_bfloat16* W1l; int K1; int K1pad;
    const float* A2; const __nv_bfloat16* W2h; const __nv_bfloat16* W2l; int K2; int K2pad;
    const float* bias; const float* gamma; const float* beta; float* out; float* out2;
};

template <bool FUSE2, bool SPLIT, bool DO_LN, bool DO_RELU>
__global__ __launch_bounds__(256, 2)
void mma_gemm(GSide s0, GSide s1, int M) {
    const GSide& S = blockIdx.y ? s1 : s0;

    extern __shared__ char smem[];
    const uint32_t sb = smem_u32(smem);
    const uint32_t aHiB = sb;
    const uint32_t aLoB = sb + 16384;
    const uint32_t bBuf0 = sb + 32768;   // bHi at +0, bLo at +16384; buffer stride 32768

    const int tid = threadIdx.x;
    const int warp = tid >> 5;
    const int lane = tid & 31;
    const int wm = warp & 3;
    const int wn = warp >> 2;
    const int r0 = blockIdx.x * 128;

    float acc[2][8][4];
#pragma unroll
    for (int mt = 0; mt < 2; mt++)
#pragma unroll
        for (int nt = 0; nt < 8; nt++)
#pragma unroll
            for (int j = 0; j < 4; j++) acc[mt][nt][j] = 0.0f;

    // staging mapping
    const int ar = tid >> 1;
    const int acb = (tid & 1) * 32;
    const int bn = tid >> 1;
    const int bq = tid & 1;

    // compute-phase lane constants
    const uint32_t a_off0 = (uint32_t)(wm * 32 + (lane & 15)) * 128;
    const uint32_t a_off1 = a_off0 + 16 * 128;
    const uint32_t a_xm = (lane & 7) * 16;
    const uint32_t a_khalf = ((lane >> 4) & 1) * 16;
    const uint32_t b_rowbase = (uint32_t)(wn * 64 + (lane & 7) + ((lane >> 4) & 1) * 8) * 128;
    const uint32_t b_xm = (lane & 7) * 16;
    const uint32_t b_khalf = ((lane >> 3) & 1) * 16;

    const int nch1 = S.K1pad >> 6;
    const int nch = nch1 + (FUSE2 ? (S.K2pad >> 6) : 0);

    auto issueB = [&](int c, int buf) {
        const __nv_bfloat16 *Wh, *Wl;
        int k0, Kpad;
        if (!FUSE2 || c < nch1) { Wh = S.W1h; Wl = S.W1l; k0 = c * 64; Kpad = S.K1pad; }
        else                    { Wh = S.W2h; Wl = S.W2l; k0 = (c - nch1) * 64; Kpad = S.K2pad; }
        const uint32_t bH = bBuf0 + (uint32_t)buf * 32768;
        const uint32_t bL = bH + 16384;
#pragma unroll
        for (int i = 0; i < 4; i++) {
            const int ck = bq * 32 + i * 8;
            const size_t so = (size_t)bn * Kpad + k0 + ck;
            const uint32_t off = SWZ(bn * 128 + ck * 2);
            CPA16(bH + off, Wh + so);
            CPA16(bL + off, Wl + so);
        }
        CPA_COMMIT();
    };

    issueB(0, 0);

    for (int c = 0; c < nch; c++) {
        if (c) __syncthreads();

        const float* A;
        int k0, K;
        if (!FUSE2 || c < nch1) { A = S.A1; k0 = c * 64; K = S.K1; }
        else                    { A = S.A2; k0 = (c - nch1) * 64; K = S.K2; }

        // ---- stage A (fp32 -> bf16 hi/lo, swizzled) ----
        {
            const int grow = r0 + ar;
            const float* arow = A + (size_t)grow * K;
#pragma unroll
            for (int i = 0; i < 4; i++) {
                const int cc = acb + i * 8;
                float x[8];
#pragma unroll
                for (int j = 0; j < 8; j++) x[j] = 0.0f;
                if (grow < M && (k0 + cc) < K) {
                    float4 v0 = *(const float4*)(arow + k0 + cc);
                    float4 v1 = *(const float4*)(arow + k0 + cc + 4);
                    x[0] = v0.x; x[1] = v0.y; x[2] = v0.z; x[3] = v0.w;
                    x[4] = v1.x; x[5] = v1.y; x[6] = v1.z; x[7] = v1.w;
                }
                uint32_t hi[4], lo[4];
#pragma unroll
                for (int j = 0; j < 4; j++) {
                    __nv_bfloat16 h0 = __float2bfloat16(x[2 * j]);
                    __nv_bfloat16 h1 = __float2bfloat16(x[2 * j + 1]);
                    hi[j] = (uint32_t)__bfloat16_as_ushort(h0) | ((uint32_t)__bfloat16_as_ushort(h1) << 16);
                    lo[j] = pack_bf16x2(x[2 * j] - __bfloat162float(h0), x[2 * j + 1] - __bfloat162float(h1));
                }
                const uint32_t off = SWZ(ar * 128 + cc * 2);
                asm volatile("st.shared.v4.b32 [%0], {%1, %2, %3, %4};" :: "r"(aHiB + off), "r"(hi[0]), "r"(hi[1]), "r"(hi[2]), "r"(hi[3]) : "memory");
                asm volatile("st.shared.v4.b32 [%0], {%1, %2, %3, %4};" :: "r"(aLoB + off), "r"(lo[0]), "r"(lo[1]), "r"(lo[2]), "r"(lo[3]) : "memory");
            }
        }

        // ---- prefetch next B, then wait for current B ----
        if (c + 1 < nch) {
            issueB(c + 1, (c + 1) & 1);
            CPA_WAIT1();
        } else {
            CPA_WAIT0();
        }
        __syncthreads();

        // ---- compute ----
        const uint32_t bHiC = bBuf0 + (uint32_t)(c & 1) * 32768;
        const uint32_t bLoC = bHiC + 16384;
#pragma unroll
        for (int ks = 0; ks < 4; ks++) {
            const uint32_t akb = ((uint32_t)(ks * 32) + a_khalf) ^ a_xm;
            uint32_t ah[2][4], al[2][4];
            ldm4(ah[0], aHiB + a_off0 + akb);
            ldm4(ah[1], aHiB + a_off1 + akb);
            ldm4(al[0], aLoB + a_off0 + akb);
            ldm4(al[1], aLoB + a_off1 + akb);
            const uint32_t bkb = ((uint32_t)(ks * 32) + b_khalf) ^ b_xm;
#pragma unroll
            for (int j = 0; j < 4; j++) {
                uint32_t bh[4], bl[4];
                const uint32_t boff = b_rowbase + (uint32_t)j * 2048;
                ldm4(bh, bHiC + boff + bkb);
                ldm4(bl, bLoC + boff + bkb);
#pragma unroll
                for (int mt = 0; mt < 2; mt++) {
                    mma_bf16(acc[mt][2 * j],     ah[mt], bh[0], bh[1]);
                    mma_bf16(acc[mt][2 * j],     ah[mt], bl[0], bl[1]);
                    mma_bf16(acc[mt][2 * j],     al[mt], bh[0], bh[1]);
                    mma_bf16(acc[mt][2 * j + 1], ah[mt], bh[2], bh[3]);
                    mma_bf16(acc[mt][2 * j + 1], ah[mt], bl[2], bl[3]);
                    mma_bf16(acc[mt][2 * j + 1], al[mt], bh[2], bh[3]);
                }
            }
        }
    }

    // ---- epilogue ----
    const int rq = lane >> 2;
    const int cq = (lane & 3) * 2;

    if (S.bias) {
#pragma unroll
        for (int nt = 0; nt < 8; nt++) {
            float2 bv = __ldg((const float2*)(S.bias + wn * 64 + nt * 8 + cq));
#pragma unroll
            for (int mt = 0; mt < 2; mt++) {
                acc[mt][nt][0] += bv.x; acc[mt][nt][1] += bv.y;
                acc[mt][nt][2] += bv.x; acc[mt][nt][3] += bv.y;
            }
        }
    }
    if (DO_LN) {
        float s1[2][2], s2[2][2];
#pragma unroll
        for (int mt = 0; mt < 2; mt++)
#pragma unroll
            for (int h = 0; h < 2; h++) { s1[mt][h] = 0.f; s2[mt][h] = 0.f; }
#pragma unroll
        for (int mt = 0; mt < 2; mt++)
#pragma unroll
            for (int nt = 0; nt < 8; nt++) {
                s1[mt][0] += acc[mt][nt][0] + acc[mt][nt][1];
                s2[mt][0] += acc[mt][nt][0] * acc[mt][nt][0] + acc[mt][nt][1] * acc[mt][nt][1];
                s1[mt][1] += acc[mt][nt][2] + acc[mt][nt][3];
                s2[mt][1] += acc[mt][nt][2] * acc[mt][nt][2] + acc[mt][nt][3] * acc[mt][nt][3];
            }
#pragma unroll
        for (int o = 1; o < 4; o <<= 1) {
#pragma unroll
            for (int mt = 0; mt < 2; mt++)
#pragma unroll
                for (int h = 0; h < 2; h++) {
                    s1[mt][h] += __shfl_xor_sync(0xFFFFFFFFu, s1[mt][h], o);
                    s2[mt][h] += __shfl_xor_sync(0xFFFFFFFFu, s2[mt][h], o);
                }
        }
        float* sc = (float*)smem;
        __syncthreads();
        if ((lane & 3) == 0) {
#pragma unroll
            for (int mt = 0; mt < 2; mt++)
#pragma unroll
                for (int h = 0; h < 2; h++) {
                    int rl = wm * 32 + mt * 16 + h * 8 + rq;
                    sc[wn * 128 + rl] = s1[mt][h];
                    sc[256 + wn * 128 + rl] = s2[mt][h];
                }
        }
        __syncthreads();
#pragma unroll
        for (int mt = 0; mt < 2; mt++)
#pragma unroll
            for (int h = 0; h < 2; h++) {
                int rl = wm * 32 + mt * 16 + h * 8 + rq;
                float S1 = sc[rl] + sc[128 + rl];
                float S2 = sc[256 + rl] + sc[384 + rl];
                float mean = S1 * (1.0f / 128.0f);
                float var = S2 * (1.0f / 128.0f) - mean * mean;
                float rstd = rsqrtf(var + 1e-5f);
                s1[mt][h] = mean;
                s2[mt][h] = rstd;
            }
#pragma unroll
        for (int nt = 0; nt < 8; nt++) {
            float2 g = __ldg((const float2*)(S.gamma + wn * 64 + nt * 8 + cq));
            float2 b = __ldg((const float2*)(S.beta + wn * 64 + nt * 8 + cq));
#pragma unroll
            for (int mt = 0; mt < 2; mt++) {
                acc[mt][nt][0] = (acc[mt][nt][0] - s1[mt][0]) * s2[mt][0] * g.x + b.x;
                acc[mt][nt][1] = (acc[mt][nt][1] - s1[mt][0]) * s2[mt][0] * g.y + b.y;
                acc[mt][nt][2] = (acc[mt][nt][2] - s1[mt][1]) * s2[mt][1] * g.x + b.x;
                acc[mt][nt][3] = (acc[mt][nt][3] - s1[mt][1]) * s2[mt][1] * g.y + b.y;
            }
        }
    }
    if (DO_RELU) {
#pragma unroll
        for (int mt = 0; mt < 2; mt++)
#pragma unroll
            for (int nt = 0; nt < 8; nt++)
#pragma unroll
                for (int j = 0; j < 4; j++) acc[mt][nt][j] = fmaxf(acc[mt][nt][j], 0.0f);
    }
    if (SPLIT) {
        float* dst = wn ? S.out2 : S.out;
#pragma unroll
        for (int mt = 0; mt < 2; mt++)
#pragma unroll
            for (int h = 0; h < 2; h++) {
                int row = r0 + wm * 32 + mt * 16 + h * 8 + rq;
                if (row < M) {
#pragma unroll
                    for (int nt = 0; nt < 8; nt++)
                        *(float2*)(dst + (size_t)row * 64 + nt * 8 + cq) =
                            make_float2(acc[mt][nt][2 * h], acc[mt][nt][2 * h + 1]);
                }
            }
    } else {
#pragma unroll
        for (int mt = 0; mt < 2; mt++)
#pragma unroll
            for (int h = 0; h < 2; h++) {
                int row = r0 + wm * 32 + mt * 16 + h * 8 + rq;
                if (row < M) {
#pragma unroll
                    for (int nt = 0; nt < 8; nt++)
                        *(float2*)(S.out + (size_t)row * BN + wn * 64 + nt * 8 + cq) =
                            make_float2(acc[mt][nt][2 * h], acc[mt][nt][2 * h + 1]);
                }
            }
    }
}

// ---------------- host launcher ----------------
extern "C" void kernel_launch(void* const* d_in, const int* in_sizes, int n_in,
                              void* d_out, int out_size) {
    const float* x_user = (const float*)d_in[0];
    const float* x_item = (const float*)d_in[1];
    const int* edge_ui = (const int*)d_in[2];
    const int* edge_iu = (const int*)d_in[3];
    const float* Wp_u = (const float*)d_in[4];
    const float* bp_u = (const float*)d_in[5];
    const float* Wp_i = (const float*)d_in[6];
    const float* bp_i = (const float*)d_in[7];
    const float* Wl0_ui = (const float*)d_in[8];
    const float* bl0_ui = (const float*)d_in[9];
    const float* Wr0_ui = (const float*)d_in[10];
    const float* Wl0_iu = (const float*)d_in[11];
    const float* bl0_iu = (const float*)d_in[12];
    const float* Wr0_iu = (const float*)d_in[13];
    const float* g0_u = (const float*)d_in[14];
    const float* b0_u = (const float*)d_in[15];
    const float* g0_i = (const float*)d_in[16];
    const float* b0_i = (const float*)d_in[17];
    const float* Wl1_ui = (const float*)d_in[18];
    const float* bl1_ui = (const float*)d_in[19];
    const float* Wr1_ui = (const float*)d_in[20];
    const float* Wl1_iu = (const float*)d_in[21];
    const float* bl1_iu = (const float*)d_in[22];
    const float* Wr1_iu = (const float*)d_in[23];
    const float* g1_u = (const float*)d_in[24];
    const float* b1_u = (const float*)d_in[25];
    const float* g1_i = (const float*)d_in[26];
    const float* b1_i = (const float*)d_in[27];

    const int E = in_sizes[2] / 2;

    float *hu, *hi, *agg_u, *agg_i, *hu1, *hi1, *proj_u, *root_u, *proj_i, *root_i;
    int *cnt, *off, *pos, *csr_iu, *csr_ui, *part;
    cudaGetSymbolAddress((void**)&hu, g_hu);
    cudaGetSymbolAddress((void**)&hi, g_hi);
    cudaGetSymbolAddress((void**)&agg_u, g_agg_u);
    cudaGetSymbolAddress((void**)&agg_i, g_agg_i);
    cudaGetSymbolAddress((void**)&hu1, g_hu1);
    cudaGetSymbolAddress((void**)&hi1, g_hi1);
    cudaGetSymbolAddress((void**)&proj_u, g_proj_u);
    cudaGetSymbolAddress((void**)&root_u, g_root_u);
    cudaGetSymbolAddress((void**)&proj_i, g_proj_i);
    cudaGetSymbolAddress((void**)&root_i, g_root_i);
    cudaGetSymbolAddress((void**)&cnt, g_cnt);
    cudaGetSymbolAddress((void**)&off, g_off);
    cudaGetSymbolAddress((void**)&pos, g_pos);
    cudaGetSymbolAddress((void**)&csr_iu, g_csr_iu);
    cudaGetSymbolAddress((void**)&csr_ui, g_csr_ui);
    cudaGetSymbolAddress((void**)&part, g_part);

    __nv_bfloat16 *wpu_h, *wpu_l, *wpi_h, *wpi_l;
    __nv_bfloat16 *wl0ui_h, *wl0ui_l, *wr0ui_h, *wr0ui_l, *wl0iu_h, *wl0iu_l, *wr0iu_h, *wr0iu_l;
    __nv_bfloat16 *w1u_h, *w1u_l, *w1i_h, *w1i_l;
    cudaGetSymbolAddress((void**)&wpu_h, g_wpu_h);   cudaGetSymbolAddress((void**)&wpu_l, g_wpu_l);
    cudaGetSymbolAddress((void**)&wpi_h, g_wpi_h);   cudaGetSymbolAddress((void**)&wpi_l, g_wpi_l);
    cudaGetSymbolAddress((void**)&wl0ui_h, g_wl0ui_h); cudaGetSymbolAddress((void**)&wl0ui_l, g_wl0ui_l);
    cudaGetSymbolAddress((void**)&wr0ui_h, g_wr0ui_h); cudaGetSymbolAddress((void**)&wr0ui_l, g_wr0ui_l);
    cudaGetSymbolAddress((void**)&wl0iu_h, g_wl0iu_h); cudaGetSymbolAddress((void**)&wl0iu_l, g_wl0iu_l);
    cudaGetSymbolAddress((void**)&wr0iu_h, g_wr0iu_h); cudaGetSymbolAddress((void**)&wr0iu_l, g_wr0iu_l);
    cudaGetSymbolAddress((void**)&w1u_h, g_w1u_h);   cudaGetSymbolAddress((void**)&w1u_l, g_w1u_l);
    cudaGetSymbolAddress((void**)&w1i_h, g_w1i_h);   cudaGetSymbolAddress((void**)&w1i_l, g_w1i_l);

    float* out_u = (float*)d_out;
    float* out_i = (float*)d_out + (size_t)NN * OD;

    const int SM = 98304;  // A 32KB + B 2x32KB
    cudaFuncSetAttribute(mma_gemm<false, false, false, true>, cudaFuncAttributeMaxDynamicSharedMemorySize, SM);
    cudaFuncSetAttribute(mma_gemm<true, false, true, true>, cudaFuncAttributeMaxDynamicSharedMemorySize, SM);
    cudaFuncSetAttribute(mma_gemm<false, true, false, false>, cudaFuncAttributeMaxDynamicSharedMemorySize, SM);

    const int GM = (NN + 127) / 128;

    // fork a side stream for the CSR chain (independent of weights/proj)
    cudaStream_t sB;
    cudaEvent_t eFork, eJoin;
    cudaStreamCreateWithFlags(&sB, cudaStreamNonBlocking);
    cudaEventCreateWithFlags(&eFork, cudaEventDisableTiming);
    cudaEventCreateWithFlags(&eJoin, cudaEventDisableTiming);

    cudaEventRecord(eFork, 0);
    cudaStreamWaitEvent(sB, eFork, 0);

    // side stream: degree + CSR build
    {
        dim3 ge((E + 255) / 256, 2);
        zero_cnt_kernel<<<(2 * NN + 255) / 256, 256, 0, sB>>>(cnt);
        count_kernel<<<ge, 256, 0, sB>>>(edge_iu + E, edge_ui + E, E, cnt);
        scan_part_kernel<<<dim3(NBLK, 2), 256, 0, sB>>>(cnt, part);
        scan_partials_kernel<<<dim3(1, 2), 512, 0, sB>>>(part, NBLK);
        scan_final_kernel<<<dim3(NBLK, 2), 256, 0, sB>>>(cnt, part, off, pos);
        build_csr_kernel<<<ge, 256, 0, sB>>>(edge_iu, edge_ui, E, pos, csr_iu, csr_ui);
        cudaEventRecord(eJoin, sB);
    }

    // main stream: weight convert + projection GEMM pair
    {
        WCon10 P;
        P.s[0] = { Wp_u,   wpu_h,   wpu_l,   FU, HD, 128 };
        P.s[1] = { Wp_i,   wpi_h,   wpi_l,   FI, HD, 192 };
        P.s[2] = { Wl0_ui, wl0ui_h, wl0ui_l, HD, HD, 128 };
        P.s[3] = { Wr0_ui, wr0ui_h, wr0ui_l, HD, HD, 128 };
        P.s[4] = { Wl0_iu, wl0iu_h, wl0iu_l, HD, HD, 128 };
        P.s[5] = { Wr0_iu, wr0iu_h, wr0iu_l, HD, HD, 128 };
        P.s[6] = { Wl1_ui, w1u_h,             w1u_l,             HD, OD, 128 };
        P.s[7] = { Wr1_iu, w1u_h + 64 * 128,  w1u_l + 64 * 128,  HD, OD, 128 };
        P.s[8] = { Wl1_iu, w1i_h,             w1i_l,             HD, OD, 128 };
        P.s[9] = { Wr1_ui, w1i_h + 64 * 128,  w1i_l + 64 * 128,  HD, OD, 128 };
        dim3 g((192 * 128 + 255) / 256, 10);
        wconv_kernel<<<g, 256>>>(P);
    }
    {
        GSide su = { x_user, wpu_h, wpu_l, FU, 128, nullptr, nullptr, nullptr, 0, 0,
                     bp_u, nullptr, nullptr, hu, nullptr };
        GSide si = { x_item, wpi_h, wpi_l, FI, 192, nullptr, nullptr, nullptr, 0, 0,
                     bp_i, nullptr, nullptr, hi, nullptr };
        mma_gemm<false, false, false, true><<<dim3(GM, 2), 256, SM>>>(su, si, NN);
    }

    // join: gather needs CSR + proj outputs
    cudaStreamWaitEvent(0, eJoin, 0);

    // layer 0 aggregation. t=0: agg_u <- hi via csr_iu; t=1: agg_i <- hu via csr_ui
    {
        const long tot = (long)NN * 32;
        dim3 gg((unsigned)((tot + 255) / 256), 2);
        gather_mean_kernel<<<gg, 256>>>(hi, csr_iu, agg_u, hu, csr_ui, agg_i, off, cnt);
    }

    // layer 0 fused dual-GEMM + bias + LN + ReLU
    {
        GSide si = { agg_i, wl0ui_h, wl0ui_l, HD, 128, hi, wr0ui_h, wr0ui_l, HD, 128,
                     bl0_ui, g0_i, b0_i, hi1, nullptr };
        GSide su = { agg_u, wl0iu_h, wl0iu_l, HD, 128, hu, wr0iu_h, wr0iu_l, HD, 128,
                     bl0_iu, g0_u, b0_u, hu1, nullptr };
        mma_gemm<true, false, true, true><<<dim3(GM, 2), 256, SM>>>(si, su, NN);
    }

    // layer 1 combined GEMM pair: [proj|root] = h1 @ [Wl1 | Wr1], split into stride-64 arrays
    {
        GSide su = { hu1, w1u_h, w1u_l, HD, 128, nullptr, nullptr, nullptr, 0, 0,
                     nullptr, nullptr, nullptr, proj_u, root_u };
        GSide si = { hi1, w1i_h, w1i_l, HD, 128, nullptr, nullptr, nullptr, 0, 0,
                     nullptr, nullptr, nullptr, proj_i, root_i };
        mma_gemm<false, true, false, false><<<dim3(GM, 2), 256, SM>>>(su, si, NN);
    }

    // fused layer-1 gather + final LN
    {
        FSide fu = { proj_i, root_u, csr_iu, bl1_iu, g1_u, b1_u, out_u };
        FSide fi = { proj_u, root_i, csr_ui, bl1_ui, g1_i, b1_i, out_i };
        dim3 gf((NN + 7) / 8, 2);
        final_fused_kernel<<<gf, 256>>>(fu, fi, off, cnt);
    }

    (void)n_in; (void)out_size; (void)in_sizes;
}

// round 10
// speedup vs baseline: 1.3596x; 1.1908x over previous
#include <cuda_runtime.h>
#include <cuda_fp16.h>
#include <cstdint>

// ---------------- problem constants ----------------
#define NU 100000
#define NI 100000
#define NN 100000   // NU == NI
#define FU 96
#define FI 160
#define HD 128
#define OD 64
#define EMAX 600000
#define NBLK 391   // ceil(100000/256)

// ---------------- scratch (device globals) ----------------
__device__ float  g_hu   [NN * HD];
__device__ float  g_hi   [NN * HD];
__device__ __half g_agg_u[NN * HD];   // fp16 agg planes (gather output = layer0 A)
__device__ __half g_agg_i[NN * HD];
__device__ __half g_hu1  [NN * HD];   // fp16 h1 planes (layer0 out = layer1 A)
__device__ __half g_hi1  [NN * HD];
__device__ float  g_proj_u[NN * OD];
__device__ float  g_root_u[NN * OD];
__device__ float  g_proj_i[NN * OD];
__device__ float  g_root_i[NN * OD];
__device__ int    g_cnt [2 * NN];
__device__ int    g_off [2 * NN];
__device__ int    g_pos [2 * NN];
__device__ int    g_csr_iu[EMAX];
__device__ int    g_csr_ui[EMAX];
__device__ int    g_part[2 * 512];

// transposed/split fp16 weights: layout [N rows, Kpad cols], zero padded
__device__ __half g_wpu_h[128 * 128],  g_wpu_l[128 * 128];
__device__ __half g_wpi_h[128 * 192],  g_wpi_l[128 * 192];
__device__ __half g_wl0ui_h[128 * 128], g_wl0ui_l[128 * 128];
__device__ __half g_wr0ui_h[128 * 128], g_wr0ui_l[128 * 128];
__device__ __half g_wl0iu_h[128 * 128], g_wl0iu_l[128 * 128];
__device__ __half g_wr0iu_h[128 * 128], g_wr0iu_l[128 * 128];
__device__ __half g_w1u_h[128 * 128],  g_w1u_l[128 * 128];   // [Wl1_ui | Wr1_iu]
__device__ __half g_w1i_h[128 * 128],  g_w1i_l[128 * 128];   // [Wl1_iu | Wr1_ui]

// ---------------- helpers ----------------
__device__ __forceinline__ uint32_t smem_u32(const void* p) {
    uint32_t a;
    asm("{ .reg .u64 t; cvta.to.shared.u64 t, %1; cvt.u32.u64 %0, t; }" : "=r"(a) : "l"(p));
    return a;
}
#define SWZ(x) ((x) ^ (((x) >> 3) & 0x70))

#define CPA16(dst, src) \
    asm volatile("cp.async.ca.shared.global [%0], [%1], 16;" :: "r"(dst), "l"(src) : "memory")
#define CPA_COMMIT() asm volatile("cp.async.commit_group;" ::: "memory")
#define CPA_WAIT1()  asm volatile("cp.async.wait_group 1;" ::: "memory")
#define CPA_WAIT0()  asm volatile("cp.async.wait_group 0;" ::: "memory")

__device__ __forceinline__ void ldm4(uint32_t* r, uint32_t addr) {
    asm volatile("ldmatrix.sync.aligned.m8n8.x4.shared.b16 {%0,%1,%2,%3}, [%4];"
        : "=r"(r[0]), "=r"(r[1]), "=r"(r[2]), "=r"(r[3]) : "r"(addr));
}
__device__ __forceinline__ void mma_fp16(float* c, const uint32_t* a, uint32_t b0, uint32_t b1) {
    asm volatile("mma.sync.aligned.m16n8k16.row.col.f32.f16.f16.f32 "
        "{%0,%1,%2,%3}, {%4,%5,%6,%7}, {%8,%9}, {%0,%1,%2,%3};"
        : "+f"(c[0]), "+f"(c[1]), "+f"(c[2]), "+f"(c[3])
        : "r"(a[0]), "r"(a[1]), "r"(a[2]), "r"(a[3]), "r"(b0), "r"(b1));
}
__device__ __forceinline__ uint32_t pack_h2(float x0, float x1) {
    __half2 h = __floats2half2_rn(x0, x1);
    return *reinterpret_cast<uint32_t*>(&h);
}

// ---------------- CSR build chain ----------------
__global__ void zero_cnt_kernel(int* __restrict__ cnt) {
    int i = blockIdx.x * blockDim.x + threadIdx.x;
    if (i < 2 * NN) cnt[i] = 0;
}

__global__ void count_kernel(const int* __restrict__ dst0, const int* __restrict__ dst1,
                             int E, int* __restrict__ cnt) {
    int t = blockIdx.y;
    const int* dst = t ? dst1 : dst0;
    int* c = cnt + t * NN;
    int e = blockIdx.x * blockDim.x + threadIdx.x;
    if (e < E) atomicAdd(&c[dst[e]], 1);
}

__global__ void scan_part_kernel(const int* __restrict__ cnt, int* __restrict__ part) {
    __shared__ int sh[256];
    const int* c = cnt + blockIdx.y * NN;
    int* p = part + blockIdx.y * 512;
    int i = blockIdx.x * 256 + threadIdx.x;
    sh[threadIdx.x] = (i < NN) ? c[i] : 0;
    __syncthreads();
    for (int s = 128; s > 0; s >>= 1) {
        if (threadIdx.x < s) sh[threadIdx.x] += sh[threadIdx.x + s];
        __syncthreads();
    }
    if (threadIdx.x == 0) p[blockIdx.x] = sh[0];
}

__global__ void scan_partials_kernel(int* __restrict__ part, int nb) {
    __shared__ int sh[512];
    int* p = part + blockIdx.y * 512;
    int t = threadIdx.x;
    int v = (t < nb) ? p[t] : 0;
    sh[t] = v;
    __syncthreads();
    for (int o = 1; o < 512; o <<= 1) {
        int x = (t >= o) ? sh[t - o] : 0;
        __syncthreads();
        sh[t] += x;
        __syncthreads();
    }
    if (t < nb) p[t] = sh[t] - v;  // exclusive
}

__global__ void scan_final_kernel(const int* __restrict__ cnt, const int* __restrict__ part,
                                  int* __restrict__ off, int* __restrict__ pos) {
    __shared__ int sh[256];
    const int* c = cnt + blockIdx.y * NN;
    const int* p = part + blockIdx.y * 512;
    int* of = off + blockIdx.y * NN;
    int* ps = pos + blockIdx.y * NN;
    int t = threadIdx.x;
    int i = blockIdx.x * 256 + t;
    int v = (i < NN) ? c[i] : 0;
    sh[t] = v;
    __syncthreads();
    for (int o = 1; o < 256; o <<= 1) {
        int x = (t >= o) ? sh[t - o] : 0;
        __syncthreads();
        sh[t] += x;
        __syncthreads();
    }
    if (i < NN) {
        int e = sh[t] - v + p[blockIdx.x];
        of[i] = e;
        ps[i] = e;
    }
}

__global__ void build_csr_kernel(const int* __restrict__ e0, const int* __restrict__ e1,
                                 int E, int* __restrict__ pos,
                                 int* __restrict__ c0, int* __restrict__ c1) {
    int t = blockIdx.y;
    const int* edge = t ? e1 : e0;
    int* ps = pos + t * NN;
    int* csr = t ? c1 : c0;
    int e = blockIdx.x * blockDim.x + threadIdx.x;
    if (e < E) {
        int s = edge[e];
        int d = edge[E + e];
        int idx = atomicAdd(&ps[d], 1);
        csr[idx] = s;
    }
}

// ---------------- gather-mean aggregation (layer 0, C=128), fp16 output ----------------
__global__ void gather_mean_kernel(const float* __restrict__ fA, const int* __restrict__ csrA, __half* __restrict__ oA,
                                   const float* __restrict__ fB, const int* __restrict__ csrB, __half* __restrict__ oB,
                                   const int* __restrict__ off, const int* __restrict__ cnt) {
    constexpr int G = 32;
    const int t = blockIdx.y;
    const float* feat = t ? fB : fA;
    const int* csr = t ? csrB : csrA;
    __half* out = t ? oB : oA;
    const int* of = off + t * NN;
    const int* cn = cnt + t * NN;

    int gid = (int)((blockIdx.x * (size_t)blockDim.x + threadIdx.x) / G);
    if (gid >= NN) return;
    const int c4 = (threadIdx.x & (G - 1)) * 4;
    const int beg = __ldg(&of[gid]);
    const int deg = __ldg(&cn[gid]);

    float4 a0 = make_float4(0.f, 0.f, 0.f, 0.f);
    float4 a1 = make_float4(0.f, 0.f, 0.f, 0.f);
    float4 a2 = make_float4(0.f, 0.f, 0.f, 0.f);
    float4 a3 = make_float4(0.f, 0.f, 0.f, 0.f);
    int e = 0;
    for (; e + 3 < deg; e += 4) {
        int s0 = __ldg(&csr[beg + e]);
        int s1 = __ldg(&csr[beg + e + 1]);
        int s2 = __ldg(&csr[beg + e + 2]);
        int s3 = __ldg(&csr[beg + e + 3]);
        float4 v0 = *(const float4*)(feat + (size_t)s0 * HD + c4);
        float4 v1 = *(const float4*)(feat + (size_t)s1 * HD + c4);
        float4 v2 = *(const float4*)(feat + (size_t)s2 * HD + c4);
        float4 v3 = *(const float4*)(feat + (size_t)s3 * HD + c4);
        a0.x += v0.x; a0.y += v0.y; a0.z += v0.z; a0.w += v0.w;
        a1.x += v1.x; a1.y += v1.y; a1.z += v1.z; a1.w += v1.w;
        a2.x += v2.x; a2.y += v2.y; a2.z += v2.z; a2.w += v2.w;
        a3.x += v3.x; a3.y += v3.y; a3.z += v3.z; a3.w += v3.w;
    }
    for (; e < deg; e++) {
        int s0 = __ldg(&csr[beg + e]);
        float4 v0 = *(const float4*)(feat + (size_t)s0 * HD + c4);
        a0.x += v0.x; a0.y += v0.y; a0.z += v0.z; a0.w += v0.w;
    }
    const float sc = 1.0f / fmaxf((float)deg, 1.0f);
    uint2 r;
    r.x = pack_h2((a0.x + a1.x + a2.x + a3.x) * sc, (a0.y + a1.y + a2.y + a3.y) * sc);
    r.y = pack_h2((a0.z + a1.z + a2.z + a3.z) * sc, (a0.w + a1.w + a2.w + a3.w) * sc);
    *(uint2*)(out + (size_t)gid * HD + c4) = r;
}

// ---------------- fused layer-1 gather + final LN ----------------
struct FSide { const float* proj_src; const float* root; const int* csr;
               const float* bias; const float* g; const float* b; float* out; };
__global__ void final_fused_kernel(FSide f0, FSide f1, const int* __restrict__ off, const int* __restrict__ cnt) {
    const int t = blockIdx.y;
    FSide s = t ? f1 : f0;
    const int* of = off + t * NN;
    const int* cn = cnt + t * NN;
    const int warp = threadIdx.x >> 5;
    const int lane = threadIdx.x & 31;
    const int row = blockIdx.x * 8 + warp;
    if (row >= NN) return;
    const int c = lane * 2;
    const int beg = __ldg(&of[row]);
    const int deg = __ldg(&cn[row]);

    float x0 = 0.f, y0 = 0.f, x1 = 0.f, y1 = 0.f;
    int e = 0;
    for (; e + 1 < deg; e += 2) {
        int s0 = __ldg(&s.csr[beg + e]);
        int s1 = __ldg(&s.csr[beg + e + 1]);
        float2 v0 = *(const float2*)(s.proj_src + (size_t)s0 * OD + c);
        float2 v1 = *(const float2*)(s.proj_src + (size_t)s1 * OD + c);
        x0 += v0.x; y0 += v0.y;
        x1 += v1.x; y1 += v1.y;
    }
    if (e < deg) {
        int s0 = __ldg(&s.csr[beg + e]);
        float2 v0 = *(const float2*)(s.proj_src + (size_t)s0 * OD + c);
        x0 += v0.x; y0 += v0.y;
    }
    const float sc = 1.0f / fmaxf((float)deg, 1.0f);
    float2 rv = *(const float2*)(s.root + (size_t)row * OD + c);
    float2 bv = __ldg((const float2*)(s.bias + c));
    float v0 = (x0 + x1) * sc + rv.x + bv.x;
    float v1 = (y0 + y1) * sc + rv.y + bv.y;

    float s1v = v0 + v1;
    float s2v = v0 * v0 + v1 * v1;
#pragma unroll
    for (int o = 16; o > 0; o >>= 1) {
        s1v += __shfl_xor_sync(0xFFFFFFFFu, s1v, o);
        s2v += __shfl_xor_sync(0xFFFFFFFFu, s2v, o);
    }
    float mean = s1v * (1.0f / 64.0f);
    float var = s2v * (1.0f / 64.0f) - mean * mean;
    float rstd = rsqrtf(var + 1e-5f);
    float2 gv = __ldg((const float2*)(s.g + c));
    float2 bb = __ldg((const float2*)(s.b + c));
    float2 o2;
    o2.x = (v0 - mean) * rstd * gv.x + bb.x;
    o2.y = (v1 - mean) * rstd * gv.y + bb.y;
    *(float2*)(s.out + (size_t)row * 64 + c) = o2;
}

// weight transpose + fp16 hi/lo split
struct WCon { const float* w; __half* h; __half* l; int K, N, Kpad; };
struct WCon10 { WCon s[10]; };
__global__ void wconv_kernel(WCon10 P) {
    WCon w = P.s[blockIdx.y];
    int idx = blockIdx.x * blockDim.x + threadIdx.x;
    if (idx >= w.N * w.Kpad) return;
    int n = idx / w.Kpad, k = idx % w.Kpad;
    float x = (k < w.K) ? w.w[(size_t)k * w.N + n] : 0.0f;
    __half h = __float2half(x);
    w.h[idx] = h;
    w.l[idx] = __float2half(x - __half2float(h));
}

// ---------------- HMMA fp16 GEMM, BN=128, 4x2 warp tiling, paired via gridDim.y ----------------
// 2-pass fp16: A single fp16 plane; B fp16 hi/lo (weights exact). C = ah*bh + ah*bl.
// B tiles double-buffered via cp.async. A fp32-convert path or pre-fp16-plane cp.async path.
// OUTHALF: write result as fp16 plane (row-major 128). SPLIT: cols 0-63 -> out, 64-127 -> out2 (stride 64).
#define BN 128

struct GSide {
    const float* A1; const __half* A1h;
    const __half* W1h; const __half* W1l; int K1; int K1pad;
    const float* A2; const __half* W2h; const __half* W2l; int K2; int K2pad;
    const float* bias; const float* gamma; const float* beta;
    float* out; float* out2; __half* outh;
};

template <bool FUSE2, bool A1HALF, bool OUTHALF, bool SPLIT, bool DO_LN, bool DO_RELU>
__global__ __launch_bounds__(256, 2)
void mma_gemm(GSide s0, GSide s1, int M) {
    const GSide& S = blockIdx.y ? s1 : s0;

    extern __shared__ char smem[];
    const uint32_t sb = smem_u32(smem);
    const uint32_t aB = sb;                 // A: 128 x 64 fp16 = 16KB
    const uint32_t bBuf0 = sb + 16384;      // B: per buffer bHi(16KB)+bLo(16KB); 2 buffers

    const int tid = threadIdx.x;
    const int warp = tid >> 5;
    const int lane = tid & 31;
    const int wm = warp & 3;
    const int wn = warp >> 2;
    const int r0 = blockIdx.x * 128;

    float acc[2][8][4];
#pragma unroll
    for (int mt = 0; mt < 2; mt++)
#pragma unroll
        for (int nt = 0; nt < 8; nt++)
#pragma unroll
            for (int j = 0; j < 4; j++) acc[mt][nt][j] = 0.0f;

    // staging mapping
    const int ar = tid >> 1;
    const int acb = (tid & 1) * 32;
    const int bn = tid >> 1;
    const int bq = tid & 1;

    // compute-phase lane constants
    const uint32_t a_off0 = (uint32_t)(wm * 32 + (lane & 15)) * 128;
    const uint32_t a_off1 = a_off0 + 16 * 128;
    const uint32_t a_xm = (lane & 7) * 16;
    const uint32_t a_khalf = ((lane >> 4) & 1) * 16;
    const uint32_t b_rowbase = (uint32_t)(wn * 64 + (lane & 7) + ((lane >> 4) & 1) * 8) * 128;
    const uint32_t b_xm = (lane & 7) * 16;
    const uint32_t b_khalf = ((lane >> 3) & 1) * 16;

    const int nch1 = S.K1pad >> 6;
    const int nch = nch1 + (FUSE2 ? (S.K2pad >> 6) : 0);

    auto issueB = [&](int c, int buf) {
        const __half *Wh, *Wl;
        int k0, Kpad;
        if (!FUSE2 || c < nch1) { Wh = S.W1h; Wl = S.W1l; k0 = c * 64; Kpad = S.K1pad; }
        else                    { Wh = S.W2h; Wl = S.W2l; k0 = (c - nch1) * 64; Kpad = S.K2pad; }
        const uint32_t bH = bBuf0 + (uint32_t)buf * 32768;
        const uint32_t bL = bH + 16384;
#pragma unroll
        for (int i = 0; i < 4; i++) {
            const int ck = bq * 32 + i * 8;
            const size_t so = (size_t)bn * Kpad + k0 + ck;
            const uint32_t off = SWZ(bn * 128 + ck * 2);
            CPA16(bH + off, Wh + so);
            CPA16(bL + off, Wl + so);
        }
        CPA_COMMIT();
    };

    issueB(0, 0);

    for (int c = 0; c < nch; c++) {
        if (c) __syncthreads();

        // ---- stage A ----
        if (A1HALF && (!FUSE2 || c < nch1)) {
            // pre-split fp16 plane: async swizzled copy
            const int grow = r0 + ar;
            const int srow = (grow < M) ? grow : 0;
            const int k0 = c * 64;
            const __half* src = S.A1h + (size_t)srow * HD + k0 + acb;
#pragma unroll
            for (int i = 0; i < 4; i++) {
                const uint32_t off = SWZ(ar * 128 + (acb + i * 8) * 2);
                CPA16(aB + off, src + i * 8);
            }
            CPA_COMMIT();
        } else {
            const float* A;
            int k0, K;
            if (!FUSE2 || c < nch1) { A = S.A1; k0 = c * 64; K = S.K1; }
            else                    { A = S.A2; k0 = (c - nch1) * 64; K = S.K2; }
            const int grow = r0 + ar;
            const float* arow = A + (size_t)grow * K;
#pragma unroll
            for (int i = 0; i < 4; i++) {
                const int cc = acb + i * 8;
                float x[8];
#pragma unroll
                for (int j = 0; j < 8; j++) x[j] = 0.0f;
                if (grow < M && (k0 + cc) < K) {
                    float4 v0 = *(const float4*)(arow + k0 + cc);
                    float4 v1 = *(const float4*)(arow + k0 + cc + 4);
                    x[0] = v0.x; x[1] = v0.y; x[2] = v0.z; x[3] = v0.w;
                    x[4] = v1.x; x[5] = v1.y; x[6] = v1.z; x[7] = v1.w;
                }
                uint32_t h4[4];
#pragma unroll
                for (int j = 0; j < 4; j++) h4[j] = pack_h2(x[2 * j], x[2 * j + 1]);
                const uint32_t off = SWZ(ar * 128 + cc * 2);
                asm volatile("st.shared.v4.b32 [%0], {%1, %2, %3, %4};" :: "r"(aB + off), "r"(h4[0]), "r"(h4[1]), "r"(h4[2]), "r"(h4[3]) : "memory");
            }
        }

        // ---- prefetch next B, then wait ----
        if (c + 1 < nch) {
            issueB(c + 1, (c + 1) & 1);
            CPA_WAIT1();   // completes B(c) and (if issued) A(c); leaves B(c+1) in flight
        } else {
            CPA_WAIT0();
        }
        __syncthreads();

        // ---- compute: 2-pass fp16 (ah*bh + ah*bl) ----
        const uint32_t bHiC = bBuf0 + (uint32_t)(c & 1) * 32768;
        const uint32_t bLoC = bHiC + 16384;
#pragma unroll
        for (int ks = 0; ks < 4; ks++) {
            const uint32_t akb = ((uint32_t)(ks * 32) + a_khalf) ^ a_xm;
            uint32_t ah[2][4];
            ldm4(ah[0], aB + a_off0 + akb);
            ldm4(ah[1], aB + a_off1 + akb);
            const uint32_t bkb = ((uint32_t)(ks * 32) + b_khalf) ^ b_xm;
#pragma unroll
            for (int j = 0; j < 4; j++) {
                uint32_t bh[4], bl[4];
                const uint32_t boff = b_rowbase + (uint32_t)j * 2048;
                ldm4(bh, bHiC + boff + bkb);
                ldm4(bl, bLoC + boff + bkb);
#pragma unroll
                for (int mt = 0; mt < 2; mt++) {
                    mma_fp16(acc[mt][2 * j],     ah[mt], bh[0], bh[1]);
                    mma_fp16(acc[mt][2 * j],     ah[mt], bl[0], bl[1]);
                    mma_fp16(acc[mt][2 * j + 1], ah[mt], bh[2], bh[3]);
                    mma_fp16(acc[mt][2 * j + 1], ah[mt], bl[2], bl[3]);
                }
            }
        }
    }

    // ---- epilogue ----
    const int rq = lane >> 2;
    const int cq = (lane & 3) * 2;

    if (S.bias) {
#pragma unroll
        for (int nt = 0; nt < 8; nt++) {
            float2 bv = __ldg((const float2*)(S.bias + wn * 64 + nt * 8 + cq));
#pragma unroll
            for (int mt = 0; mt < 2; mt++) {
                acc[mt][nt][0] += bv.x; acc[mt][nt][1] += bv.y;
                acc[mt][nt][2] += bv.x; acc[mt][nt][3] += bv.y;
            }
        }
    }
    if (DO_LN) {
        float s1[2][2], s2[2][2];
#pragma unroll
        for (int mt = 0; mt < 2; mt++)
#pragma unroll
            for (int h = 0; h < 2; h++) { s1[mt][h] = 0.f; s2[mt][h] = 0.f; }
#pragma unroll
        for (int mt = 0; mt < 2; mt++)
#pragma unroll
            for (int nt = 0; nt < 8; nt++) {
                s1[mt][0] += acc[mt][nt][0] + acc[mt][nt][1];
                s2[mt][0] += acc[mt][nt][0] * acc[mt][nt][0] + acc[mt][nt][1] * acc[mt][nt][1];
                s1[mt][1] += acc[mt][nt][2] + acc[mt][nt][3];
                s2[mt][1] += acc[mt][nt][2] * acc[mt][nt][2] + acc[mt][nt][3] * acc[mt][nt][3];
            }
#pragma unroll
        for (int o = 1; o < 4; o <<= 1) {
#pragma unroll
            for (int mt = 0; mt < 2; mt++)
#pragma unroll
                for (int h = 0; h < 2; h++) {
                    s1[mt][h] += __shfl_xor_sync(0xFFFFFFFFu, s1[mt][h], o);
                    s2[mt][h] += __shfl_xor_sync(0xFFFFFFFFu, s2[mt][h], o);
                }
        }
        float* sc = (float*)smem;
        __syncthreads();
        if ((lane & 3) == 0) {
#pragma unroll
            for (int mt = 0; mt < 2; mt++)
#pragma unroll
                for (int h = 0; h < 2; h++) {
                    int rl = wm * 32 + mt * 16 + h * 8 + rq;
                    sc[wn * 128 + rl] = s1[mt][h];
                    sc[256 + wn * 128 + rl] = s2[mt][h];
                }
        }
        __syncthreads();
#pragma unroll
        for (int mt = 0; mt < 2; mt++)
#pragma unroll
            for (int h = 0; h < 2; h++) {
                int rl = wm * 32 + mt * 16 + h * 8 + rq;
                float S1 = sc[rl] + sc[128 + rl];
                float S2 = sc[256 + rl] + sc[384 + rl];
                float mean = S1 * (1.0f / 128.0f);
                float var = S2 * (1.0f / 128.0f) - mean * mean;
                float rstd = rsqrtf(var + 1e-5f);
                s1[mt][h] = mean;
                s2[mt][h] = rstd;
            }
#pragma unroll
        for (int nt = 0; nt < 8; nt++) {
            float2 g = __ldg((const float2*)(S.gamma + wn * 64 + nt * 8 + cq));
            float2 b = __ldg((const float2*)(S.beta + wn * 64 + nt * 8 + cq));
#pragma unroll
            for (int mt = 0; mt < 2; mt++) {
                acc[mt][nt][0] = (acc[mt][nt][0] - s1[mt][0]) * s2[mt][0] * g.x + b.x;
                acc[mt][nt][1] = (acc[mt][nt][1] - s1[mt][0]) * s2[mt][0] * g.y + b.y;
                acc[mt][nt][2] = (acc[mt][nt][2] - s1[mt][1]) * s2[mt][1] * g.x + b.x;
                acc[mt][nt][3] = (acc[mt][nt][3] - s1[mt][1]) * s2[mt][1] * g.y + b.y;
            }
        }
    }
    if (DO_RELU) {
#pragma unroll
        for (int mt = 0; mt < 2; mt++)
#pragma unroll
            for (int nt = 0; nt < 8; nt++)
#pragma unroll
                for (int j = 0; j < 4; j++) acc[mt][nt][j] = fmaxf(acc[mt][nt][j], 0.0f);
    }
    if (OUTHALF) {
#pragma unroll
        for (int mt = 0; mt < 2; mt++)
#pragma unroll
            for (int h = 0; h < 2; h++) {
                int row = r0 + wm * 32 + mt * 16 + h * 8 + rq;
                if (row < M) {
#pragma unroll
                    for (int nt = 0; nt < 8; nt++)
                        *(uint32_t*)(S.outh + (size_t)row * BN + wn * 64 + nt * 8 + cq) =
                            pack_h2(acc[mt][nt][2 * h], acc[mt][nt][2 * h + 1]);
                }
            }
    } else if (SPLIT) {
        float* dst = wn ? S.out2 : S.out;
#pragma unroll
        for (int mt = 0; mt < 2; mt++)
#pragma unroll
            for (int h = 0; h < 2; h++) {
                int row = r0 + wm * 32 + mt * 16 + h * 8 + rq;
                if (row < M) {
#pragma unroll
                    for (int nt = 0; nt < 8; nt++)
                        *(float2*)(dst + (size_t)row * 64 + nt * 8 + cq) =
                            make_float2(acc[mt][nt][2 * h], acc[mt][nt][2 * h + 1]);
                }
            }
    } else {
#pragma unroll
        for (int mt = 0; mt < 2; mt++)
#pragma unroll
            for (int h = 0; h < 2; h++) {
                int row = r0 + wm * 32 + mt * 16 + h * 8 + rq;
                if (row < M) {
#pragma unroll
                    for (int nt = 0; nt < 8; nt++)
                        *(float2*)(S.out + (size_t)row * BN + wn * 64 + nt * 8 + cq) =
                            make_float2(acc[mt][nt][2 * h], acc[mt][nt][2 * h + 1]);
                }
            }
    }
}

// ---------------- host launcher ----------------
extern "C" void kernel_launch(void* const* d_in, const int* in_sizes, int n_in,
                              void* d_out, int out_size) {
    const float* x_user = (const float*)d_in[0];
    const float* x_item = (const float*)d_in[1];
    const int* edge_ui = (const int*)d_in[2];
    const int* edge_iu = (const int*)d_in[3];
    const float* Wp_u = (const float*)d_in[4];
    const float* bp_u = (const float*)d_in[5];
    const float* Wp_i = (const float*)d_in[6];
    const float* bp_i = (const float*)d_in[7];
    const float* Wl0_ui = (const float*)d_in[8];
    const float* bl0_ui = (const float*)d_in[9];
    const float* Wr0_ui = (const float*)d_in[10];
    const float* Wl0_iu = (const float*)d_in[11];
    const float* bl0_iu = (const float*)d_in[12];
    const float* Wr0_iu = (const float*)d_in[13];
    const float* g0_u = (const float*)d_in[14];
    const float* b0_u = (const float*)d_in[15];
    const float* g0_i = (const float*)d_in[16];
    const float* b0_i = (const float*)d_in[17];
    const float* Wl1_ui = (const float*)d_in[18];
    const float* bl1_ui = (const float*)d_in[19];
    const float* Wr1_ui = (const float*)d_in[20];
    const float* Wl1_iu = (const float*)d_in[21];
    const float* bl1_iu = (const float*)d_in[22];
    const float* Wr1_iu = (const float*)d_in[23];
    const float* g1_u = (const float*)d_in[24];
    const float* b1_u = (const float*)d_in[25];
    const float* g1_i = (const float*)d_in[26];
    const float* b1_i = (const float*)d_in[27];

    const int E = in_sizes[2] / 2;

    float *hu, *hi, *proj_u, *root_u, *proj_i, *root_i;
    __half *agg_u, *agg_i, *hu1, *hi1;
    int *cnt, *off, *pos, *csr_iu, *csr_ui, *part;
    cudaGetSymbolAddress((void**)&hu, g_hu);
    cudaGetSymbolAddress((void**)&hi, g_hi);
    cudaGetSymbolAddress((void**)&agg_u, g_agg_u);
    cudaGetSymbolAddress((void**)&agg_i, g_agg_i);
    cudaGetSymbolAddress((void**)&hu1, g_hu1);
    cudaGetSymbolAddress((void**)&hi1, g_hi1);
    cudaGetSymbolAddress((void**)&proj_u, g_proj_u);
    cudaGetSymbolAddress((void**)&root_u, g_root_u);
    cudaGetSymbolAddress((void**)&proj_i, g_proj_i);
    cudaGetSymbolAddress((void**)&root_i, g_root_i);
    cudaGetSymbolAddress((void**)&cnt, g_cnt);
    cudaGetSymbolAddress((void**)&off, g_off);
    cudaGetSymbolAddress((void**)&pos, g_pos);
    cudaGetSymbolAddress((void**)&csr_iu, g_csr_iu);
    cudaGetSymbolAddress((void**)&csr_ui, g_csr_ui);
    cudaGetSymbolAddress((void**)&part, g_part);

    __half *wpu_h, *wpu_l, *wpi_h, *wpi_l;
    __half *wl0ui_h, *wl0ui_l, *wr0ui_h, *wr0ui_l, *wl0iu_h, *wl0iu_l, *wr0iu_h, *wr0iu_l;
    __half *w1u_h, *w1u_l, *w1i_h, *w1i_l;
    cudaGetSymbolAddress((void**)&wpu_h, g_wpu_h);   cudaGetSymbolAddress((void**)&wpu_l, g_wpu_l);
    cudaGetSymbolAddress((void**)&wpi_h, g_wpi_h);   cudaGetSymbolAddress((void**)&wpi_l, g_wpi_l);
    cudaGetSymbolAddress((void**)&wl0ui_h, g_wl0ui_h); cudaGetSymbolAddress((void**)&wl0ui_l, g_wl0ui_l);
    cudaGetSymbolAddress((void**)&wr0ui_h, g_wr0ui_h); cudaGetSymbolAddress((void**)&wr0ui_l, g_wr0ui_l);
    cudaGetSymbolAddress((void**)&wl0iu_h, g_wl0iu_h); cudaGetSymbolAddress((void**)&wl0iu_l, g_wl0iu_l);
    cudaGetSymbolAddress((void**)&wr0iu_h, g_wr0iu_h); cudaGetSymbolAddress((void**)&wr0iu_l, g_wr0iu_l);
    cudaGetSymbolAddress((void**)&w1u_h, g_w1u_h);   cudaGetSymbolAddress((void**)&w1u_l, g_w1u_l);
    cudaGetSymbolAddress((void**)&w1i_h, g_w1i_h);   cudaGetSymbolAddress((void**)&w1i_l, g_w1i_l);

    float* out_u = (float*)d_out;
    float* out_i = (float*)d_out + (size_t)NN * OD;

    const int SM = 16384 + 2 * 32768;   // A 16KB + B 2x32KB = 80KB
    cudaFuncSetAttribute(mma_gemm<false, false, false, false, false, true>, cudaFuncAttributeMaxDynamicSharedMemorySize, SM);
    cudaFuncSetAttribute(mma_gemm<true, true, true, false, true, true>, cudaFuncAttributeMaxDynamicSharedMemorySize, SM);
    cudaFuncSetAttribute(mma_gemm<false, true, false, true, false, false>, cudaFuncAttributeMaxDynamicSharedMemorySize, SM);

    const int GM = (NN + 127) / 128;

    // fork a side stream for the CSR chain (independent of weights/proj)
    cudaStream_t sB;
    cudaEvent_t eFork, eJoin;
    cudaStreamCreateWithFlags(&sB, cudaStreamNonBlocking);
    cudaEventCreateWithFlags(&eFork, cudaEventDisableTiming);
    cudaEventCreateWithFlags(&eJoin, cudaEventDisableTiming);

    cudaEventRecord(eFork, 0);
    cudaStreamWaitEvent(sB, eFork, 0);

    // side stream: degree + CSR build
    {
        dim3 ge((E + 255) / 256, 2);
        zero_cnt_kernel<<<(2 * NN + 255) / 256, 256, 0, sB>>>(cnt);
        count_kernel<<<ge, 256, 0, sB>>>(edge_iu + E, edge_ui + E, E, cnt);
        scan_part_kernel<<<dim3(NBLK, 2), 256, 0, sB>>>(cnt, part);
        scan_partials_kernel<<<dim3(1, 2), 512, 0, sB>>>(part, NBLK);
        scan_final_kernel<<<dim3(NBLK, 2), 256, 0, sB>>>(cnt, part, off, pos);
        build_csr_kernel<<<ge, 256, 0, sB>>>(edge_iu, edge_ui, E, pos, csr_iu, csr_ui);
        cudaEventRecord(eJoin, sB);
    }

    // main stream: weight convert + projection GEMM pair
    {
        WCon10 P;
        P.s[0] = { Wp_u,   wpu_h,   wpu_l,   FU, HD, 128 };
        P.s[1] = { Wp_i,   wpi_h,   wpi_l,   FI, HD, 192 };
        P.s[2] = { Wl0_ui, wl0ui_h, wl0ui_l, HD, HD, 128 };
        P.s[3] = { Wr0_ui, wr0ui_h, wr0ui_l, HD, HD, 128 };
        P.s[4] = { Wl0_iu, wl0iu_h, wl0iu_l, HD, HD, 128 };
        P.s[5] = { Wr0_iu, wr0iu_h, wr0iu_l, HD, HD, 128 };
        P.s[6] = { Wl1_ui, w1u_h,             w1u_l,             HD, OD, 128 };
        P.s[7] = { Wr1_iu, w1u_h + 64 * 128,  w1u_l + 64 * 128,  HD, OD, 128 };
        P.s[8] = { Wl1_iu, w1i_h,             w1i_l,             HD, OD, 128 };
        P.s[9] = { Wr1_ui, w1i_h + 64 * 128,  w1i_l + 64 * 128,  HD, OD, 128 };
        dim3 g((192 * 128 + 255) / 256, 10);
        wconv_kernel<<<g, 256>>>(P);
    }
    {
        GSide su = { x_user, nullptr, wpu_h, wpu_l, FU, 128, nullptr, nullptr, nullptr, 0, 0,
                     bp_u, nullptr, nullptr, hu, nullptr, nullptr };
        GSide si = { x_item, nullptr, wpi_h, wpi_l, FI, 192, nullptr, nullptr, nullptr, 0, 0,
                     bp_i, nullptr, nullptr, hi, nullptr, nullptr };
        mma_gemm<false, false, false, false, false, true><<<dim3(GM, 2), 256, SM>>>(su, si, NN);
    }

    // join: gather needs CSR + proj outputs
    cudaStreamWaitEvent(0, eJoin, 0);

    // layer 0 aggregation (fp16 output). t=0: agg_u <- hi via csr_iu; t=1: agg_i <- hu via csr_ui
    {
        const long tot = (long)NN * 32;
        dim3 gg((unsigned)((tot + 255) / 256), 2);
        gather_mean_kernel<<<gg, 256>>>(hi, csr_iu, agg_u, hu, csr_ui, agg_i, off, cnt);
    }

    // layer 0 fused dual-GEMM + bias + LN + ReLU -> fp16 h1 planes
    {
        GSide si = { nullptr, agg_i, wl0ui_h, wl0ui_l, HD, 128, hi, wr0ui_h, wr0ui_l, HD, 128,
                     bl0_ui, g0_i, b0_i, nullptr, nullptr, hi1 };
        GSide su = { nullptr, agg_u, wl0iu_h, wl0iu_l, HD, 128, hu, wr0iu_h, wr0iu_l, HD, 128,
                     bl0_iu, g0_u, b0_u, nullptr, nullptr, hu1 };
        mma_gemm<true, true, true, false, true, true><<<dim3(GM, 2), 256, SM>>>(si, su, NN);
    }

    // layer 1 combined GEMM pair: [proj|root] = h1 @ [Wl1 | Wr1], fp16 A plane, split fp32 outputs
    {
        GSide su = { nullptr, hu1, w1u_h, w1u_l, HD, 128, nullptr, nullptr, nullptr, 0, 0,
                     nullptr, nullptr, nullptr, proj_u, root_u, nullptr };
        GSide si = { nullptr, hi1, w1i_h, w1i_l, HD, 128, nullptr, nullptr, nullptr, 0, 0,
                     nullptr, nullptr, nullptr, proj_i, root_i, nullptr };
        mma_gemm<false, true, false, true, false, false><<<dim3(GM, 2), 256, SM>>>(su, si, NN);
    }

    // fused layer-1 gather + final LN
    {
        FSide fu = { proj_i, root_u, csr_iu, bl1_iu, g1_u, b1_u, out_u };
        FSide fi = { proj_u, root_i, csr_ui, bl1_ui, g1_i, b1_i, out_i };
        dim3 gf((NN + 7) / 8, 2);
        final_fused_kernel<<<gf, 256>>>(fu, fi, off, cnt);
    }

    (void)n_in; (void)out_size; (void)in_sizes;
}

// round 11
// speedup vs baseline: 1.4989x; 1.1025x over previous
#include <cuda_runtime.h>
#include <cuda_fp16.h>
#include <cstdint>

// ---------------- problem constants ----------------
#define NU 100000
#define NI 100000
#define NN 100000   // NU == NI
#define FU 96
#define FI 160
#define HD 128
#define OD 64
#define EMAX 600000
#define NBLK 391   // ceil(100000/256)

// ---------------- scratch (device globals) ----------------
__device__ __half g_hu   [NN * HD];   // fp16 proj planes (gather input + layer0 root)
__device__ __half g_hi   [NN * HD];
__device__ __half g_agg_u[NN * HD];   // fp16 agg planes (gather output = layer0 A)
__device__ __half g_agg_i[NN * HD];
__device__ __half g_hu1  [NN * HD];   // fp16 h1 planes (layer0 out = layer1 A)
__device__ __half g_hi1  [NN * HD];
__device__ float  g_proj_u[NN * OD];
__device__ float  g_root_u[NN * OD];
__device__ float  g_proj_i[NN * OD];
__device__ float  g_root_i[NN * OD];
__device__ int    g_cnt [2 * NN];
__device__ int    g_off [2 * NN];
__device__ int    g_pos [2 * NN];
__device__ int    g_csr_iu[EMAX];
__device__ int    g_csr_ui[EMAX];
__device__ int    g_part[2 * 512];

// transposed/split fp16 weights: layout [N rows, Kpad cols], zero padded
__device__ __half g_wpu_h[128 * 128],  g_wpu_l[128 * 128];
__device__ __half g_wpi_h[128 * 192],  g_wpi_l[128 * 192];
__device__ __half g_wl0ui_h[128 * 128], g_wl0ui_l[128 * 128];
__device__ __half g_wr0ui_h[128 * 128], g_wr0ui_l[128 * 128];
__device__ __half g_wl0iu_h[128 * 128], g_wl0iu_l[128 * 128];
__device__ __half g_wr0iu_h[128 * 128], g_wr0iu_l[128 * 128];
__device__ __half g_w1u_h[128 * 128],  g_w1u_l[128 * 128];   // [Wl1_ui | Wr1_iu]
__device__ __half g_w1i_h[128 * 128],  g_w1i_l[128 * 128];   // [Wl1_iu | Wr1_ui]

// ---------------- helpers ----------------
__device__ __forceinline__ uint32_t smem_u32(const void* p) {
    uint32_t a;
    asm("{ .reg .u64 t; cvta.to.shared.u64 t, %1; cvt.u32.u64 %0, t; }" : "=r"(a) : "l"(p));
    return a;
}
#define SWZ(x) ((x) ^ (((x) >> 3) & 0x70))

#define CPA16(dst, src) \
    asm volatile("cp.async.ca.shared.global [%0], [%1], 16;" :: "r"(dst), "l"(src) : "memory")
#define CPA_COMMIT() asm volatile("cp.async.commit_group;" ::: "memory")
#define CPA_WAIT1()  asm volatile("cp.async.wait_group 1;" ::: "memory")
#define CPA_WAIT0()  asm volatile("cp.async.wait_group 0;" ::: "memory")

__device__ __forceinline__ void ldm4(uint32_t* r, uint32_t addr) {
    asm volatile("ldmatrix.sync.aligned.m8n8.x4.shared.b16 {%0,%1,%2,%3}, [%4];"
        : "=r"(r[0]), "=r"(r[1]), "=r"(r[2]), "=r"(r[3]) : "r"(addr));
}
__device__ __forceinline__ void mma_fp16(float* c, const uint32_t* a, uint32_t b0, uint32_t b1) {
    asm volatile("mma.sync.aligned.m16n8k16.row.col.f32.f16.f16.f32 "
        "{%0,%1,%2,%3}, {%4,%5,%6,%7}, {%8,%9}, {%0,%1,%2,%3};"
        : "+f"(c[0]), "+f"(c[1]), "+f"(c[2]), "+f"(c[3])
        : "r"(a[0]), "r"(a[1]), "r"(a[2]), "r"(a[3]), "r"(b0), "r"(b1));
}
__device__ __forceinline__ uint32_t pack_h2(float x0, float x1) {
    __half2 h = __floats2half2_rn(x0, x1);
    return *reinterpret_cast<uint32_t*>(&h);
}

// ---------------- CSR build chain ----------------
__global__ void zero_cnt_kernel(int* __restrict__ cnt) {
    int i = blockIdx.x * blockDim.x + threadIdx.x;
    if (i < 2 * NN) cnt[i] = 0;
}

__global__ void count_kernel(const int* __restrict__ dst0, const int* __restrict__ dst1,
                             int E, int* __restrict__ cnt) {
    int t = blockIdx.y;
    const int* dst = t ? dst1 : dst0;
    int* c = cnt + t * NN;
    int e = blockIdx.x * blockDim.x + threadIdx.x;
    if (e < E) atomicAdd(&c[dst[e]], 1);
}

__global__ void scan_part_kernel(const int* __restrict__ cnt, int* __restrict__ part) {
    __shared__ int sh[256];
    const int* c = cnt + blockIdx.y * NN;
    int* p = part + blockIdx.y * 512;
    int i = blockIdx.x * 256 + threadIdx.x;
    sh[threadIdx.x] = (i < NN) ? c[i] : 0;
    __syncthreads();
    for (int s = 128; s > 0; s >>= 1) {
        if (threadIdx.x < s) sh[threadIdx.x] += sh[threadIdx.x + s];
        __syncthreads();
    }
    if (threadIdx.x == 0) p[blockIdx.x] = sh[0];
}

__global__ void scan_partials_kernel(int* __restrict__ part, int nb) {
    __shared__ int sh[512];
    int* p = part + blockIdx.y * 512;
    int t = threadIdx.x;
    int v = (t < nb) ? p[t] : 0;
    sh[t] = v;
    __syncthreads();
    for (int o = 1; o < 512; o <<= 1) {
        int x = (t >= o) ? sh[t - o] : 0;
        __syncthreads();
        sh[t] += x;
        __syncthreads();
    }
    if (t < nb) p[t] = sh[t] - v;  // exclusive
}

__global__ void scan_final_kernel(const int* __restrict__ cnt, const int* __restrict__ part,
                                  int* __restrict__ off, int* __restrict__ pos) {
    __shared__ int sh[256];
    const int* c = cnt + blockIdx.y * NN;
    const int* p = part + blockIdx.y * 512;
    int* of = off + blockIdx.y * NN;
    int* ps = pos + blockIdx.y * NN;
    int t = threadIdx.x;
    int i = blockIdx.x * 256 + t;
    int v = (i < NN) ? c[i] : 0;
    sh[t] = v;
    __syncthreads();
    for (int o = 1; o < 256; o <<= 1) {
        int x = (t >= o) ? sh[t - o] : 0;
        __syncthreads();
        sh[t] += x;
        __syncthreads();
    }
    if (i < NN) {
        int e = sh[t] - v + p[blockIdx.x];
        of[i] = e;
        ps[i] = e;
    }
}

__global__ void build_csr_kernel(const int* __restrict__ e0, const int* __restrict__ e1,
                                 int E, int* __restrict__ pos,
                                 int* __restrict__ c0, int* __restrict__ c1) {
    int t = blockIdx.y;
    const int* edge = t ? e1 : e0;
    int* ps = pos + t * NN;
    int* csr = t ? c1 : c0;
    int e = blockIdx.x * blockDim.x + threadIdx.x;
    if (e < E) {
        int s = edge[e];
        int d = edge[E + e];
        int idx = atomicAdd(&ps[d], 1);
        csr[idx] = s;
    }
}

// ---------------- gather-mean aggregation (layer 0, C=128), fp16 in / fp16 out ----------------
__global__ void gather_mean_kernel(const __half* __restrict__ fA, const int* __restrict__ csrA, __half* __restrict__ oA,
                                   const __half* __restrict__ fB, const int* __restrict__ csrB, __half* __restrict__ oB,
                                   const int* __restrict__ off, const int* __restrict__ cnt) {
    constexpr int G = 32;
    const int t = blockIdx.y;
    const __half* feat = t ? fB : fA;
    const int* csr = t ? csrB : csrA;
    __half* out = t ? oB : oA;
    const int* of = off + t * NN;
    const int* cn = cnt + t * NN;

    int gid = (int)((blockIdx.x * (size_t)blockDim.x + threadIdx.x) / G);
    if (gid >= NN) return;
    const int c4 = (threadIdx.x & (G - 1)) * 4;
    const int beg = __ldg(&of[gid]);
    const int deg = __ldg(&cn[gid]);

    float4 a0 = make_float4(0.f, 0.f, 0.f, 0.f);
    float4 a1 = make_float4(0.f, 0.f, 0.f, 0.f);
    float4 a2 = make_float4(0.f, 0.f, 0.f, 0.f);
    float4 a3 = make_float4(0.f, 0.f, 0.f, 0.f);
    int e = 0;
    for (; e + 3 < deg; e += 4) {
        int s0 = __ldg(&csr[beg + e]);
        int s1 = __ldg(&csr[beg + e + 1]);
        int s2 = __ldg(&csr[beg + e + 2]);
        int s3 = __ldg(&csr[beg + e + 3]);
        const __half2* p0 = (const __half2*)(feat + (size_t)s0 * HD + c4);
        const __half2* p1 = (const __half2*)(feat + (size_t)s1 * HD + c4);
        const __half2* p2 = (const __half2*)(feat + (size_t)s2 * HD + c4);
        const __half2* p3 = (const __half2*)(feat + (size_t)s3 * HD + c4);
        float2 u0 = __half22float2(p0[0]), w0 = __half22float2(p0[1]);
        float2 u1 = __half22float2(p1[0]), w1 = __half22float2(p1[1]);
        float2 u2 = __half22float2(p2[0]), w2 = __half22float2(p2[1]);
        float2 u3 = __half22float2(p3[0]), w3 = __half22float2(p3[1]);
        a0.x += u0.x; a0.y += u0.y; a0.z += w0.x; a0.w += w0.y;
        a1.x += u1.x; a1.y += u1.y; a1.z += w1.x; a1.w += w1.y;
        a2.x += u2.x; a2.y += u2.y; a2.z += w2.x; a2.w += w2.y;
        a3.x += u3.x; a3.y += u3.y; a3.z += w3.x; a3.w += w3.y;
    }
    for (; e < deg; e++) {
        int s0 = __ldg(&csr[beg + e]);
        const __half2* p0 = (const __half2*)(feat + (size_t)s0 * HD + c4);
        float2 u0 = __half22float2(p0[0]), w0 = __half22float2(p0[1]);
        a0.x += u0.x; a0.y += u0.y; a0.z += w0.x; a0.w += w0.y;
    }
    const float sc = 1.0f / fmaxf((float)deg, 1.0f);
    uint2 r;
    r.x = pack_h2((a0.x + a1.x + a2.x + a3.x) * sc, (a0.y + a1.y + a2.y + a3.y) * sc);
    r.y = pack_h2((a0.z + a1.z + a2.z + a3.z) * sc, (a0.w + a1.w + a2.w + a3.w) * sc);
    *(uint2*)(out + (size_t)gid * HD + c4) = r;
}

// ---------------- fused layer-1 gather + final LN ----------------
struct FSide { const float* proj_src; const float* root; const int* csr;
               const float* bias; const float* g; const float* b; float* out; };
__global__ void final_fused_kernel(FSide f0, FSide f1, const int* __restrict__ off, const int* __restrict__ cnt) {
    const int t = blockIdx.y;
    FSide s = t ? f1 : f0;
    const int* of = off + t * NN;
    const int* cn = cnt + t * NN;
    const int warp = threadIdx.x >> 5;
    const int lane = threadIdx.x & 31;
    const int row = blockIdx.x * 8 + warp;
    if (row >= NN) return;
    const int c = lane * 2;
    const int beg = __ldg(&of[row]);
    const int deg = __ldg(&cn[row]);

    float x0 = 0.f, y0 = 0.f, x1 = 0.f, y1 = 0.f;
    int e = 0;
    for (; e + 1 < deg; e += 2) {
        int s0 = __ldg(&s.csr[beg + e]);
        int s1 = __ldg(&s.csr[beg + e + 1]);
        float2 v0 = *(const float2*)(s.proj_src + (size_t)s0 * OD + c);
        float2 v1 = *(const float2*)(s.proj_src + (size_t)s1 * OD + c);
        x0 += v0.x; y0 += v0.y;
        x1 += v1.x; y1 += v1.y;
    }
    if (e < deg) {
        int s0 = __ldg(&s.csr[beg + e]);
        float2 v0 = *(const float2*)(s.proj_src + (size_t)s0 * OD + c);
        x0 += v0.x; y0 += v0.y;
    }
    const float sc = 1.0f / fmaxf((float)deg, 1.0f);
    float2 rv = *(const float2*)(s.root + (size_t)row * OD + c);
    float2 bv = __ldg((const float2*)(s.bias + c));
    float v0 = (x0 + x1) * sc + rv.x + bv.x;
    float v1 = (y0 + y1) * sc + rv.y + bv.y;

    float s1v = v0 + v1;
    float s2v = v0 * v0 + v1 * v1;
#pragma unroll
    for (int o = 16; o > 0; o >>= 1) {
        s1v += __shfl_xor_sync(0xFFFFFFFFu, s1v, o);
        s2v += __shfl_xor_sync(0xFFFFFFFFu, s2v, o);
    }
    float mean = s1v * (1.0f / 64.0f);
    float var = s2v * (1.0f / 64.0f) - mean * mean;
    float rstd = rsqrtf(var + 1e-5f);
    float2 gv = __ldg((const float2*)(s.g + c));
    float2 bb = __ldg((const float2*)(s.b + c));
    float2 o2;
    o2.x = (v0 - mean) * rstd * gv.x + bb.x;
    o2.y = (v1 - mean) * rstd * gv.y + bb.y;
    *(float2*)(s.out + (size_t)row * 64 + c) = o2;
}

// weight transpose + fp16 hi/lo split
struct WCon { const float* w; __half* h; __half* l; int K, N, Kpad; };
struct WCon10 { WCon s[10]; };
__global__ void wconv_kernel(WCon10 P) {
    WCon w = P.s[blockIdx.y];
    int idx = blockIdx.x * blockDim.x + threadIdx.x;
    if (idx >= w.N * w.Kpad) return;
    int n = idx / w.Kpad, k = idx % w.Kpad;
    float x = (k < w.K) ? w.w[(size_t)k * w.N + n] : 0.0f;
    __half h = __float2half(x);
    w.h[idx] = h;
    w.l[idx] = __float2half(x - __half2float(h));
}

// ---------------- HMMA fp16 GEMM, BN=128, 4x2 warp tiling, paired via gridDim.y ----------------
// 2-pass fp16: A single fp16 plane; B fp16 hi/lo (weights exact). C = ah*bh + ah*bl.
// AHALF: all A segments are fp16 planes (A1h, A2h) loaded via cp.async; else fp32-convert from A1.
// OUTHALF: write result as fp16 plane (row-major 128). SPLIT: cols 0-63 -> out, 64-127 -> out2 (stride 64).
#define BN 128

struct GSide {
    const float* A1; const __half* A1h; const __half* A2h;
    const __half* W1h; const __half* W1l; int K1; int K1pad;
    const __half* W2h; const __half* W2l; int K2pad;
    const float* bias; const float* gamma; const float* beta;
    float* out; float* out2; __half* outh;
};

template <bool FUSE2, bool AHALF, bool OUTHALF, bool SPLIT, bool DO_LN, bool DO_RELU>
__global__ __launch_bounds__(256, 2)
void mma_gemm(GSide s0, GSide s1, int M) {
    const GSide& S = blockIdx.y ? s1 : s0;

    extern __shared__ char smem[];
    const uint32_t sb = smem_u32(smem);
    const uint32_t aB = sb;                 // A: 128 x 64 fp16 = 16KB
    const uint32_t bBuf0 = sb + 16384;      // B: per buffer bHi(16KB)+bLo(16KB); 2 buffers

    const int tid = threadIdx.x;
    const int warp = tid >> 5;
    const int lane = tid & 31;
    const int wm = warp & 3;
    const int wn = warp >> 2;
    const int r0 = blockIdx.x * 128;

    float acc[2][8][4];
#pragma unroll
    for (int mt = 0; mt < 2; mt++)
#pragma unroll
        for (int nt = 0; nt < 8; nt++)
#pragma unroll
            for (int j = 0; j < 4; j++) acc[mt][nt][j] = 0.0f;

    // staging mapping
    const int ar = tid >> 1;
    const int acb = (tid & 1) * 32;
    const int bn = tid >> 1;
    const int bq = tid & 1;

    // compute-phase lane constants
    const uint32_t a_off0 = (uint32_t)(wm * 32 + (lane & 15)) * 128;
    const uint32_t a_off1 = a_off0 + 16 * 128;
    const uint32_t a_xm = (lane & 7) * 16;
    const uint32_t a_khalf = ((lane >> 4) & 1) * 16;
    const uint32_t b_rowbase = (uint32_t)(wn * 64 + (lane & 7) + ((lane >> 4) & 1) * 8) * 128;
    const uint32_t b_xm = (lane & 7) * 16;
    const uint32_t b_khalf = ((lane >> 3) & 1) * 16;

    const int nch1 = S.K1pad >> 6;
    const int nch = nch1 + (FUSE2 ? (S.K2pad >> 6) : 0);

    auto issueB = [&](int c, int buf) {
        const __half *Wh, *Wl;
        int k0, Kpad;
        if (!FUSE2 || c < nch1) { Wh = S.W1h; Wl = S.W1l; k0 = c * 64; Kpad = S.K1pad; }
        else                    { Wh = S.W2h; Wl = S.W2l; k0 = (c - nch1) * 64; Kpad = S.K2pad; }
        const uint32_t bH = bBuf0 + (uint32_t)buf * 32768;
        const uint32_t bL = bH + 16384;
#pragma unroll
        for (int i = 0; i < 4; i++) {
            const int ck = bq * 32 + i * 8;
            const size_t so = (size_t)bn * Kpad + k0 + ck;
            const uint32_t off = SWZ(bn * 128 + ck * 2);
            CPA16(bH + off, Wh + so);
            CPA16(bL + off, Wl + so);
        }
        CPA_COMMIT();
    };

    issueB(0, 0);

    for (int c = 0; c < nch; c++) {
        if (c) __syncthreads();

        // ---- stage A ----
        if (AHALF) {
            const __half* base;
            int k0;
            if (!FUSE2 || c < nch1) { base = S.A1h; k0 = c * 64; }
            else                    { base = S.A2h; k0 = (c - nch1) * 64; }
            const int grow = r0 + ar;
            const int srow = (grow < M) ? grow : 0;
            const __half* src = base + (size_t)srow * HD + k0 + acb;
#pragma unroll
            for (int i = 0; i < 4; i++) {
                const uint32_t off = SWZ(ar * 128 + (acb + i * 8) * 2);
                CPA16(aB + off, src + i * 8);
            }
            CPA_COMMIT();
        } else {
            const int k0 = c * 64;
            const int K = S.K1;
            const int grow = r0 + ar;
            const float* arow = S.A1 + (size_t)grow * K;
#pragma unroll
            for (int i = 0; i < 4; i++) {
                const int cc = acb + i * 8;
                float x[8];
#pragma unroll
                for (int j = 0; j < 8; j++) x[j] = 0.0f;
                if (grow < M && (k0 + cc) < K) {
                    float4 v0 = *(const float4*)(arow + k0 + cc);
                    float4 v1 = *(const float4*)(arow + k0 + cc + 4);
                    x[0] = v0.x; x[1] = v0.y; x[2] = v0.z; x[3] = v0.w;
                    x[4] = v1.x; x[5] = v1.y; x[6] = v1.z; x[7] = v1.w;
                }
                uint32_t h4[4];
#pragma unroll
                for (int j = 0; j < 4; j++) h4[j] = pack_h2(x[2 * j], x[2 * j + 1]);
                const uint32_t off = SWZ(ar * 128 + cc * 2);
                asm volatile("st.shared.v4.b32 [%0], {%1, %2, %3, %4};" :: "r"(aB + off), "r"(h4[0]), "r"(h4[1]), "r"(h4[2]), "r"(h4[3]) : "memory");
            }
        }

        // ---- prefetch next B, then wait ----
        if (c + 1 < nch) {
            issueB(c + 1, (c + 1) & 1);
            CPA_WAIT1();   // completes B(c) and (if issued) A(c); leaves B(c+1) in flight
        } else {
            CPA_WAIT0();
        }
        __syncthreads();

        // ---- compute: 2-pass fp16 (ah*bh + ah*bl) ----
        const uint32_t bHiC = bBuf0 + (uint32_t)(c & 1) * 32768;
        const uint32_t bLoC = bHiC + 16384;
#pragma unroll
        for (int ks = 0; ks < 4; ks++) {
            const uint32_t akb = ((uint32_t)(ks * 32) + a_khalf) ^ a_xm;
            uint32_t ah[2][4];
            ldm4(ah[0], aB + a_off0 + akb);
            ldm4(ah[1], aB + a_off1 + akb);
            const uint32_t bkb = ((uint32_t)(ks * 32) + b_khalf) ^ b_xm;
#pragma unroll
            for (int j = 0; j < 4; j++) {
                uint32_t bh[4], bl[4];
                const uint32_t boff = b_rowbase + (uint32_t)j * 2048;
                ldm4(bh, bHiC + boff + bkb);
                ldm4(bl, bLoC + boff + bkb);
#pragma unroll
                for (int mt = 0; mt < 2; mt++) {
                    mma_fp16(acc[mt][2 * j],     ah[mt], bh[0], bh[1]);
                    mma_fp16(acc[mt][2 * j],     ah[mt], bl[0], bl[1]);
                    mma_fp16(acc[mt][2 * j + 1], ah[mt], bh[2], bh[3]);
                    mma_fp16(acc[mt][2 * j + 1], ah[mt], bl[2], bl[3]);
                }
            }
        }
    }

    // ---- epilogue ----
    const int rq = lane >> 2;
    const int cq = (lane & 3) * 2;

    if (S.bias) {
#pragma unroll
        for (int nt = 0; nt < 8; nt++) {
            float2 bv = __ldg((const float2*)(S.bias + wn * 64 + nt * 8 + cq));
#pragma unroll
            for (int mt = 0; mt < 2; mt++) {
                acc[mt][nt][0] += bv.x; acc[mt][nt][1] += bv.y;
                acc[mt][nt][2] += bv.x; acc[mt][nt][3] += bv.y;
            }
        }
    }
    if (DO_LN) {
        float s1[2][2], s2[2][2];
#pragma unroll
        for (int mt = 0; mt < 2; mt++)
#pragma unroll
            for (int h = 0; h < 2; h++) { s1[mt][h] = 0.f; s2[mt][h] = 0.f; }
#pragma unroll
        for (int mt = 0; mt < 2; mt++)
#pragma unroll
            for (int nt = 0; nt < 8; nt++) {
                s1[mt][0] += acc[mt][nt][0] + acc[mt][nt][1];
                s2[mt][0] += acc[mt][nt][0] * acc[mt][nt][0] + acc[mt][nt][1] * acc[mt][nt][1];
                s1[mt][1] += acc[mt][nt][2] + acc[mt][nt][3];
                s2[mt][1] += acc[mt][nt][2] * acc[mt][nt][2] + acc[mt][nt][3] * acc[mt][nt][3];
            }
#pragma unroll
        for (int o = 1; o < 4; o <<= 1) {
#pragma unroll
            for (int mt = 0; mt < 2; mt++)
#pragma unroll
                for (int h = 0; h < 2; h++) {
                    s1[mt][h] += __shfl_xor_sync(0xFFFFFFFFu, s1[mt][h], o);
                    s2[mt][h] += __shfl_xor_sync(0xFFFFFFFFu, s2[mt][h], o);
                }
        }
        float* sc = (float*)smem;
        __syncthreads();
        if ((lane & 3) == 0) {
#pragma unroll
            for (int mt = 0; mt < 2; mt++)
#pragma unroll
                for (int h = 0; h < 2; h++) {
                    int rl = wm * 32 + mt * 16 + h * 8 + rq;
                    sc[wn * 128 + rl] = s1[mt][h];
                    sc[256 + wn * 128 + rl] = s2[mt][h];
                }
        }
        __syncthreads();
#pragma unroll
        for (int mt = 0; mt < 2; mt++)
#pragma unroll
            for (int h = 0; h < 2; h++) {
                int rl = wm * 32 + mt * 16 + h * 8 + rq;
                float S1 = sc[rl] + sc[128 + rl];
                float S2 = sc[256 + rl] + sc[384 + rl];
                float mean = S1 * (1.0f / 128.0f);
                float var = S2 * (1.0f / 128.0f) - mean * mean;
                float rstd = rsqrtf(var + 1e-5f);
                s1[mt][h] = mean;
                s2[mt][h] = rstd;
            }
#pragma unroll
        for (int nt = 0; nt < 8; nt++) {
            float2 g = __ldg((const float2*)(S.gamma + wn * 64 + nt * 8 + cq));
            float2 b = __ldg((const float2*)(S.beta + wn * 64 + nt * 8 + cq));
#pragma unroll
            for (int mt = 0; mt < 2; mt++) {
                acc[mt][nt][0] = (acc[mt][nt][0] - s1[mt][0]) * s2[mt][0] * g.x + b.x;
                acc[mt][nt][1] = (acc[mt][nt][1] - s1[mt][0]) * s2[mt][0] * g.y + b.y;
                acc[mt][nt][2] = (acc[mt][nt][2] - s1[mt][1]) * s2[mt][1] * g.x + b.x;
                acc[mt][nt][3] = (acc[mt][nt][3] - s1[mt][1]) * s2[mt][1] * g.y + b.y;
            }
        }
    }
    if (DO_RELU) {
#pragma unroll
        for (int mt = 0; mt < 2; mt++)
#pragma unroll
            for (int nt = 0; nt < 8; nt++)
#pragma unroll
                for (int j = 0; j < 4; j++) acc[mt][nt][j] = fmaxf(acc[mt][nt][j], 0.0f);
    }
    if (OUTHALF) {
#pragma unroll
        for (int mt = 0; mt < 2; mt++)
#pragma unroll
            for (int h = 0; h < 2; h++) {
                int row = r0 + wm * 32 + mt * 16 + h * 8 + rq;
                if (row < M) {
#pragma unroll
                    for (int nt = 0; nt < 8; nt++)
                        *(uint32_t*)(S.outh + (size_t)row * BN + wn * 64 + nt * 8 + cq) =
                            pack_h2(acc[mt][nt][2 * h], acc[mt][nt][2 * h + 1]);
                }
            }
    } else if (SPLIT) {
        float* dst = wn ? S.out2 : S.out;
#pragma unroll
        for (int mt = 0; mt < 2; mt++)
#pragma unroll
            for (int h = 0; h < 2; h++) {
                int row = r0 + wm * 32 + mt * 16 + h * 8 + rq;
                if (row < M) {
#pragma unroll
                    for (int nt = 0; nt < 8; nt++)
                        *(float2*)(dst + (size_t)row * 64 + nt * 8 + cq) =
                            make_float2(acc[mt][nt][2 * h], acc[mt][nt][2 * h + 1]);
                }
            }
    } else {
#pragma unroll
        for (int mt = 0; mt < 2; mt++)
#pragma unroll
            for (int h = 0; h < 2; h++) {
                int row = r0 + wm * 32 + mt * 16 + h * 8 + rq;
                if (row < M) {
#pragma unroll
                    for (int nt = 0; nt < 8; nt++)
                        *(float2*)(S.out + (size_t)row * BN + wn * 64 + nt * 8 + cq) =
                            make_float2(acc[mt][nt][2 * h], acc[mt][nt][2 * h + 1]);
                }
            }
    }
}

// ---------------- host launcher ----------------
extern "C" void kernel_launch(void* const* d_in, const int* in_sizes, int n_in,
                              void* d_out, int out_size) {
    const float* x_user = (const float*)d_in[0];
    const float* x_item = (const float*)d_in[1];
    const int* edge_ui = (const int*)d_in[2];
    const int* edge_iu = (const int*)d_in[3];
    const float* Wp_u = (const float*)d_in[4];
    const float* bp_u = (const float*)d_in[5];
    const float* Wp_i = (const float*)d_in[6];
    const float* bp_i = (const float*)d_in[7];
    const float* Wl0_ui = (const float*)d_in[8];
    const float* bl0_ui = (const float*)d_in[9];
    const float* Wr0_ui = (const float*)d_in[10];
    const float* Wl0_iu = (const float*)d_in[11];
    const float* bl0_iu = (const float*)d_in[12];
    const float* Wr0_iu = (const float*)d_in[13];
    const float* g0_u = (const float*)d_in[14];
    const float* b0_u = (const float*)d_in[15];
    const float* g0_i = (const float*)d_in[16];
    const float* b0_i = (const float*)d_in[17];
    const float* Wl1_ui = (const float*)d_in[18];
    const float* bl1_ui = (const float*)d_in[19];
    const float* Wr1_ui = (const float*)d_in[20];
    const float* Wl1_iu = (const float*)d_in[21];
    const float* bl1_iu = (const float*)d_in[22];
    const float* Wr1_iu = (const float*)d_in[23];
    const float* g1_u = (const float*)d_in[24];
    const float* b1_u = (const float*)d_in[25];
    const float* g1_i = (const float*)d_in[26];
    const float* b1_i = (const float*)d_in[27];

    const int E = in_sizes[2] / 2;

    float *proj_u, *root_u, *proj_i, *root_i;
    __half *hu, *hi, *agg_u, *agg_i, *hu1, *hi1;
    int *cnt, *off, *pos, *csr_iu, *csr_ui, *part;
    cudaGetSymbolAddress((void**)&hu, g_hu);
    cudaGetSymbolAddress((void**)&hi, g_hi);
    cudaGetSymbolAddress((void**)&agg_u, g_agg_u);
    cudaGetSymbolAddress((void**)&agg_i, g_agg_i);
    cudaGetSymbolAddress((void**)&hu1, g_hu1);
    cudaGetSymbolAddress((void**)&hi1, g_hi1);
    cudaGetSymbolAddress((void**)&proj_u, g_proj_u);
    cudaGetSymbolAddress((void**)&root_u, g_root_u);
    cudaGetSymbolAddress((void**)&proj_i, g_proj_i);
    cudaGetSymbolAddress((void**)&root_i, g_root_i);
    cudaGetSymbolAddress((void**)&cnt, g_cnt);
    cudaGetSymbolAddress((void**)&off, g_off);
    cudaGetSymbolAddress((void**)&pos, g_pos);
    cudaGetSymbolAddress((void**)&csr_iu, g_csr_iu);
    cudaGetSymbolAddress((void**)&csr_ui, g_csr_ui);
    cudaGetSymbolAddress((void**)&part, g_part);

    __half *wpu_h, *wpu_l, *wpi_h, *wpi_l;
    __half *wl0ui_h, *wl0ui_l, *wr0ui_h, *wr0ui_l, *wl0iu_h, *wl0iu_l, *wr0iu_h, *wr0iu_l;
    __half *w1u_h, *w1u_l, *w1i_h, *w1i_l;
    cudaGetSymbolAddress((void**)&wpu_h, g_wpu_h);   cudaGetSymbolAddress((void**)&wpu_l, g_wpu_l);
    cudaGetSymbolAddress((void**)&wpi_h, g_wpi_h);   cudaGetSymbolAddress((void**)&wpi_l, g_wpi_l);
    cudaGetSymbolAddress((void**)&wl0ui_h, g_wl0ui_h); cudaGetSymbolAddress((void**)&wl0ui_l, g_wl0ui_l);
    cudaGetSymbolAddress((void**)&wr0ui_h, g_wr0ui_h); cudaGetSymbolAddress((void**)&wr0ui_l, g_wr0ui_l);
    cudaGetSymbolAddress((void**)&wl0iu_h, g_wl0iu_h); cudaGetSymbolAddress((void**)&wl0iu_l, g_wl0iu_l);
    cudaGetSymbolAddress((void**)&wr0iu_h, g_wr0iu_h); cudaGetSymbolAddress((void**)&wr0iu_l, g_wr0iu_l);
    cudaGetSymbolAddress((void**)&w1u_h, g_w1u_h);   cudaGetSymbolAddress((void**)&w1u_l, g_w1u_l);
    cudaGetSymbolAddress((void**)&w1i_h, g_w1i_h);   cudaGetSymbolAddress((void**)&w1i_l, g_w1i_l);

    float* out_u = (float*)d_out;
    float* out_i = (float*)d_out + (size_t)NN * OD;

    const int SM = 16384 + 2 * 32768;   // A 16KB + B 2x32KB = 80KB
    cudaFuncSetAttribute(mma_gemm<false, false, true, false, false, true>, cudaFuncAttributeMaxDynamicSharedMemorySize, SM);
    cudaFuncSetAttribute(mma_gemm<true, true, true, false, true, true>, cudaFuncAttributeMaxDynamicSharedMemorySize, SM);
    cudaFuncSetAttribute(mma_gemm<false, true, false, true, false, false>, cudaFuncAttributeMaxDynamicSharedMemorySize, SM);

    const int GM = (NN + 127) / 128;

    // fork a side stream for the CSR chain (independent of weights/proj)
    cudaStream_t sB;
    cudaEvent_t eFork, eJoin;
    cudaStreamCreateWithFlags(&sB, cudaStreamNonBlocking);
    cudaEventCreateWithFlags(&eFork, cudaEventDisableTiming);
    cudaEventCreateWithFlags(&eJoin, cudaEventDisableTiming);

    cudaEventRecord(eFork, 0);
    cudaStreamWaitEvent(sB, eFork, 0);

    // side stream: degree + CSR build
    {
        dim3 ge((E + 255) / 256, 2);
        zero_cnt_kernel<<<(2 * NN + 255) / 256, 256, 0, sB>>>(cnt);
        count_kernel<<<ge, 256, 0, sB>>>(edge_iu + E, edge_ui + E, E, cnt);
        scan_part_kernel<<<dim3(NBLK, 2), 256, 0, sB>>>(cnt, part);
        scan_partials_kernel<<<dim3(1, 2), 512, 0, sB>>>(part, NBLK);
        scan_final_kernel<<<dim3(NBLK, 2), 256, 0, sB>>>(cnt, part, off, pos);
        build_csr_kernel<<<ge, 256, 0, sB>>>(edge_iu, edge_ui, E, pos, csr_iu, csr_ui);
        cudaEventRecord(eJoin, sB);
    }

    // main stream: weight convert + projection GEMM pair
    {
        WCon10 P;
        P.s[0] = { Wp_u,   wpu_h,   wpu_l,   FU, HD, 128 };
        P.s[1] = { Wp_i,   wpi_h,   wpi_l,   FI, HD, 192 };
        P.s[2] = { Wl0_ui, wl0ui_h, wl0ui_l, HD, HD, 128 };
        P.s[3] = { Wr0_ui, wr0ui_h, wr0ui_l, HD, HD, 128 };
        P.s[4] = { Wl0_iu, wl0iu_h, wl0iu_l, HD, HD, 128 };
        P.s[5] = { Wr0_iu, wr0iu_h, wr0iu_l, HD, HD, 128 };
        P.s[6] = { Wl1_ui, w1u_h,             w1u_l,             HD, OD, 128 };
        P.s[7] = { Wr1_iu, w1u_h + 64 * 128,  w1u_l + 64 * 128,  HD, OD, 128 };
        P.s[8] = { Wl1_iu, w1i_h,             w1i_l,             HD, OD, 128 };
        P.s[9] = { Wr1_ui, w1i_h + 64 * 128,  w1i_l + 64 * 128,  HD, OD, 128 };
        dim3 g((192 * 128 + 255) / 256, 10);
        wconv_kernel<<<g, 256>>>(P);
    }
    {
        GSide su = { x_user, nullptr, nullptr, wpu_h, wpu_l, FU, 128, nullptr, nullptr, 0,
                     bp_u, nullptr, nullptr, nullptr, nullptr, hu };
        GSide si = { x_item, nullptr, nullptr, wpi_h, wpi_l, FI, 192, nullptr, nullptr, 0,
                     bp_i, nullptr, nullptr, nullptr, nullptr, hi };
        mma_gemm<false, false, true, false, false, true><<<dim3(GM, 2), 256, SM>>>(su, si, NN);
    }

    // join: gather needs CSR + proj outputs
    cudaStreamWaitEvent(0, eJoin, 0);

    // layer 0 aggregation (fp16 in/out). t=0: agg_u <- hi via csr_iu; t=1: agg_i <- hu via csr_ui
    {
        const long tot = (long)NN * 32;
        dim3 gg((unsigned)((tot + 255) / 256), 2);
        gather_mean_kernel<<<gg, 256>>>(hi, csr_iu, agg_u, hu, csr_ui, agg_i, off, cnt);
    }

    // layer 0 fused dual-GEMM + bias + LN + ReLU -> fp16 h1 planes (A1=agg fp16, A2=root fp16)
    {
        GSide si = { nullptr, agg_i, hi, wl0ui_h, wl0ui_l, HD, 128, wr0ui_h, wr0ui_l, 128,
                     bl0_ui, g0_i, b0_i, nullptr, nullptr, hi1 };
        GSide su = { nullptr, agg_u, hu, wl0iu_h, wl0iu_l, HD, 128, wr0iu_h, wr0iu_l, 128,
                     bl0_iu, g0_u, b0_u, nullptr, nullptr, hu1 };
        mma_gemm<true, true, true, false, true, true><<<dim3(GM, 2), 256, SM>>>(si, su, NN);
    }

    // layer 1 combined GEMM pair: [proj|root] = h1 @ [Wl1 | Wr1], fp16 A plane, split fp32 outputs
    {
        GSide su = { nullptr, hu1, nullptr, w1u_h, w1u_l, HD, 128, nullptr, nullptr, 0,
                     nullptr, nullptr, nullptr, proj_u, root_u, nullptr };
        GSide si = { nullptr, hi1, nullptr, w1i_h, w1i_l, HD, 128, nullptr, nullptr, 0,
                     nullptr, nullptr, nullptr, proj_i, root_i, nullptr };
        mma_gemm<false, true, false, true, false, false><<<dim3(GM, 2), 256, SM>>>(su, si, NN);
    }

    // fused layer-1 gather + final LN
    {
        FSide fu = { proj_i, root_u, csr_iu, bl1_iu, g1_u, b1_u, out_u };
        FSide fi = { proj_u, root_i, csr_ui, bl1_ui, g1_i, b1_i, out_i };
        dim3 gf((NN + 7) / 8, 2);
        final_fused_kernel<<<gf, 256>>>(fu, fi, off, cnt);
    }

    (void)n_in; (void)out_size; (void)in_sizes;
}

// round 12
// speedup vs baseline: 1.5167x; 1.0118x over previous
#include <cuda_runtime.h>
#include <cuda_fp16.h>
#include <cstdint>

// ---------------- problem constants ----------------
#define NU 100000
#define NI 100000
#define NN 100000   // NU == NI
#define FU 96
#define FI 160
#define HD 128
#define OD 64
#define EMAX 600000
#define NBLK 391   // ceil(100000/256)

// ---------------- scratch (device globals) ----------------
__device__ __half g_hu   [NN * HD];   // fp16 proj planes (gather input + layer0 root)
__device__ __half g_hi   [NN * HD];
__device__ __half g_agg_u[NN * HD];   // fp16 agg planes (gather output = layer0 A)
__device__ __half g_agg_i[NN * HD];
__device__ __half g_hu1  [NN * HD];   // fp16 h1 planes (layer0 out = layer1 A)
__device__ __half g_hi1  [NN * HD];
__device__ __half g_proj_u[NN * OD];  // fp16 layer-1 outputs
__device__ __half g_root_u[NN * OD];
__device__ __half g_proj_i[NN * OD];
__device__ __half g_root_i[NN * OD];
__device__ int    g_cnt [2 * NN];
__device__ int    g_off [2 * NN];
__device__ int    g_pos [2 * NN];
__device__ int    g_csr_iu[EMAX];
__device__ int    g_csr_ui[EMAX];
__device__ int    g_part[2 * 512];

// transposed/split fp16 weights: layout [N rows, Kpad cols], zero padded
__device__ __half g_wpu_h[128 * 128],  g_wpu_l[128 * 128];
__device__ __half g_wpi_h[128 * 192],  g_wpi_l[128 * 192];
__device__ __half g_wl0ui_h[128 * 128], g_wl0ui_l[128 * 128];
__device__ __half g_wr0ui_h[128 * 128], g_wr0ui_l[128 * 128];
__device__ __half g_wl0iu_h[128 * 128], g_wl0iu_l[128 * 128];
__device__ __half g_wr0iu_h[128 * 128], g_wr0iu_l[128 * 128];
__device__ __half g_w1u_h[128 * 128],  g_w1u_l[128 * 128];   // [Wl1_ui | Wr1_iu]
__device__ __half g_w1i_h[128 * 128],  g_w1i_l[128 * 128];   // [Wl1_iu | Wr1_ui]

// ---------------- helpers ----------------
__device__ __forceinline__ uint32_t smem_u32(const void* p) {
    uint32_t a;
    asm("{ .reg .u64 t; cvta.to.shared.u64 t, %1; cvt.u32.u64 %0, t; }" : "=r"(a) : "l"(p));
    return a;
}
#define SWZ(x) ((x) ^ (((x) >> 3) & 0x70))

#define CPA16(dst, src) \
    asm volatile("cp.async.ca.shared.global [%0], [%1], 16;" :: "r"(dst), "l"(src) : "memory")
#define CPA_COMMIT() asm volatile("cp.async.commit_group;" ::: "memory")
#define CPA_WAIT1()  asm volatile("cp.async.wait_group 1;" ::: "memory")
#define CPA_WAIT0()  asm volatile("cp.async.wait_group 0;" ::: "memory")

__device__ __forceinline__ void ldm4(uint32_t* r, uint32_t addr) {
    asm volatile("ldmatrix.sync.aligned.m8n8.x4.shared.b16 {%0,%1,%2,%3}, [%4];"
        : "=r"(r[0]), "=r"(r[1]), "=r"(r[2]), "=r"(r[3]) : "r"(addr));
}
__device__ __forceinline__ void mma_fp16(float* c, const uint32_t* a, uint32_t b0, uint32_t b1) {
    asm volatile("mma.sync.aligned.m16n8k16.row.col.f32.f16.f16.f32 "
        "{%0,%1,%2,%3}, {%4,%5,%6,%7}, {%8,%9}, {%0,%1,%2,%3};"
        : "+f"(c[0]), "+f"(c[1]), "+f"(c[2]), "+f"(c[3])
        : "r"(a[0]), "r"(a[1]), "r"(a[2]), "r"(a[3]), "r"(b0), "r"(b1));
}
__device__ __forceinline__ uint32_t pack_h2(float x0, float x1) {
    __half2 h = __floats2half2_rn(x0, x1);
    return *reinterpret_cast<uint32_t*>(&h);
}

// ---------------- CSR build chain ----------------
__global__ void zero_cnt_kernel(int* __restrict__ cnt) {
    int i = blockIdx.x * blockDim.x + threadIdx.x;
    if (i < 2 * NN) cnt[i] = 0;
}

__global__ void count_kernel(const int* __restrict__ dst0, const int* __restrict__ dst1,
                             int E, int* __restrict__ cnt) {
    int t = blockIdx.y;
    const int* dst = t ? dst1 : dst0;
    int* c = cnt + t * NN;
    int e = blockIdx.x * blockDim.x + threadIdx.x;
    if (e < E) atomicAdd(&c[dst[e]], 1);
}

__global__ void scan_part_kernel(const int* __restrict__ cnt, int* __restrict__ part) {
    __shared__ int sh[256];
    const int* c = cnt + blockIdx.y * NN;
    int* p = part + blockIdx.y * 512;
    int i = blockIdx.x * 256 + threadIdx.x;
    sh[threadIdx.x] = (i < NN) ? c[i] : 0;
    __syncthreads();
    for (int s = 128; s > 0; s >>= 1) {
        if (threadIdx.x < s) sh[threadIdx.x] += sh[threadIdx.x + s];
        __syncthreads();
    }
    if (threadIdx.x == 0) p[blockIdx.x] = sh[0];
}

__global__ void scan_partials_kernel(int* __restrict__ part, int nb) {
    __shared__ int sh[512];
    int* p = part + blockIdx.y * 512;
    int t = threadIdx.x;
    int v = (t < nb) ? p[t] : 0;
    sh[t] = v;
    __syncthreads();
    for (int o = 1; o < 512; o <<= 1) {
        int x = (t >= o) ? sh[t - o] : 0;
        __syncthreads();
        sh[t] += x;
        __syncthreads();
    }
    if (t < nb) p[t] = sh[t] - v;  // exclusive
}

__global__ void scan_final_kernel(const int* __restrict__ cnt, const int* __restrict__ part,
                                  int* __restrict__ off, int* __restrict__ pos) {
    __shared__ int sh[256];
    const int* c = cnt + blockIdx.y * NN;
    const int* p = part + blockIdx.y * 512;
    int* of = off + blockIdx.y * NN;
    int* ps = pos + blockIdx.y * NN;
    int t = threadIdx.x;
    int i = blockIdx.x * 256 + t;
    int v = (i < NN) ? c[i] : 0;
    sh[t] = v;
    __syncthreads();
    for (int o = 1; o < 256; o <<= 1) {
        int x = (t >= o) ? sh[t - o] : 0;
        __syncthreads();
        sh[t] += x;
        __syncthreads();
    }
    if (i < NN) {
        int e = sh[t] - v + p[blockIdx.x];
        of[i] = e;
        ps[i] = e;
    }
}

__global__ void build_csr_kernel(const int* __restrict__ e0, const int* __restrict__ e1,
                                 int E, int* __restrict__ pos,
                                 int* __restrict__ c0, int* __restrict__ c1) {
    int t = blockIdx.y;
    const int* edge = t ? e1 : e0;
    int* ps = pos + t * NN;
    int* csr = t ? c1 : c0;
    int e = blockIdx.x * blockDim.x + threadIdx.x;
    if (e < E) {
        int s = edge[e];
        int d = edge[E + e];
        int idx = atomicAdd(&ps[d], 1);
        csr[idx] = s;
    }
}

// ---------------- gather-mean aggregation (layer 0, C=128), fp16 in / fp16 out ----------------
__global__ void gather_mean_kernel(const __half* __restrict__ fA, const int* __restrict__ csrA, __half* __restrict__ oA,
                                   const __half* __restrict__ fB, const int* __restrict__ csrB, __half* __restrict__ oB,
                                   const int* __restrict__ off, const int* __restrict__ cnt) {
    constexpr int G = 32;
    const int t = blockIdx.y;
    const __half* feat = t ? fB : fA;
    const int* csr = t ? csrB : csrA;
    __half* out = t ? oB : oA;
    const int* of = off + t * NN;
    const int* cn = cnt + t * NN;

    int gid = (int)((blockIdx.x * (size_t)blockDim.x + threadIdx.x) / G);
    if (gid >= NN) return;
    const int c4 = (threadIdx.x & (G - 1)) * 4;
    const int beg = __ldg(&of[gid]);
    const int deg = __ldg(&cn[gid]);

    float4 a0 = make_float4(0.f, 0.f, 0.f, 0.f);
    float4 a1 = make_float4(0.f, 0.f, 0.f, 0.f);
    float4 a2 = make_float4(0.f, 0.f, 0.f, 0.f);
    float4 a3 = make_float4(0.f, 0.f, 0.f, 0.f);
    int e = 0;
    for (; e + 3 < deg; e += 4) {
        int s0 = __ldg(&csr[beg + e]);
        int s1 = __ldg(&csr[beg + e + 1]);
        int s2 = __ldg(&csr[beg + e + 2]);
        int s3 = __ldg(&csr[beg + e + 3]);
        const __half2* p0 = (const __half2*)(feat + (size_t)s0 * HD + c4);
        const __half2* p1 = (const __half2*)(feat + (size_t)s1 * HD + c4);
        const __half2* p2 = (const __half2*)(feat + (size_t)s2 * HD + c4);
        const __half2* p3 = (const __half2*)(feat + (size_t)s3 * HD + c4);
        float2 u0 = __half22float2(p0[0]), w0 = __half22float2(p0[1]);
        float2 u1 = __half22float2(p1[0]), w1 = __half22float2(p1[1]);
        float2 u2 = __half22float2(p2[0]), w2 = __half22float2(p2[1]);
        float2 u3 = __half22float2(p3[0]), w3 = __half22float2(p3[1]);
        a0.x += u0.x; a0.y += u0.y; a0.z += w0.x; a0.w += w0.y;
        a1.x += u1.x; a1.y += u1.y; a1.z += w1.x; a1.w += w1.y;
        a2.x += u2.x; a2.y += u2.y; a2.z += w2.x; a2.w += w2.y;
        a3.x += u3.x; a3.y += u3.y; a3.z += w3.x; a3.w += w3.y;
    }
    for (; e < deg; e++) {
        int s0 = __ldg(&csr[beg + e]);
        const __half2* p0 = (const __half2*)(feat + (size_t)s0 * HD + c4);
        float2 u0 = __half22float2(p0[0]), w0 = __half22float2(p0[1]);
        a0.x += u0.x; a0.y += u0.y; a0.z += w0.x; a0.w += w0.y;
    }
    const float sc = 1.0f / fmaxf((float)deg, 1.0f);
    uint2 r;
    r.x = pack_h2((a0.x + a1.x + a2.x + a3.x) * sc, (a0.y + a1.y + a2.y + a3.y) * sc);
    r.y = pack_h2((a0.z + a1.z + a2.z + a3.z) * sc, (a0.w + a1.w + a2.w + a3.w) * sc);
    *(uint2*)(out + (size_t)gid * HD + c4) = r;
}

// ---------------- fused layer-1 gather + final LN (fp16 proj/root inputs) ----------------
struct FSide { const __half* proj_src; const __half* root; const int* csr;
               const float* bias; const float* g; const float* b; float* out; };
__global__ void final_fused_kernel(FSide f0, FSide f1, const int* __restrict__ off, const int* __restrict__ cnt) {
    const int t = blockIdx.y;
    FSide s = t ? f1 : f0;
    const int* of = off + t * NN;
    const int* cn = cnt + t * NN;
    const int warp = threadIdx.x >> 5;
    const int lane = threadIdx.x & 31;
    const int row = blockIdx.x * 8 + warp;
    if (row >= NN) return;
    const int c = lane * 2;
    const int beg = __ldg(&of[row]);
    const int deg = __ldg(&cn[row]);

    float x0 = 0.f, y0 = 0.f, x1 = 0.f, y1 = 0.f;
    int e = 0;
    for (; e + 1 < deg; e += 2) {
        int s0 = __ldg(&s.csr[beg + e]);
        int s1 = __ldg(&s.csr[beg + e + 1]);
        float2 v0 = __half22float2(*(const __half2*)(s.proj_src + (size_t)s0 * OD + c));
        float2 v1 = __half22float2(*(const __half2*)(s.proj_src + (size_t)s1 * OD + c));
        x0 += v0.x; y0 += v0.y;
        x1 += v1.x; y1 += v1.y;
    }
    if (e < deg) {
        int s0 = __ldg(&s.csr[beg + e]);
        float2 v0 = __half22float2(*(const __half2*)(s.proj_src + (size_t)s0 * OD + c));
        x0 += v0.x; y0 += v0.y;
    }
    const float sc = 1.0f / fmaxf((float)deg, 1.0f);
    float2 rv = __half22float2(*(const __half2*)(s.root + (size_t)row * OD + c));
    float2 bv = __ldg((const float2*)(s.bias + c));
    float v0 = (x0 + x1) * sc + rv.x + bv.x;
    float v1 = (y0 + y1) * sc + rv.y + bv.y;

    float s1v = v0 + v1;
    float s2v = v0 * v0 + v1 * v1;
#pragma unroll
    for (int o = 16; o > 0; o >>= 1) {
        s1v += __shfl_xor_sync(0xFFFFFFFFu, s1v, o);
        s2v += __shfl_xor_sync(0xFFFFFFFFu, s2v, o);
    }
    float mean = s1v * (1.0f / 64.0f);
    float var = s2v * (1.0f / 64.0f) - mean * mean;
    float rstd = rsqrtf(var + 1e-5f);
    float2 gv = __ldg((const float2*)(s.g + c));
    float2 bb = __ldg((const float2*)(s.b + c));
    float2 o2;
    o2.x = (v0 - mean) * rstd * gv.x + bb.x;
    o2.y = (v1 - mean) * rstd * gv.y + bb.y;
    *(float2*)(s.out + (size_t)row * 64 + c) = o2;
}

// weight transpose + fp16 hi/lo split
struct WCon { const float* w; __half* h; __half* l; int K, N, Kpad; };
struct WCon10 { WCon s[10]; };
__global__ void wconv_kernel(WCon10 P) {
    WCon w = P.s[blockIdx.y];
    int idx = blockIdx.x * blockDim.x + threadIdx.x;
    if (idx >= w.N * w.Kpad) return;
    int n = idx / w.Kpad, k = idx % w.Kpad;
    float x = (k < w.K) ? w.w[(size_t)k * w.N + n] : 0.0f;
    __half h = __float2half(x);
    w.h[idx] = h;
    w.l[idx] = __float2half(x - __half2float(h));
}

// ---------------- HMMA fp16 GEMM, BN=128, 4x2 warp tiling, paired via gridDim.y ----------------
// 2-pass fp16: A single fp16 plane; B fp16 hi/lo (weights exact). C = ah*bh + ah*bl.
// AHALF: A segments are fp16 planes (A1h, A2h) via cp.async; else fp32-convert from A1.
// OUTHALF: result as fp16 plane stride 128. SPLIT: fp16, cols 0-63 -> outh, 64-127 -> outh2 (stride 64).
#define BN 128

struct GSide {
    const float* A1; const __half* A1h; const __half* A2h;
    const __half* W1h; const __half* W1l; int K1; int K1pad;
    const __half* W2h; const __half* W2l; int K2pad;
    const float* bias; const float* gamma; const float* beta;
    __half* outh; __half* outh2;
};

template <bool FUSE2, bool AHALF, bool SPLIT, bool DO_LN, bool DO_RELU>
__global__ __launch_bounds__(256, 2)
void mma_gemm(GSide s0, GSide s1, int M) {
    const GSide& S = blockIdx.y ? s1 : s0;

    extern __shared__ char smem[];
    const uint32_t sb = smem_u32(smem);
    const uint32_t aB = sb;                 // A: 128 x 64 fp16 = 16KB
    const uint32_t bBuf0 = sb + 16384;      // B: per buffer bHi(16KB)+bLo(16KB); 2 buffers

    const int tid = threadIdx.x;
    const int warp = tid >> 5;
    const int lane = tid & 31;
    const int wm = warp & 3;
    const int wn = warp >> 2;
    const int r0 = blockIdx.x * 128;

    float acc[2][8][4];
#pragma unroll
    for (int mt = 0; mt < 2; mt++)
#pragma unroll
        for (int nt = 0; nt < 8; nt++)
#pragma unroll
            for (int j = 0; j < 4; j++) acc[mt][nt][j] = 0.0f;

    // staging mapping
    const int ar = tid >> 1;
    const int acb = (tid & 1) * 32;
    const int bn = tid >> 1;
    const int bq = tid & 1;

    // compute-phase lane constants
    const uint32_t a_off0 = (uint32_t)(wm * 32 + (lane & 15)) * 128;
    const uint32_t a_off1 = a_off0 + 16 * 128;
    const uint32_t a_xm = (lane & 7) * 16;
    const uint32_t a_khalf = ((lane >> 4) & 1) * 16;
    const uint32_t b_rowbase = (uint32_t)(wn * 64 + (lane & 7) + ((lane >> 4) & 1) * 8) * 128;
    const uint32_t b_xm = (lane & 7) * 16;
    const uint32_t b_khalf = ((lane >> 3) & 1) * 16;

    const int nch1 = S.K1pad >> 6;
    const int nch = nch1 + (FUSE2 ? (S.K2pad >> 6) : 0);

    auto issueB = [&](int c, int buf) {
        const __half *Wh, *Wl;
        int k0, Kpad;
        if (!FUSE2 || c < nch1) { Wh = S.W1h; Wl = S.W1l; k0 = c * 64; Kpad = S.K1pad; }
        else                    { Wh = S.W2h; Wl = S.W2l; k0 = (c - nch1) * 64; Kpad = S.K2pad; }
        const uint32_t bH = bBuf0 + (uint32_t)buf * 32768;
        const uint32_t bL = bH + 16384;
#pragma unroll
        for (int i = 0; i < 4; i++) {
            const int ck = bq * 32 + i * 8;
            const size_t so = (size_t)bn * Kpad + k0 + ck;
            const uint32_t off = SWZ(bn * 128 + ck * 2);
            CPA16(bH + off, Wh + so);
            CPA16(bL + off, Wl + so);
        }
        CPA_COMMIT();
    };

    issueB(0, 0);

    for (int c = 0; c < nch; c++) {
        if (c) __syncthreads();

        // ---- stage A ----
        if (AHALF) {
            const __half* base;
            int k0;
            if (!FUSE2 || c < nch1) { base = S.A1h; k0 = c * 64; }
            else                    { base = S.A2h; k0 = (c - nch1) * 64; }
            const int grow = r0 + ar;
            const int srow = (grow < M) ? grow : 0;
            const __half* src = base + (size_t)srow * HD + k0 + acb;
#pragma unroll
            for (int i = 0; i < 4; i++) {
                const uint32_t off = SWZ(ar * 128 + (acb + i * 8) * 2);
                CPA16(aB + off, src + i * 8);
            }
            CPA_COMMIT();
        } else {
            const int k0 = c * 64;
            const int K = S.K1;
            const int grow = r0 + ar;
            const float* arow = S.A1 + (size_t)grow * K;
#pragma unroll
            for (int i = 0; i < 4; i++) {
                const int cc = acb + i * 8;
                float x[8];
#pragma unroll
                for (int j = 0; j < 8; j++) x[j] = 0.0f;
                if (grow < M && (k0 + cc) < K) {
                    float4 v0 = *(const float4*)(arow + k0 + cc);
                    float4 v1 = *(const float4*)(arow + k0 + cc + 4);
                    x[0] = v0.x; x[1] = v0.y; x[2] = v0.z; x[3] = v0.w;
                    x[4] = v1.x; x[5] = v1.y; x[6] = v1.z; x[7] = v1.w;
                }
                uint32_t h4[4];
#pragma unroll
                for (int j = 0; j < 4; j++) h4[j] = pack_h2(x[2 * j], x[2 * j + 1]);
                const uint32_t off = SWZ(ar * 128 + cc * 2);
                asm volatile("st.shared.v4.b32 [%0], {%1, %2, %3, %4};" :: "r"(aB + off), "r"(h4[0]), "r"(h4[1]), "r"(h4[2]), "r"(h4[3]) : "memory");
            }
        }

        // ---- prefetch next B, then wait ----
        if (c + 1 < nch) {
            issueB(c + 1, (c + 1) & 1);
            CPA_WAIT1();
        } else {
            CPA_WAIT0();
        }
        __syncthreads();

        // ---- compute: 2-pass fp16 (ah*bh + ah*bl) ----
        const uint32_t bHiC = bBuf0 + (uint32_t)(c & 1) * 32768;
        const uint32_t bLoC = bHiC + 16384;
#pragma unroll
        for (int ks = 0; ks < 4; ks++) {
            const uint32_t akb = ((uint32_t)(ks * 32) + a_khalf) ^ a_xm;
            uint32_t ah[2][4];
            ldm4(ah[0], aB + a_off0 + akb);
            ldm4(ah[1], aB + a_off1 + akb);
            const uint32_t bkb = ((uint32_t)(ks * 32) + b_khalf) ^ b_xm;
#pragma unroll
            for (int j = 0; j < 4; j++) {
                uint32_t bh[4], bl[4];
                const uint32_t boff = b_rowbase + (uint32_t)j * 2048;
                ldm4(bh, bHiC + boff + bkb);
                ldm4(bl, bLoC + boff + bkb);
#pragma unroll
                for (int mt = 0; mt < 2; mt++) {
                    mma_fp16(acc[mt][2 * j],     ah[mt], bh[0], bh[1]);
                    mma_fp16(acc[mt][2 * j],     ah[mt], bl[0], bl[1]);
                    mma_fp16(acc[mt][2 * j + 1], ah[mt], bh[2], bh[3]);
                    mma_fp16(acc[mt][2 * j + 1], ah[mt], bl[2], bl[3]);
                }
            }
        }
    }

    // ---- epilogue ----
    const int rq = lane >> 2;
    const int cq = (lane & 3) * 2;

    if (S.bias) {
#pragma unroll
        for (int nt = 0; nt < 8; nt++) {
            float2 bv = __ldg((const float2*)(S.bias + wn * 64 + nt * 8 + cq));
#pragma unroll
            for (int mt = 0; mt < 2; mt++) {
                acc[mt][nt][0] += bv.x; acc[mt][nt][1] += bv.y;
                acc[mt][nt][2] += bv.x; acc[mt][nt][3] += bv.y;
            }
        }
    }
    if (DO_LN) {
        float s1[2][2], s2[2][2];
#pragma unroll
        for (int mt = 0; mt < 2; mt++)
#pragma unroll
            for (int h = 0; h < 2; h++) { s1[mt][h] = 0.f; s2[mt][h] = 0.f; }
#pragma unroll
        for (int mt = 0; mt < 2; mt++)
#pragma unroll
            for (int nt = 0; nt < 8; nt++) {
                s1[mt][0] += acc[mt][nt][0] + acc[mt][nt][1];
                s2[mt][0] += acc[mt][nt][0] * acc[mt][nt][0] + acc[mt][nt][1] * acc[mt][nt][1];
                s1[mt][1] += acc[mt][nt][2] + acc[mt][nt][3];
                s2[mt][1] += acc[mt][nt][2] * acc[mt][nt][2] + acc[mt][nt][3] * acc[mt][nt][3];
            }
#pragma unroll
        for (int o = 1; o < 4; o <<= 1) {
#pragma unroll
            for (int mt = 0; mt < 2; mt++)
#pragma unroll
                for (int h = 0; h < 2; h++) {
                    s1[mt][h] += __shfl_xor_sync(0xFFFFFFFFu, s1[mt][h], o);
                    s2[mt][h] += __shfl_xor_sync(0xFFFFFFFFu, s2[mt][h], o);
                }
        }
        float* sc = (float*)smem;
        __syncthreads();
        if ((lane & 3) == 0) {
#pragma unroll
            for (int mt = 0; mt < 2; mt++)
#pragma unroll
                for (int h = 0; h < 2; h++) {
                    int rl = wm * 32 + mt * 16 + h * 8 + rq;
                    sc[wn * 128 + rl] = s1[mt][h];
                    sc[256 + wn * 128 + rl] = s2[mt][h];
                }
        }
        __syncthreads();
#pragma unroll
        for (int mt = 0; mt < 2; mt++)
#pragma unroll
            for (int h = 0; h < 2; h++) {
                int rl = wm * 32 + mt * 16 + h * 8 + rq;
                float S1 = sc[rl] + sc[128 + rl];
                float S2 = sc[256 + rl] + sc[384 + rl];
                float mean = S1 * (1.0f / 128.0f);
                float var = S2 * (1.0f / 128.0f) - mean * mean;
                float rstd = rsqrtf(var + 1e-5f);
                s1[mt][h] = mean;
                s2[mt][h] = rstd;
            }
#pragma unroll
        for (int nt = 0; nt < 8; nt++) {
            float2 g = __ldg((const float2*)(S.gamma + wn * 64 + nt * 8 + cq));
            float2 b = __ldg((const float2*)(S.beta + wn * 64 + nt * 8 + cq));
#pragma unroll
            for (int mt = 0; mt < 2; mt++) {
                acc[mt][nt][0] = (acc[mt][nt][0] - s1[mt][0]) * s2[mt][0] * g.x + b.x;
                acc[mt][nt][1] = (acc[mt][nt][1] - s1[mt][0]) * s2[mt][0] * g.y + b.y;
                acc[mt][nt][2] = (acc[mt][nt][2] - s1[mt][1]) * s2[mt][1] * g.x + b.x;
                acc[mt][nt][3] = (acc[mt][nt][3] - s1[mt][1]) * s2[mt][1] * g.y + b.y;
            }
        }
    }
    if (DO_RELU) {
#pragma unroll
        for (int mt = 0; mt < 2; mt++)
#pragma unroll
            for (int nt = 0; nt < 8; nt++)
#pragma unroll
                for (int j = 0; j < 4; j++) acc[mt][nt][j] = fmaxf(acc[mt][nt][j], 0.0f);
    }
    if (SPLIT) {
        __half* dst = wn ? S.outh2 : S.outh;
#pragma unroll
        for (int mt = 0; mt < 2; mt++)
#pragma unroll
            for (int h = 0; h < 2; h++) {
                int row = r0 + wm * 32 + mt * 16 + h * 8 + rq;
                if (row < M) {
#pragma unroll
                    for (int nt = 0; nt < 8; nt++)
                        *(uint32_t*)(dst + (size_t)row * 64 + nt * 8 + cq) =
                            pack_h2(acc[mt][nt][2 * h], acc[mt][nt][2 * h + 1]);
                }
            }
    } else {
#pragma unroll
        for (int mt = 0; mt < 2; mt++)
#pragma unroll
            for (int h = 0; h < 2; h++) {
                int row = r0 + wm * 32 + mt * 16 + h * 8 + rq;
                if (row < M) {
#pragma unroll
                    for (int nt = 0; nt < 8; nt++)
                        *(uint32_t*)(S.outh + (size_t)row * BN + wn * 64 + nt * 8 + cq) =
                            pack_h2(acc[mt][nt][2 * h], acc[mt][nt][2 * h + 1]);
                }
            }
    }
}

// ---------------- host launcher ----------------
extern "C" void kernel_launch(void* const* d_in, const int* in_sizes, int n_in,
                              void* d_out, int out_size) {
    const float* x_user = (const float*)d_in[0];
    const float* x_item = (const float*)d_in[1];
    const int* edge_ui = (const int*)d_in[2];
    const int* edge_iu = (const int*)d_in[3];
    const float* Wp_u = (const float*)d_in[4];
    const float* bp_u = (const float*)d_in[5];
    const float* Wp_i = (const float*)d_in[6];
    const float* bp_i = (const float*)d_in[7];
    const float* Wl0_ui = (const float*)d_in[8];
    const float* bl0_ui = (const float*)d_in[9];
    const float* Wr0_ui = (const float*)d_in[10];
    const float* Wl0_iu = (const float*)d_in[11];
    const float* bl0_iu = (const float*)d_in[12];
    const float* Wr0_iu = (const float*)d_in[13];
    const float* g0_u = (const float*)d_in[14];
    const float* b0_u = (const float*)d_in[15];
    const float* g0_i = (const float*)d_in[16];
    const float* b0_i = (const float*)d_in[17];
    const float* Wl1_ui = (const float*)d_in[18];
    const float* bl1_ui = (const float*)d_in[19];
    const float* Wr1_ui = (const float*)d_in[20];
    const float* Wl1_iu = (const float*)d_in[21];
    const float* bl1_iu = (const float*)d_in[22];
    const float* Wr1_iu = (const float*)d_in[23];
    const float* g1_u = (const float*)d_in[24];
    const float* b1_u = (const float*)d_in[25];
    const float* g1_i = (const float*)d_in[26];
    const float* b1_i = (const float*)d_in[27];

    const int E = in_sizes[2] / 2;

    __half *hu, *hi, *agg_u, *agg_i, *hu1, *hi1, *proj_u, *root_u, *proj_i, *root_i;
    int *cnt, *off, *pos, *csr_iu, *csr_ui, *part;
    cudaGetSymbolAddress((void**)&hu, g_hu);
    cudaGetSymbolAddress((void**)&hi, g_hi);
    cudaGetSymbolAddress((void**)&agg_u, g_agg_u);
    cudaGetSymbolAddress((void**)&agg_i, g_agg_i);
    cudaGetSymbolAddress((void**)&hu1, g_hu1);
    cudaGetSymbolAddress((void**)&hi1, g_hi1);
    cudaGetSymbolAddress((void**)&proj_u, g_proj_u);
    cudaGetSymbolAddress((void**)&root_u, g_root_u);
    cudaGetSymbolAddress((void**)&proj_i, g_proj_i);
    cudaGetSymbolAddress((void**)&root_i, g_root_i);
    cudaGetSymbolAddress((void**)&cnt, g_cnt);
    cudaGetSymbolAddress((void**)&off, g_off);
    cudaGetSymbolAddress((void**)&pos, g_pos);
    cudaGetSymbolAddress((void**)&csr_iu, g_csr_iu);
    cudaGetSymbolAddress((void**)&csr_ui, g_csr_ui);
    cudaGetSymbolAddress((void**)&part, g_part);

    __half *wpu_h, *wpu_l, *wpi_h, *wpi_l;
    __half *wl0ui_h, *wl0ui_l, *wr0ui_h, *wr0ui_l, *wl0iu_h, *wl0iu_l, *wr0iu_h, *wr0iu_l;
    __half *w1u_h, *w1u_l, *w1i_h, *w1i_l;
    cudaGetSymbolAddress((void**)&wpu_h, g_wpu_h);   cudaGetSymbolAddress((void**)&wpu_l, g_wpu_l);
    cudaGetSymbolAddress((void**)&wpi_h, g_wpi_h);   cudaGetSymbolAddress((void**)&wpi_l, g_wpi_l);
    cudaGetSymbolAddress((void**)&wl0ui_h, g_wl0ui_h); cudaGetSymbolAddress((void**)&wl0ui_l, g_wl0ui_l);
    cudaGetSymbolAddress((void**)&wr0ui_h, g_wr0ui_h); cudaGetSymbolAddress((void**)&wr0ui_l, g_wr0ui_l);
    cudaGetSymbolAddress((void**)&wl0iu_h, g_wl0iu_h); cudaGetSymbolAddress((void**)&wl0iu_l, g_wl0iu_l);
    cudaGetSymbolAddress((void**)&wr0iu_h, g_wr0iu_h); cudaGetSymbolAddress((void**)&wr0iu_l, g_wr0iu_l);
    cudaGetSymbolAddress((void**)&w1u_h, g_w1u_h);   cudaGetSymbolAddress((void**)&w1u_l, g_w1u_l);
    cudaGetSymbolAddress((void**)&w1i_h, g_w1i_h);   cudaGetSymbolAddress((void**)&w1i_l, g_w1i_l);

    float* out_u = (float*)d_out;
    float* out_i = (float*)d_out + (size_t)NN * OD;

    const int SM = 16384 + 2 * 32768;   // A 16KB + B 2x32KB = 80KB
    cudaFuncSetAttribute(mma_gemm<false, false, false, false, true>, cudaFuncAttributeMaxDynamicSharedMemorySize, SM);
    cudaFuncSetAttribute(mma_gemm<true, true, false, true, true>, cudaFuncAttributeMaxDynamicSharedMemorySize, SM);
    cudaFuncSetAttribute(mma_gemm<false, true, true, false, false>, cudaFuncAttributeMaxDynamicSharedMemorySize, SM);

    const int GM = (NN + 127) / 128;

    // fork a side stream for the CSR chain (independent of weights/proj)
    cudaStream_t sB;
    cudaEvent_t eFork, eJoin;
    cudaStreamCreateWithFlags(&sB, cudaStreamNonBlocking);
    cudaEventCreateWithFlags(&eFork, cudaEventDisableTiming);
    cudaEventCreateWithFlags(&eJoin, cudaEventDisableTiming);

    cudaEventRecord(eFork, 0);
    cudaStreamWaitEvent(sB, eFork, 0);

    // side stream: degree + CSR build
    {
        dim3 ge((E + 255) / 256, 2);
        zero_cnt_kernel<<<(2 * NN + 255) / 256, 256, 0, sB>>>(cnt);
        count_kernel<<<ge, 256, 0, sB>>>(edge_iu + E, edge_ui + E, E, cnt);
        scan_part_kernel<<<dim3(NBLK, 2), 256, 0, sB>>>(cnt, part);
        scan_partials_kernel<<<dim3(1, 2), 512, 0, sB>>>(part, NBLK);
        scan_final_kernel<<<dim3(NBLK, 2), 256, 0, sB>>>(cnt, part, off, pos);
        build_csr_kernel<<<ge, 256, 0, sB>>>(edge_iu, edge_ui, E, pos, csr_iu, csr_ui);
        cudaEventRecord(eJoin, sB);
    }

    // main stream: weight convert + projection GEMM pair
    {
        WCon10 P;
        P.s[0] = { Wp_u,   wpu_h,   wpu_l,   FU, HD, 128 };
        P.s[1] = { Wp_i,   wpi_h,   wpi_l,   FI, HD, 192 };
        P.s[2] = { Wl0_ui, wl0ui_h, wl0ui_l, HD, HD, 128 };
        P.s[3] = { Wr0_ui, wr0ui_h, wr0ui_l, HD, HD, 128 };
        P.s[4] = { Wl0_iu, wl0iu_h, wl0iu_l, HD, HD, 128 };
        P.s[5] = { Wr0_iu, wr0iu_h, wr0iu_l, HD, HD, 128 };
        P.s[6] = { Wl1_ui, w1u_h,             w1u_l,             HD, OD, 128 };
        P.s[7] = { Wr1_iu, w1u_h + 64 * 128,  w1u_l + 64 * 128,  HD, OD, 128 };
        P.s[8] = { Wl1_iu, w1i_h,             w1i_l,             HD, OD, 128 };
        P.s[9] = { Wr1_ui, w1i_h + 64 * 128,  w1i_l + 64 * 128,  HD, OD, 128 };
        dim3 g((192 * 128 + 255) / 256, 10);
        wconv_kernel<<<g, 256>>>(P);
    }
    {
        GSide su = { x_user, nullptr, nullptr, wpu_h, wpu_l, FU, 128, nullptr, nullptr, 0,
                     bp_u, nullptr, nullptr, hu, nullptr };
        GSide si = { x_item, nullptr, nullptr, wpi_h, wpi_l, FI, 192, nullptr, nullptr, 0,
                     bp_i, nullptr, nullptr, hi, nullptr };
        mma_gemm<false, false, false, false, true><<<dim3(GM, 2), 256, SM>>>(su, si, NN);
    }

    // join: gather needs CSR + proj outputs
    cudaStreamWaitEvent(0, eJoin, 0);

    // layer 0 aggregation (fp16 in/out). t=0: agg_u <- hi via csr_iu; t=1: agg_i <- hu via csr_ui
    {
        const long tot = (long)NN * 32;
        dim3 gg((unsigned)((tot + 255) / 256), 2);
        gather_mean_kernel<<<gg, 256>>>(hi, csr_iu, agg_u, hu, csr_ui, agg_i, off, cnt);
    }

    // layer 0 fused dual-GEMM + bias + LN + ReLU -> fp16 h1 planes (A1=agg fp16, A2=root fp16)
    {
        GSide si = { nullptr, agg_i, hi, wl0ui_h, wl0ui_l, HD, 128, wr0ui_h, wr0ui_l, 128,
                     bl0_ui, g0_i, b0_i, hi1, nullptr };
        GSide su = { nullptr, agg_u, hu, wl0iu_h, wl0iu_l, HD, 128, wr0iu_h, wr0iu_l, 128,
                     bl0_iu, g0_u, b0_u, hu1, nullptr };
        mma_gemm<true, true, false, true, true><<<dim3(GM, 2), 256, SM>>>(si, su, NN);
    }

    // layer 1 combined GEMM pair: [proj|root] = h1 @ [Wl1 | Wr1], fp16 A plane, split fp16 outputs
    {
        GSide su = { nullptr, hu1, nullptr, w1u_h, w1u_l, HD, 128, nullptr, nullptr, 0,
                     nullptr, nullptr, nullptr, proj_u, root_u };
        GSide si = { nullptr, hi1, nullptr, w1i_h, w1i_l, HD, 128, nullptr, nullptr, 0,
                     nullptr, nullptr, nullptr, proj_i, root_i };
        mma_gemm<false, true, true, false, false><<<dim3(GM, 2), 256, SM>>>(su, si, NN);
    }

    // fused layer-1 gather + final LN (fp16 proj/root)
    {
        FSide fu = { proj_i, root_u, csr_iu, bl1_iu, g1_u, b1_u, out_u };
        FSide fi = { proj_u, root_i, csr_ui, bl1_ui, g1_i, b1_i, out_i };
        dim3 gf((NN + 7) / 8, 2);
        final_fused_kernel<<<gf, 256>>>(fu, fi, off, cnt);
    }

    (void)n_in; (void)out_size; (void)in_sizes;
}

// round 13
// speedup vs baseline: 1.7609x; 1.1610x over previous
#include <cuda_runtime.h>
#include <cuda_fp16.h>
#include <cstdint>

// ---------------- problem constants ----------------
#define NU 100000
#define NI 100000
#define NN 100000   // NU == NI
#define FU 96
#define FI 160
#define HD 128
#define OD 64
#define EMAX 600000
#define NBLK 391   // ceil(100000/256)

// ---------------- scratch (device globals) ----------------
__device__ __half g_hu   [NN * HD];   // fp16 proj planes (gather input + layer0 root)
__device__ __half g_hi   [NN * HD];
__device__ __half g_agg_u[NN * HD];   // fp16 agg planes (gather output = layer0 A)
__device__ __half g_agg_i[NN * HD];
__device__ __half g_hu1  [NN * HD];   // fp16 h1 planes (layer0 out = layer1 A)
__device__ __half g_hi1  [NN * HD];
__device__ __half g_proj_u[NN * OD];  // fp16 layer-1 outputs
__device__ __half g_root_u[NN * OD];
__device__ __half g_proj_i[NN * OD];
__device__ __half g_root_i[NN * OD];
__device__ int    g_cnt [2 * NN];
__device__ int    g_off [2 * NN];
__device__ int    g_pos [2 * NN];
__device__ int    g_csr_iu[EMAX];
__device__ int    g_csr_ui[EMAX];
__device__ int    g_part[2 * 512];

// transposed fp16 weights: layout [N rows, Kpad cols], zero padded
__device__ __half g_wpu[128 * 128];
__device__ __half g_wpi[128 * 192];
__device__ __half g_wl0ui[128 * 128];
__device__ __half g_wr0ui[128 * 128];
__device__ __half g_wl0iu[128 * 128];
__device__ __half g_wr0iu[128 * 128];
__device__ __half g_w1u[128 * 128];   // [Wl1_ui | Wr1_iu]
__device__ __half g_w1i[128 * 128];   // [Wl1_iu | Wr1_ui]

// ---------------- helpers ----------------
__device__ __forceinline__ uint32_t smem_u32(const void* p) {
    uint32_t a;
    asm("{ .reg .u64 t; cvta.to.shared.u64 t, %1; cvt.u32.u64 %0, t; }" : "=r"(a) : "l"(p));
    return a;
}
#define SWZ(x) ((x) ^ (((x) >> 3) & 0x70))

#define CPA16(dst, src) \
    asm volatile("cp.async.ca.shared.global [%0], [%1], 16;" :: "r"(dst), "l"(src) : "memory")
#define CPA_COMMIT() asm volatile("cp.async.commit_group;" ::: "memory")
#define CPA_WAIT1()  asm volatile("cp.async.wait_group 1;" ::: "memory")
#define CPA_WAIT0()  asm volatile("cp.async.wait_group 0;" ::: "memory")

__device__ __forceinline__ void ldm4(uint32_t* r, uint32_t addr) {
    asm volatile("ldmatrix.sync.aligned.m8n8.x4.shared.b16 {%0,%1,%2,%3}, [%4];"
        : "=r"(r[0]), "=r"(r[1]), "=r"(r[2]), "=r"(r[3]) : "r"(addr));
}
__device__ __forceinline__ void mma_fp16(float* c, const uint32_t* a, uint32_t b0, uint32_t b1) {
    asm volatile("mma.sync.aligned.m16n8k16.row.col.f32.f16.f16.f32 "
        "{%0,%1,%2,%3}, {%4,%5,%6,%7}, {%8,%9}, {%0,%1,%2,%3};"
        : "+f"(c[0]), "+f"(c[1]), "+f"(c[2]), "+f"(c[3])
        : "r"(a[0]), "r"(a[1]), "r"(a[2]), "r"(a[3]), "r"(b0), "r"(b1));
}
__device__ __forceinline__ uint32_t pack_h2(float x0, float x1) {
    __half2 h = __floats2half2_rn(x0, x1);
    return *reinterpret_cast<uint32_t*>(&h);
}

// ---------------- CSR build chain ----------------
__global__ void zero_cnt_kernel(int* __restrict__ cnt) {
    int i = blockIdx.x * blockDim.x + threadIdx.x;
    if (i < 2 * NN) cnt[i] = 0;
}

__global__ void count_kernel(const int* __restrict__ dst0, const int* __restrict__ dst1,
                             int E, int* __restrict__ cnt) {
    int t = blockIdx.y;
    const int* dst = t ? dst1 : dst0;
    int* c = cnt + t * NN;
    int e = blockIdx.x * blockDim.x + threadIdx.x;
    if (e < E) atomicAdd(&c[dst[e]], 1);
}

__global__ void scan_part_kernel(const int* __restrict__ cnt, int* __restrict__ part) {
    __shared__ int sh[256];
    const int* c = cnt + blockIdx.y * NN;
    int* p = part + blockIdx.y * 512;
    int i = blockIdx.x * 256 + threadIdx.x;
    sh[threadIdx.x] = (i < NN) ? c[i] : 0;
    __syncthreads();
    for (int s = 128; s > 0; s >>= 1) {
        if (threadIdx.x < s) sh[threadIdx.x] += sh[threadIdx.x + s];
        __syncthreads();
    }
    if (threadIdx.x == 0) p[blockIdx.x] = sh[0];
}

__global__ void scan_partials_kernel(int* __restrict__ part, int nb) {
    __shared__ int sh[512];
    int* p = part + blockIdx.y * 512;
    int t = threadIdx.x;
    int v = (t < nb) ? p[t] : 0;
    sh[t] = v;
    __syncthreads();
    for (int o = 1; o < 512; o <<= 1) {
        int x = (t >= o) ? sh[t - o] : 0;
        __syncthreads();
        sh[t] += x;
        __syncthreads();
    }
    if (t < nb) p[t] = sh[t] - v;  // exclusive
}

__global__ void scan_final_kernel(const int* __restrict__ cnt, const int* __restrict__ part,
                                  int* __restrict__ off, int* __restrict__ pos) {
    __shared__ int sh[256];
    const int* c = cnt + blockIdx.y * NN;
    const int* p = part + blockIdx.y * 512;
    int* of = off + blockIdx.y * NN;
    int* ps = pos + blockIdx.y * NN;
    int t = threadIdx.x;
    int i = blockIdx.x * 256 + t;
    int v = (i < NN) ? c[i] : 0;
    sh[t] = v;
    __syncthreads();
    for (int o = 1; o < 256; o <<= 1) {
        int x = (t >= o) ? sh[t - o] : 0;
        __syncthreads();
        sh[t] += x;
        __syncthreads();
    }
    if (i < NN) {
        int e = sh[t] - v + p[blockIdx.x];
        of[i] = e;
        ps[i] = e;
    }
}

__global__ void build_csr_kernel(const int* __restrict__ e0, const int* __restrict__ e1,
                                 int E, int* __restrict__ pos,
                                 int* __restrict__ c0, int* __restrict__ c1) {
    int t = blockIdx.y;
    const int* edge = t ? e1 : e0;
    int* ps = pos + t * NN;
    int* csr = t ? c1 : c0;
    int e = blockIdx.x * blockDim.x + threadIdx.x;
    if (e < E) {
        int s = edge[e];
        int d = edge[E + e];
        int idx = atomicAdd(&ps[d], 1);
        csr[idx] = s;
    }
}

// ---------------- gather-mean aggregation (layer 0, C=128), fp16 in / fp16 out ----------------
__global__ void gather_mean_kernel(const __half* __restrict__ fA, const int* __restrict__ csrA, __half* __restrict__ oA,
                                   const __half* __restrict__ fB, const int* __restrict__ csrB, __half* __restrict__ oB,
                                   const int* __restrict__ off, const int* __restrict__ cnt) {
    constexpr int G = 32;
    const int t = blockIdx.y;
    const __half* feat = t ? fB : fA;
    const int* csr = t ? csrB : csrA;
    __half* out = t ? oB : oA;
    const int* of = off + t * NN;
    const int* cn = cnt + t * NN;

    int gid = (int)((blockIdx.x * (size_t)blockDim.x + threadIdx.x) / G);
    if (gid >= NN) return;
    const int c4 = (threadIdx.x & (G - 1)) * 4;
    const int beg = __ldg(&of[gid]);
    const int deg = __ldg(&cn[gid]);

    float4 a0 = make_float4(0.f, 0.f, 0.f, 0.f);
    float4 a1 = make_float4(0.f, 0.f, 0.f, 0.f);
    float4 a2 = make_float4(0.f, 0.f, 0.f, 0.f);
    float4 a3 = make_float4(0.f, 0.f, 0.f, 0.f);
    int e = 0;
    for (; e + 3 < deg; e += 4) {
        int s0 = __ldg(&csr[beg + e]);
        int s1 = __ldg(&csr[beg + e + 1]);
        int s2 = __ldg(&csr[beg + e + 2]);
        int s3 = __ldg(&csr[beg + e + 3]);
        const __half2* p0 = (const __half2*)(feat + (size_t)s0 * HD + c4);
        const __half2* p1 = (const __half2*)(feat + (size_t)s1 * HD + c4);
        const __half2* p2 = (const __half2*)(feat + (size_t)s2 * HD + c4);
        const __half2* p3 = (const __half2*)(feat + (size_t)s3 * HD + c4);
        float2 u0 = __half22float2(p0[0]), w0 = __half22float2(p0[1]);
        float2 u1 = __half22float2(p1[0]), w1 = __half22float2(p1[1]);
        float2 u2 = __half22float2(p2[0]), w2 = __half22float2(p2[1]);
        float2 u3 = __half22float2(p3[0]), w3 = __half22float2(p3[1]);
        a0.x += u0.x; a0.y += u0.y; a0.z += w0.x; a0.w += w0.y;
        a1.x += u1.x; a1.y += u1.y; a1.z += w1.x; a1.w += w1.y;
        a2.x += u2.x; a2.y += u2.y; a2.z += w2.x; a2.w += w2.y;
        a3.x += u3.x; a3.y += u3.y; a3.z += w3.x; a3.w += w3.y;
    }
    for (; e < deg; e++) {
        int s0 = __ldg(&csr[beg + e]);
        const __half2* p0 = (const __half2*)(feat + (size_t)s0 * HD + c4);
        float2 u0 = __half22float2(p0[0]), w0 = __half22float2(p0[1]);
        a0.x += u0.x; a0.y += u0.y; a0.z += w0.x; a0.w += w0.y;
    }
    const float sc = 1.0f / fmaxf((float)deg, 1.0f);
    uint2 r;
    r.x = pack_h2((a0.x + a1.x + a2.x + a3.x) * sc, (a0.y + a1.y + a2.y + a3.y) * sc);
    r.y = pack_h2((a0.z + a1.z + a2.z + a3.z) * sc, (a0.w + a1.w + a2.w + a3.w) * sc);
    *(uint2*)(out + (size_t)gid * HD + c4) = r;
}

// ---------------- fused layer-1 gather + final LN (fp16 proj/root inputs) ----------------
struct FSide { const __half* proj_src; const __half* root; const int* csr;
               const float* bias; const float* g; const float* b; float* out; };
__global__ void final_fused_kernel(FSide f0, FSide f1, const int* __restrict__ off, const int* __restrict__ cnt) {
    const int t = blockIdx.y;
    FSide s = t ? f1 : f0;
    const int* of = off + t * NN;
    const int* cn = cnt + t * NN;
    const int warp = threadIdx.x >> 5;
    const int lane = threadIdx.x & 31;
    const int row = blockIdx.x * 8 + warp;
    if (row >= NN) return;
    const int c = lane * 2;
    const int beg = __ldg(&of[row]);
    const int deg = __ldg(&cn[row]);

    float x0 = 0.f, y0 = 0.f, x1 = 0.f, y1 = 0.f;
    int e = 0;
    for (; e + 1 < deg; e += 2) {
        int s0 = __ldg(&s.csr[beg + e]);
        int s1 = __ldg(&s.csr[beg + e + 1]);
        float2 v0 = __half22float2(*(const __half2*)(s.proj_src + (size_t)s0 * OD + c));
        float2 v1 = __half22float2(*(const __half2*)(s.proj_src + (size_t)s1 * OD + c));
        x0 += v0.x; y0 += v0.y;
        x1 += v1.x; y1 += v1.y;
    }
    if (e < deg) {
        int s0 = __ldg(&s.csr[beg + e]);
        float2 v0 = __half22float2(*(const __half2*)(s.proj_src + (size_t)s0 * OD + c));
        x0 += v0.x; y0 += v0.y;
    }
    const float sc = 1.0f / fmaxf((float)deg, 1.0f);
    float2 rv = __half22float2(*(const __half2*)(s.root + (size_t)row * OD + c));
    float2 bv = __ldg((const float2*)(s.bias + c));
    float v0 = (x0 + x1) * sc + rv.x + bv.x;
    float v1 = (y0 + y1) * sc + rv.y + bv.y;

    float s1v = v0 + v1;
    float s2v = v0 * v0 + v1 * v1;
#pragma unroll
    for (int o = 16; o > 0; o >>= 1) {
        s1v += __shfl_xor_sync(0xFFFFFFFFu, s1v, o);
        s2v += __shfl_xor_sync(0xFFFFFFFFu, s2v, o);
    }
    float mean = s1v * (1.0f / 64.0f);
    float var = s2v * (1.0f / 64.0f) - mean * mean;
    float rstd = rsqrtf(var + 1e-5f);
    float2 gv = __ldg((const float2*)(s.g + c));
    float2 bb = __ldg((const float2*)(s.b + c));
    float2 o2;
    o2.x = (v0 - mean) * rstd * gv.x + bb.x;
    o2.y = (v1 - mean) * rstd * gv.y + bb.y;
    *(float2*)(s.out + (size_t)row * 64 + c) = o2;
}

// weight transpose to fp16: W [K,N] fp32 -> Wt [N,Kpad] fp16, zero pad
struct WCon { const float* w; __half* h; int K, N, Kpad; };
struct WCon10 { WCon s[10]; };
__global__ void wconv_kernel(WCon10 P) {
    WCon w = P.s[blockIdx.y];
    int idx = blockIdx.x * blockDim.x + threadIdx.x;
    if (idx >= w.N * w.Kpad) return;
    int n = idx / w.Kpad, k = idx % w.Kpad;
    float x = (k < w.K) ? w.w[(size_t)k * w.N + n] : 0.0f;
    w.h[idx] = __float2half(x);
}

// ---------------- HMMA fp16 GEMM, BN=128, 4x2 warp tiling, paired via gridDim.y ----------------
// 1-pass fp16: A and B single fp16 planes. B double-buffered via cp.async.
// AHALF: A segments are fp16 planes via cp.async; else fp32-convert from A1.
// SPLIT: fp16 outputs, cols 0-63 -> outh, 64-127 -> outh2 (stride 64); else fp16 plane stride 128.
#define BN 128

struct GSide {
    const float* A1; const __half* A1h; const __half* A2h;
    const __half* W1; int K1; int K1pad;
    const __half* W2; int K2pad;
    const float* bias; const float* gamma; const float* beta;
    __half* outh; __half* outh2;
};

template <bool FUSE2, bool AHALF, bool SPLIT, bool DO_LN, bool DO_RELU>
__global__ __launch_bounds__(256, 2)
void mma_gemm(GSide s0, GSide s1, int M) {
    const GSide& S = blockIdx.y ? s1 : s0;

    extern __shared__ char smem[];
    const uint32_t sb = smem_u32(smem);
    const uint32_t aB = sb;                 // A: 128 x 64 fp16 = 16KB
    const uint32_t bBuf0 = sb + 16384;      // B: 16KB per buffer; 2 buffers

    const int tid = threadIdx.x;
    const int warp = tid >> 5;
    const int lane = tid & 31;
    const int wm = warp & 3;
    const int wn = warp >> 2;
    const int r0 = blockIdx.x * 128;

    float acc[2][8][4];
#pragma unroll
    for (int mt = 0; mt < 2; mt++)
#pragma unroll
        for (int nt = 0; nt < 8; nt++)
#pragma unroll
            for (int j = 0; j < 4; j++) acc[mt][nt][j] = 0.0f;

    // staging mapping
    const int ar = tid >> 1;
    const int acb = (tid & 1) * 32;
    const int bn = tid >> 1;
    const int bq = tid & 1;

    // compute-phase lane constants
    const uint32_t a_off0 = (uint32_t)(wm * 32 + (lane & 15)) * 128;
    const uint32_t a_off1 = a_off0 + 16 * 128;
    const uint32_t a_xm = (lane & 7) * 16;
    const uint32_t a_khalf = ((lane >> 4) & 1) * 16;
    const uint32_t b_rowbase = (uint32_t)(wn * 64 + (lane & 7) + ((lane >> 4) & 1) * 8) * 128;
    const uint32_t b_xm = (lane & 7) * 16;
    const uint32_t b_khalf = ((lane >> 3) & 1) * 16;

    const int nch1 = S.K1pad >> 6;
    const int nch = nch1 + (FUSE2 ? (S.K2pad >> 6) : 0);

    auto issueB = [&](int c, int buf) {
        const __half* W;
        int k0, Kpad;
        if (!FUSE2 || c < nch1) { W = S.W1; k0 = c * 64; Kpad = S.K1pad; }
        else                    { W = S.W2; k0 = (c - nch1) * 64; Kpad = S.K2pad; }
        const uint32_t bB = bBuf0 + (uint32_t)buf * 16384;
#pragma unroll
        for (int i = 0; i < 4; i++) {
            const int ck = bq * 32 + i * 8;
            const size_t so = (size_t)bn * Kpad + k0 + ck;
            const uint32_t off = SWZ(bn * 128 + ck * 2);
            CPA16(bB + off, W + so);
        }
        CPA_COMMIT();
    };

    issueB(0, 0);

    for (int c = 0; c < nch; c++) {
        if (c) __syncthreads();

        // ---- stage A ----
        if (AHALF) {
            const __half* base;
            int k0;
            if (!FUSE2 || c < nch1) { base = S.A1h; k0 = c * 64; }
            else                    { base = S.A2h; k0 = (c - nch1) * 64; }
            const int grow = r0 + ar;
            const int srow = (grow < M) ? grow : 0;
            const __half* src = base + (size_t)srow * HD + k0 + acb;
#pragma unroll
            for (int i = 0; i < 4; i++) {
                const uint32_t off = SWZ(ar * 128 + (acb + i * 8) * 2);
                CPA16(aB + off, src + i * 8);
            }
            CPA_COMMIT();
        } else {
            const int k0 = c * 64;
            const int K = S.K1;
            const int grow = r0 + ar;
            const float* arow = S.A1 + (size_t)grow * K;
#pragma unroll
            for (int i = 0; i < 4; i++) {
                const int cc = acb + i * 8;
                float x[8];
#pragma unroll
                for (int j = 0; j < 8; j++) x[j] = 0.0f;
                if (grow < M && (k0 + cc) < K) {
                    float4 v0 = *(const float4*)(arow + k0 + cc);
                    float4 v1 = *(const float4*)(arow + k0 + cc + 4);
                    x[0] = v0.x; x[1] = v0.y; x[2] = v0.z; x[3] = v0.w;
                    x[4] = v1.x; x[5] = v1.y; x[6] = v1.z; x[7] = v1.w;
                }
                uint32_t h4[4];
#pragma unroll
                for (int j = 0; j < 4; j++) h4[j] = pack_h2(x[2 * j], x[2 * j + 1]);
                const uint32_t off = SWZ(ar * 128 + cc * 2);
                asm volatile("st.shared.v4.b32 [%0], {%1, %2, %3, %4};" :: "r"(aB + off), "r"(h4[0]), "r"(h4[1]), "r"(h4[2]), "r"(h4[3]) : "memory");
            }
        }

        // ---- prefetch next B, then wait ----
        if (c + 1 < nch) {
            issueB(c + 1, (c + 1) & 1);
            CPA_WAIT1();
        } else {
            CPA_WAIT0();
        }
        __syncthreads();

        // ---- compute: 1-pass fp16 ----
        const uint32_t bC = bBuf0 + (uint32_t)(c & 1) * 16384;
#pragma unroll
        for (int ks = 0; ks < 4; ks++) {
            const uint32_t akb = ((uint32_t)(ks * 32) + a_khalf) ^ a_xm;
            uint32_t ah[2][4];
            ldm4(ah[0], aB + a_off0 + akb);
            ldm4(ah[1], aB + a_off1 + akb);
            const uint32_t bkb = ((uint32_t)(ks * 32) + b_khalf) ^ b_xm;
#pragma unroll
            for (int j = 0; j < 4; j++) {
                uint32_t bh[4];
                const uint32_t boff = b_rowbase + (uint32_t)j * 2048;
                ldm4(bh, bC + boff + bkb);
#pragma unroll
                for (int mt = 0; mt < 2; mt++) {
                    mma_fp16(acc[mt][2 * j],     ah[mt], bh[0], bh[1]);
                    mma_fp16(acc[mt][2 * j + 1], ah[mt], bh[2], bh[3]);
                }
            }
        }
    }

    // ---- epilogue ----
    const int rq = lane >> 2;
    const int cq = (lane & 3) * 2;

    if (S.bias) {
#pragma unroll
        for (int nt = 0; nt < 8; nt++) {
            float2 bv = __ldg((const float2*)(S.bias + wn * 64 + nt * 8 + cq));
#pragma unroll
            for (int mt = 0; mt < 2; mt++) {
                acc[mt][nt][0] += bv.x; acc[mt][nt][1] += bv.y;
                acc[mt][nt][2] += bv.x; acc[mt][nt][3] += bv.y;
            }
        }
    }
    if (DO_LN) {
        float s1[2][2], s2[2][2];
#pragma unroll
        for (int mt = 0; mt < 2; mt++)
#pragma unroll
            for (int h = 0; h < 2; h++) { s1[mt][h] = 0.f; s2[mt][h] = 0.f; }
#pragma unroll
        for (int mt = 0; mt < 2; mt++)
#pragma unroll
            for (int nt = 0; nt < 8; nt++) {
                s1[mt][0] += acc[mt][nt][0] + acc[mt][nt][1];
                s2[mt][0] += acc[mt][nt][0] * acc[mt][nt][0] + acc[mt][nt][1] * acc[mt][nt][1];
                s1[mt][1] += acc[mt][nt][2] + acc[mt][nt][3];
                s2[mt][1] += acc[mt][nt][2] * acc[mt][nt][2] + acc[mt][nt][3] * acc[mt][nt][3];
            }
#pragma unroll
        for (int o = 1; o < 4; o <<= 1) {
#pragma unroll
            for (int mt = 0; mt < 2; mt++)
#pragma unroll
                for (int h = 0; h < 2; h++) {
                    s1[mt][h] += __shfl_xor_sync(0xFFFFFFFFu, s1[mt][h], o);
                    s2[mt][h] += __shfl_xor_sync(0xFFFFFFFFu, s2[mt][h], o);
                }
        }
        float* sc = (float*)smem;
        __syncthreads();
        if ((lane & 3) == 0) {
#pragma unroll
            for (int mt = 0; mt < 2; mt++)
#pragma unroll
                for (int h = 0; h < 2; h++) {
                    int rl = wm * 32 + mt * 16 + h * 8 + rq;
                    sc[wn * 128 + rl] = s1[mt][h];
                    sc[256 + wn * 128 + rl] = s2[mt][h];
                }
        }
        __syncthreads();
#pragma unroll
        for (int mt = 0; mt < 2; mt++)
#pragma unroll
            for (int h = 0; h < 2; h++) {
                int rl = wm * 32 + mt * 16 + h * 8 + rq;
                float S1 = sc[rl] + sc[128 + rl];
                float S2 = sc[256 + rl] + sc[384 + rl];
                float mean = S1 * (1.0f / 128.0f);
                float var = S2 * (1.0f / 128.0f) - mean * mean;
                float rstd = rsqrtf(var + 1e-5f);
                s1[mt][h] = mean;
                s2[mt][h] = rstd;
            }
#pragma unroll
        for (int nt = 0; nt < 8; nt++) {
            float2 g = __ldg((const float2*)(S.gamma + wn * 64 + nt * 8 + cq));
            float2 b = __ldg((const float2*)(S.beta + wn * 64 + nt * 8 + cq));
#pragma unroll
            for (int mt = 0; mt < 2; mt++) {
                acc[mt][nt][0] = (acc[mt][nt][0] - s1[mt][0]) * s2[mt][0] * g.x + b.x;
                acc[mt][nt][1] = (acc[mt][nt][1] - s1[mt][0]) * s2[mt][0] * g.y + b.y;
                acc[mt][nt][2] = (acc[mt][nt][2] - s1[mt][1]) * s2[mt][1] * g.x + b.x;
                acc[mt][nt][3] = (acc[mt][nt][3] - s1[mt][1]) * s2[mt][1] * g.y + b.y;
            }
        }
    }
    if (DO_RELU) {
#pragma unroll
        for (int mt = 0; mt < 2; mt++)
#pragma unroll
            for (int nt = 0; nt < 8; nt++)
#pragma unroll
                for (int j = 0; j < 4; j++) acc[mt][nt][j] = fmaxf(acc[mt][nt][j], 0.0f);
    }
    if (SPLIT) {
        __half* dst = wn ? S.outh2 : S.outh;
#pragma unroll
        for (int mt = 0; mt < 2; mt++)
#pragma unroll
            for (int h = 0; h < 2; h++) {
                int row = r0 + wm * 32 + mt * 16 + h * 8 + rq;
                if (row < M) {
#pragma unroll
                    for (int nt = 0; nt < 8; nt++)
                        *(uint32_t*)(dst + (size_t)row * 64 + nt * 8 + cq) =
                            pack_h2(acc[mt][nt][2 * h], acc[mt][nt][2 * h + 1]);
                }
            }
    } else {
#pragma unroll
        for (int mt = 0; mt < 2; mt++)
#pragma unroll
            for (int h = 0; h < 2; h++) {
                int row = r0 + wm * 32 + mt * 16 + h * 8 + rq;
                if (row < M) {
#pragma unroll
                    for (int nt = 0; nt < 8; nt++)
                        *(uint32_t*)(S.outh + (size_t)row * BN + wn * 64 + nt * 8 + cq) =
                            pack_h2(acc[mt][nt][2 * h], acc[mt][nt][2 * h + 1]);
                }
            }
    }
}

// ---------------- host launcher ----------------
extern "C" void kernel_launch(void* const* d_in, const int* in_sizes, int n_in,
                              void* d_out, int out_size) {
    const float* x_user = (const float*)d_in[0];
    const float* x_item = (const float*)d_in[1];
    const int* edge_ui = (const int*)d_in[2];
    const int* edge_iu = (const int*)d_in[3];
    const float* Wp_u = (const float*)d_in[4];
    const float* bp_u = (const float*)d_in[5];
    const float* Wp_i = (const float*)d_in[6];
    const float* bp_i = (const float*)d_in[7];
    const float* Wl0_ui = (const float*)d_in[8];
    const float* bl0_ui = (const float*)d_in[9];
    const float* Wr0_ui = (const float*)d_in[10];
    const float* Wl0_iu = (const float*)d_in[11];
    const float* bl0_iu = (const float*)d_in[12];
    const float* Wr0_iu = (const float*)d_in[13];
    const float* g0_u = (const float*)d_in[14];
    const float* b0_u = (const float*)d_in[15];
    const float* g0_i = (const float*)d_in[16];
    const float* b0_i = (const float*)d_in[17];
    const float* Wl1_ui = (const float*)d_in[18];
    const float* bl1_ui = (const float*)d_in[19];
    const float* Wr1_ui = (const float*)d_in[20];
    const float* Wl1_iu = (const float*)d_in[21];
    const float* bl1_iu = (const float*)d_in[22];
    const float* Wr1_iu = (const float*)d_in[23];
    const float* g1_u = (const float*)d_in[24];
    const float* b1_u = (const float*)d_in[25];
    const float* g1_i = (const float*)d_in[26];
    const float* b1_i = (const float*)d_in[27];

    const int E = in_sizes[2] / 2;

    __half *hu, *hi, *agg_u, *agg_i, *hu1, *hi1, *proj_u, *root_u, *proj_i, *root_i;
    int *cnt, *off, *pos, *csr_iu, *csr_ui, *part;
    cudaGetSymbolAddress((void**)&hu, g_hu);
    cudaGetSymbolAddress((void**)&hi, g_hi);
    cudaGetSymbolAddress((void**)&agg_u, g_agg_u);
    cudaGetSymbolAddress((void**)&agg_i, g_agg_i);
    cudaGetSymbolAddress((void**)&hu1, g_hu1);
    cudaGetSymbolAddress((void**)&hi1, g_hi1);
    cudaGetSymbolAddress((void**)&proj_u, g_proj_u);
    cudaGetSymbolAddress((void**)&root_u, g_root_u);
    cudaGetSymbolAddress((void**)&proj_i, g_proj_i);
    cudaGetSymbolAddress((void**)&root_i, g_root_i);
    cudaGetSymbolAddress((void**)&cnt, g_cnt);
    cudaGetSymbolAddress((void**)&off, g_off);
    cudaGetSymbolAddress((void**)&pos, g_pos);
    cudaGetSymbolAddress((void**)&csr_iu, g_csr_iu);
    cudaGetSymbolAddress((void**)&csr_ui, g_csr_ui);
    cudaGetSymbolAddress((void**)&part, g_part);

    __half *wpu, *wpi, *wl0ui, *wr0ui, *wl0iu, *wr0iu, *w1u, *w1i;
    cudaGetSymbolAddress((void**)&wpu, g_wpu);
    cudaGetSymbolAddress((void**)&wpi, g_wpi);
    cudaGetSymbolAddress((void**)&wl0ui, g_wl0ui);
    cudaGetSymbolAddress((void**)&wr0ui, g_wr0ui);
    cudaGetSymbolAddress((void**)&wl0iu, g_wl0iu);
    cudaGetSymbolAddress((void**)&wr0iu, g_wr0iu);
    cudaGetSymbolAddress((void**)&w1u, g_w1u);
    cudaGetSymbolAddress((void**)&w1i, g_w1i);

    float* out_u = (float*)d_out;
    float* out_i = (float*)d_out + (size_t)NN * OD;

    const int SM = 16384 + 2 * 16384;   // A 16KB + B 2x16KB = 48KB
    cudaFuncSetAttribute(mma_gemm<false, false, false, false, true>, cudaFuncAttributeMaxDynamicSharedMemorySize, SM);
    cudaFuncSetAttribute(mma_gemm<true, true, false, true, true>, cudaFuncAttributeMaxDynamicSharedMemorySize, SM);
    cudaFuncSetAttribute(mma_gemm<false, true, true, false, false>, cudaFuncAttributeMaxDynamicSharedMemorySize, SM);

    const int GM = (NN + 127) / 128;

    // fork a side stream for the CSR chain (independent of weights/proj)
    cudaStream_t sB;
    cudaEvent_t eFork, eJoin;
    cudaStreamCreateWithFlags(&sB, cudaStreamNonBlocking);
    cudaEventCreateWithFlags(&eFork, cudaEventDisableTiming);
    cudaEventCreateWithFlags(&eJoin, cudaEventDisableTiming);

    cudaEventRecord(eFork, 0);
    cudaStreamWaitEvent(sB, eFork, 0);

    // side stream: degree + CSR build
    {
        dim3 ge((E + 255) / 256, 2);
        zero_cnt_kernel<<<(2 * NN + 255) / 256, 256, 0, sB>>>(cnt);
        count_kernel<<<ge, 256, 0, sB>>>(edge_iu + E, edge_ui + E, E, cnt);
        scan_part_kernel<<<dim3(NBLK, 2), 256, 0, sB>>>(cnt, part);
        scan_partials_kernel<<<dim3(1, 2), 512, 0, sB>>>(part, NBLK);
        scan_final_kernel<<<dim3(NBLK, 2), 256, 0, sB>>>(cnt, part, off, pos);
        build_csr_kernel<<<ge, 256, 0, sB>>>(edge_iu, edge_ui, E, pos, csr_iu, csr_ui);
        cudaEventRecord(eJoin, sB);
    }

    // main stream: weight convert + projection GEMM pair
    {
        WCon10 P;
        P.s[0] = { Wp_u,   wpu,   FU, HD, 128 };
        P.s[1] = { Wp_i,   wpi,   FI, HD, 192 };
        P.s[2] = { Wl0_ui, wl0ui, HD, HD, 128 };
        P.s[3] = { Wr0_ui, wr0ui, HD, HD, 128 };
        P.s[4] = { Wl0_iu, wl0iu, HD, HD, 128 };
        P.s[5] = { Wr0_iu, wr0iu, HD, HD, 128 };
        P.s[6] = { Wl1_ui, w1u,            HD, OD, 128 };
        P.s[7] = { Wr1_iu, w1u + 64 * 128, HD, OD, 128 };
        P.s[8] = { Wl1_iu, w1i,            HD, OD, 128 };
        P.s[9] = { Wr1_ui, w1i + 64 * 128, HD, OD, 128 };
        dim3 g((192 * 128 + 255) / 256, 10);
        wconv_kernel<<<g, 256>>>(P);
    }
    {
        GSide su = { x_user, nullptr, nullptr, wpu, FU, 128, nullptr, 0,
                     bp_u, nullptr, nullptr, hu, nullptr };
        GSide si = { x_item, nullptr, nullptr, wpi, FI, 192, nullptr, 0,
                     bp_i, nullptr, nullptr, hi, nullptr };
        mma_gemm<false, false, false, false, true><<<dim3(GM, 2), 256, SM>>>(su, si, NN);
    }

    // join: gather needs CSR + proj outputs
    cudaStreamWaitEvent(0, eJoin, 0);

    // layer 0 aggregation (fp16 in/out). t=0: agg_u <- hi via csr_iu; t=1: agg_i <- hu via csr_ui
    {
        const long tot = (long)NN * 32;
        dim3 gg((unsigned)((tot + 255) / 256), 2);
        gather_mean_kernel<<<gg, 256>>>(hi, csr_iu, agg_u, hu, csr_ui, agg_i, off, cnt);
    }

    // layer 0 fused dual-GEMM + bias + LN + ReLU -> fp16 h1 planes (A1=agg fp16, A2=root fp16)
    {
        GSide si = { nullptr, agg_i, hi, wl0ui, HD, 128, wr0ui, 128,
                     bl0_ui, g0_i, b0_i, hi1, nullptr };
        GSide su = { nullptr, agg_u, hu, wl0iu, HD, 128, wr0iu, 128,
                     bl0_iu, g0_u, b0_u, hu1, nullptr };
        mma_gemm<true, true, false, true, true><<<dim3(GM, 2), 256, SM>>>(si, su, NN);
    }

    // layer 1 combined GEMM pair: [proj|root] = h1 @ [Wl1 | Wr1], fp16 A plane, split fp16 outputs
    {
        GSide su = { nullptr, hu1, nullptr, w1u, HD, 128, nullptr, 0,
                     nullptr, nullptr, nullptr, proj_u, root_u };
        GSide si = { nullptr, hi1, nullptr, w1i, HD, 128, nullptr, 0,
                     nullptr, nullptr, nullptr, proj_i, root_i };
        mma_gemm<false, true, true, false, false><<<dim3(GM, 2), 256, SM>>>(su, si, NN);
    }

    // fused layer-1 gather + final LN (fp16 proj/root)
    {
        FSide fu = { proj_i, root_u, csr_iu, bl1_iu, g1_u, b1_u, out_u };
        FSide fi = { proj_u, root_i, csr_ui, bl1_ui, g1_i, b1_i, out_i };
        dim3 gf((NN + 7) / 8, 2);
        final_fused_kernel<<<gf, 256>>>(fu, fi, off, cnt);
    }

    (void)n_in; (void)out_size; (void)in_sizes;
}

// round 14
// speedup vs baseline: 1.7908x; 1.0170x over previous
#include <cuda_runtime.h>
#include <cuda_fp16.h>
#include <cstdint>

// ---------------- problem constants ----------------
#define NU 100000
#define NI 100000
#define NN 100000   // NU == NI
#define FU 96
#define FI 160
#define HD 128
#define OD 64
#define EMAX 600000
#define NBLK 391   // ceil(100000/256)

// ---------------- scratch (device globals) ----------------
__device__ __half g_hu   [NN * HD];   // fp16 proj planes (gather input + layer0 root)
__device__ __half g_hi   [NN * HD];
__device__ __half g_agg_u[NN * HD];   // fp16 agg planes (gather output = layer0 A)
__device__ __half g_agg_i[NN * HD];
__device__ __half g_hu1  [NN * HD];   // fp16 h1 planes (layer0 out = layer1 A)
__device__ __half g_hi1  [NN * HD];
__device__ __half g_proj_u[NN * OD];  // fp16 layer-1 outputs
__device__ __half g_root_u[NN * OD];
__device__ __half g_proj_i[NN * OD];
__device__ __half g_root_i[NN * OD];
__device__ int    g_cnt [2 * NN];
__device__ int    g_off [2 * NN];
__device__ int    g_pos [2 * NN];
__device__ int    g_csr_iu[EMAX];
__device__ int    g_csr_ui[EMAX];
__device__ int    g_part[2 * 512];

// transposed fp16 weights: layout [N rows, Kpad cols], zero padded
__device__ __half g_wpu[128 * 128];
__device__ __half g_wpi[128 * 192];
__device__ __half g_wl0ui[128 * 128];
__device__ __half g_wr0ui[128 * 128];
__device__ __half g_wl0iu[128 * 128];
__device__ __half g_wr0iu[128 * 128];
__device__ __half g_w1u[128 * 128];   // [Wl1_ui | Wr1_iu]
__device__ __half g_w1i[128 * 128];   // [Wl1_iu | Wr1_ui]

// ---------------- helpers ----------------
__device__ __forceinline__ uint32_t smem_u32(const void* p) {
    uint32_t a;
    asm("{ .reg .u64 t; cvta.to.shared.u64 t, %1; cvt.u32.u64 %0, t; }" : "=r"(a) : "l"(p));
    return a;
}
#define SWZ(x) ((x) ^ (((x) >> 3) & 0x70))

#define CPA16(dst, src) \
    asm volatile("cp.async.ca.shared.global [%0], [%1], 16;" :: "r"(dst), "l"(src) : "memory")
#define CPA_COMMIT() asm volatile("cp.async.commit_group;" ::: "memory")
#define CPA_WAIT1()  asm volatile("cp.async.wait_group 1;" ::: "memory")
#define CPA_WAIT0()  asm volatile("cp.async.wait_group 0;" ::: "memory")

__device__ __forceinline__ void ldm4(uint32_t* r, uint32_t addr) {
    asm volatile("ldmatrix.sync.aligned.m8n8.x4.shared.b16 {%0,%1,%2,%3}, [%4];"
        : "=r"(r[0]), "=r"(r[1]), "=r"(r[2]), "=r"(r[3]) : "r"(addr));
}
__device__ __forceinline__ void mma_fp16(float* c, const uint32_t* a, uint32_t b0, uint32_t b1) {
    asm volatile("mma.sync.aligned.m16n8k16.row.col.f32.f16.f16.f32 "
        "{%0,%1,%2,%3}, {%4,%5,%6,%7}, {%8,%9}, {%0,%1,%2,%3};"
        : "+f"(c[0]), "+f"(c[1]), "+f"(c[2]), "+f"(c[3])
        : "r"(a[0]), "r"(a[1]), "r"(a[2]), "r"(a[3]), "r"(b0), "r"(b1));
}
__device__ __forceinline__ uint32_t pack_h2(float x0, float x1) {
    __half2 h = __floats2half2_rn(x0, x1);
    return *reinterpret_cast<uint32_t*>(&h);
}

// ---------------- CSR build chain ----------------
__global__ void zero_cnt_kernel(int* __restrict__ cnt) {
    int i = blockIdx.x * blockDim.x + threadIdx.x;
    if (i < 2 * NN) cnt[i] = 0;
}

__global__ void count_kernel(const int* __restrict__ dst0, const int* __restrict__ dst1,
                             int E, int* __restrict__ cnt) {
    int t = blockIdx.y;
    const int* dst = t ? dst1 : dst0;
    int* c = cnt + t * NN;
    int e = blockIdx.x * blockDim.x + threadIdx.x;
    if (e < E) atomicAdd(&c[dst[e]], 1);
}

__global__ void scan_part_kernel(const int* __restrict__ cnt, int* __restrict__ part) {
    __shared__ int sh[256];
    const int* c = cnt + blockIdx.y * NN;
    int* p = part + blockIdx.y * 512;
    int i = blockIdx.x * 256 + threadIdx.x;
    sh[threadIdx.x] = (i < NN) ? c[i] : 0;
    __syncthreads();
    for (int s = 128; s > 0; s >>= 1) {
        if (threadIdx.x < s) sh[threadIdx.x] += sh[threadIdx.x + s];
        __syncthreads();
    }
    if (threadIdx.x == 0) p[blockIdx.x] = sh[0];
}

__global__ void scan_partials_kernel(int* __restrict__ part, int nb) {
    __shared__ int sh[512];
    int* p = part + blockIdx.y * 512;
    int t = threadIdx.x;
    int v = (t < nb) ? p[t] : 0;
    sh[t] = v;
    __syncthreads();
    for (int o = 1; o < 512; o <<= 1) {
        int x = (t >= o) ? sh[t - o] : 0;
        __syncthreads();
        sh[t] += x;
        __syncthreads();
    }
    if (t < nb) p[t] = sh[t] - v;  // exclusive
}

__global__ void scan_final_kernel(const int* __restrict__ cnt, const int* __restrict__ part,
                                  int* __restrict__ off, int* __restrict__ pos) {
    __shared__ int sh[256];
    const int* c = cnt + blockIdx.y * NN;
    const int* p = part + blockIdx.y * 512;
    int* of = off + blockIdx.y * NN;
    int* ps = pos + blockIdx.y * NN;
    int t = threadIdx.x;
    int i = blockIdx.x * 256 + t;
    int v = (i < NN) ? c[i] : 0;
    sh[t] = v;
    __syncthreads();
    for (int o = 1; o < 256; o <<= 1) {
        int x = (t >= o) ? sh[t - o] : 0;
        __syncthreads();
        sh[t] += x;
        __syncthreads();
    }
    if (i < NN) {
        int e = sh[t] - v + p[blockIdx.x];
        of[i] = e;
        ps[i] = e;
    }
}

__global__ void build_csr_kernel(const int* __restrict__ e0, const int* __restrict__ e1,
                                 int E, int* __restrict__ pos,
                                 int* __restrict__ c0, int* __restrict__ c1) {
    int t = blockIdx.y;
    const int* edge = t ? e1 : e0;
    int* ps = pos + t * NN;
    int* csr = t ? c1 : c0;
    int e = blockIdx.x * blockDim.x + threadIdx.x;
    if (e < E) {
        int s = edge[e];
        int d = edge[E + e];
        int idx = atomicAdd(&ps[d], 1);
        csr[idx] = s;
    }
}

// ---------------- gather-mean aggregation (layer 0, C=128), fp16 in / fp16 out ----------------
__global__ void gather_mean_kernel(const __half* __restrict__ fA, const int* __restrict__ csrA, __half* __restrict__ oA,
                                   const __half* __restrict__ fB, const int* __restrict__ csrB, __half* __restrict__ oB,
                                   const int* __restrict__ off, const int* __restrict__ cnt) {
    constexpr int G = 32;
    const int t = blockIdx.y;
    const __half* feat = t ? fB : fA;
    const int* csr = t ? csrB : csrA;
    __half* out = t ? oB : oA;
    const int* of = off + t * NN;
    const int* cn = cnt + t * NN;

    int gid = (int)((blockIdx.x * (size_t)blockDim.x + threadIdx.x) / G);
    if (gid >= NN) return;
    const int c4 = (threadIdx.x & (G - 1)) * 4;
    const int beg = __ldg(&of[gid]);
    const int deg = __ldg(&cn[gid]);

    float4 a0 = make_float4(0.f, 0.f, 0.f, 0.f);
    float4 a1 = make_float4(0.f, 0.f, 0.f, 0.f);
    float4 a2 = make_float4(0.f, 0.f, 0.f, 0.f);
    float4 a3 = make_float4(0.f, 0.f, 0.f, 0.f);
    int e = 0;
    for (; e + 3 < deg; e += 4) {
        int s0 = __ldg(&csr[beg + e]);
        int s1 = __ldg(&csr[beg + e + 1]);
        int s2 = __ldg(&csr[beg + e + 2]);
        int s3 = __ldg(&csr[beg + e + 3]);
        const __half2* p0 = (const __half2*)(feat + (size_t)s0 * HD + c4);
        const __half2* p1 = (const __half2*)(feat + (size_t)s1 * HD + c4);
        const __half2* p2 = (const __half2*)(feat + (size_t)s2 * HD + c4);
        const __half2* p3 = (const __half2*)(feat + (size_t)s3 * HD + c4);
        float2 u0 = __half22float2(p0[0]), w0 = __half22float2(p0[1]);
        float2 u1 = __half22float2(p1[0]), w1 = __half22float2(p1[1]);
        float2 u2 = __half22float2(p2[0]), w2 = __half22float2(p2[1]);
        float2 u3 = __half22float2(p3[0]), w3 = __half22float2(p3[1]);
        a0.x += u0.x; a0.y += u0.y; a0.z += w0.x; a0.w += w0.y;
        a1.x += u1.x; a1.y += u1.y; a1.z += w1.x; a1.w += w1.y;
        a2.x += u2.x; a2.y += u2.y; a2.z += w2.x; a2.w += w2.y;
        a3.x += u3.x; a3.y += u3.y; a3.z += w3.x; a3.w += w3.y;
    }
    for (; e < deg; e++) {
        int s0 = __ldg(&csr[beg + e]);
        const __half2* p0 = (const __half2*)(feat + (size_t)s0 * HD + c4);
        float2 u0 = __half22float2(p0[0]), w0 = __half22float2(p0[1]);
        a0.x += u0.x; a0.y += u0.y; a0.z += w0.x; a0.w += w0.y;
    }
    const float sc = 1.0f / fmaxf((float)deg, 1.0f);
    uint2 r;
    r.x = pack_h2((a0.x + a1.x + a2.x + a3.x) * sc, (a0.y + a1.y + a2.y + a3.y) * sc);
    r.y = pack_h2((a0.z + a1.z + a2.z + a3.z) * sc, (a0.w + a1.w + a2.w + a3.w) * sc);
    *(uint2*)(out + (size_t)gid * HD + c4) = r;
}

// ---------------- fused layer-1 gather + final LN (fp16 proj/root inputs) ----------------
struct FSide { const __half* proj_src; const __half* root; const int* csr;
               const float* bias; const float* g; const float* b; float* out; };
__global__ void final_fused_kernel(FSide f0, FSide f1, const int* __restrict__ off, const int* __restrict__ cnt) {
    const int t = blockIdx.y;
    FSide s = t ? f1 : f0;
    const int* of = off + t * NN;
    const int* cn = cnt + t * NN;
    const int warp = threadIdx.x >> 5;
    const int lane = threadIdx.x & 31;
    const int row = blockIdx.x * 8 + warp;
    if (row >= NN) return;
    const int c = lane * 2;
    const int beg = __ldg(&of[row]);
    const int deg = __ldg(&cn[row]);

    float x0 = 0.f, y0 = 0.f, x1 = 0.f, y1 = 0.f;
    int e = 0;
    for (; e + 1 < deg; e += 2) {
        int s0 = __ldg(&s.csr[beg + e]);
        int s1 = __ldg(&s.csr[beg + e + 1]);
        float2 v0 = __half22float2(*(const __half2*)(s.proj_src + (size_t)s0 * OD + c));
        float2 v1 = __half22float2(*(const __half2*)(s.proj_src + (size_t)s1 * OD + c));
        x0 += v0.x; y0 += v0.y;
        x1 += v1.x; y1 += v1.y;
    }
    if (e < deg) {
        int s0 = __ldg(&s.csr[beg + e]);
        float2 v0 = __half22float2(*(const __half2*)(s.proj_src + (size_t)s0 * OD + c));
        x0 += v0.x; y0 += v0.y;
    }
    const float sc = 1.0f / fmaxf((float)deg, 1.0f);
    float2 rv = __half22float2(*(const __half2*)(s.root + (size_t)row * OD + c));
    float2 bv = __ldg((const float2*)(s.bias + c));
    float v0 = (x0 + x1) * sc + rv.x + bv.x;
    float v1 = (y0 + y1) * sc + rv.y + bv.y;

    float s1v = v0 + v1;
    float s2v = v0 * v0 + v1 * v1;
#pragma unroll
    for (int o = 16; o > 0; o >>= 1) {
        s1v += __shfl_xor_sync(0xFFFFFFFFu, s1v, o);
        s2v += __shfl_xor_sync(0xFFFFFFFFu, s2v, o);
    }
    float mean = s1v * (1.0f / 64.0f);
    float var = s2v * (1.0f / 64.0f) - mean * mean;
    float rstd = rsqrtf(var + 1e-5f);
    float2 gv = __ldg((const float2*)(s.g + c));
    float2 bb = __ldg((const float2*)(s.b + c));
    float2 o2;
    o2.x = (v0 - mean) * rstd * gv.x + bb.x;
    o2.y = (v1 - mean) * rstd * gv.y + bb.y;
    *(float2*)(s.out + (size_t)row * 64 + c) = o2;
}

// weight transpose to fp16: W [K,N] fp32 -> Wt [N,Kpad] fp16, zero pad
struct WCon { const float* w; __half* h; int K, N, Kpad; };
struct WCon10 { WCon s[10]; };
__global__ void wconv_kernel(WCon10 P) {
    WCon w = P.s[blockIdx.y];
    int idx = blockIdx.x * blockDim.x + threadIdx.x;
    if (idx >= w.N * w.Kpad) return;
    int n = idx / w.Kpad, k = idx % w.Kpad;
    float x = (k < w.K) ? w.w[(size_t)k * w.N + n] : 0.0f;
    w.h[idx] = __float2half(x);
}

// ---------------- HMMA fp16 GEMM, BN=128, 4x2 warp tiling, paired via gridDim.y ----------------
// 1-pass fp16. A and B both double-buffered; chunk c+1 staged (cp.async) before waiting on chunk c,
// so staging latency overlaps compute. For !AHALF, A is staged synchronously (fp32->fp16 convert).
// SPLIT: fp16 outputs, cols 0-63 -> outh, 64-127 -> outh2 (stride 64); else fp16 plane stride 128.
#define BN 128

struct GSide {
    const float* A1; const __half* A1h; const __half* A2h;
    const __half* W1; int K1; int K1pad;
    const __half* W2; int K2pad;
    const float* bias; const float* gamma; const float* beta;
    __half* outh; __half* outh2;
};

template <bool FUSE2, bool AHALF, bool SPLIT, bool DO_LN, bool DO_RELU>
__global__ __launch_bounds__(256, 2)
void mma_gemm(GSide s0, GSide s1, int M) {
    const GSide& S = blockIdx.y ? s1 : s0;

    extern __shared__ char smem[];
    const uint32_t sb = smem_u32(smem);
    const uint32_t aBuf0 = sb;              // A: 2 x 16KB
    const uint32_t bBuf0 = sb + 32768;      // B: 2 x 16KB

    const int tid = threadIdx.x;
    const int warp = tid >> 5;
    const int lane = tid & 31;
    const int wm = warp & 3;
    const int wn = warp >> 2;
    const int r0 = blockIdx.x * 128;

    float acc[2][8][4];
#pragma unroll
    for (int mt = 0; mt < 2; mt++)
#pragma unroll
        for (int nt = 0; nt < 8; nt++)
#pragma unroll
            for (int j = 0; j < 4; j++) acc[mt][nt][j] = 0.0f;

    // staging mapping
    const int ar = tid >> 1;
    const int acb = (tid & 1) * 32;
    const int bn = tid >> 1;
    const int bq = tid & 1;

    // compute-phase lane constants
    const uint32_t a_off0 = (uint32_t)(wm * 32 + (lane & 15)) * 128;
    const uint32_t a_off1 = a_off0 + 16 * 128;
    const uint32_t a_xm = (lane & 7) * 16;
    const uint32_t a_khalf = ((lane >> 4) & 1) * 16;
    const uint32_t b_rowbase = (uint32_t)(wn * 64 + (lane & 7) + ((lane >> 4) & 1) * 8) * 128;
    const uint32_t b_xm = (lane & 7) * 16;
    const uint32_t b_khalf = ((lane >> 3) & 1) * 16;

    const int nch1 = S.K1pad >> 6;
    const int nch = nch1 + (FUSE2 ? (S.K2pad >> 6) : 0);

    auto issueB = [&](int c, int buf) {
        const __half* W;
        int k0, Kpad;
        if (!FUSE2 || c < nch1) { W = S.W1; k0 = c * 64; Kpad = S.K1pad; }
        else                    { W = S.W2; k0 = (c - nch1) * 64; Kpad = S.K2pad; }
        const uint32_t bB = bBuf0 + (uint32_t)buf * 16384;
#pragma unroll
        for (int i = 0; i < 4; i++) {
            const int ck = bq * 32 + i * 8;
            const size_t so = (size_t)bn * Kpad + k0 + ck;
            const uint32_t off = SWZ(bn * 128 + ck * 2);
            CPA16(bB + off, W + so);
        }
    };
    auto issueA = [&](int c, int buf) {   // AHALF only
        const __half* base;
        int k0;
        if (!FUSE2 || c < nch1) { base = S.A1h; k0 = c * 64; }
        else                    { base = S.A2h; k0 = (c - nch1) * 64; }
        const int grow = r0 + ar;
        const int srow = (grow < M) ? grow : 0;
        const __half* src = base + (size_t)srow * HD + k0 + acb;
        const uint32_t aB = aBuf0 + (uint32_t)buf * 16384;
#pragma unroll
        for (int i = 0; i < 4; i++) {
            const uint32_t off = SWZ(ar * 128 + (acb + i * 8) * 2);
            CPA16(aB + off, src + i * 8);
        }
    };
    auto stageA_sync = [&](int c, int buf) {   // fp32 convert path
        const int k0 = c * 64;
        const int K = S.K1;
        const int grow = r0 + ar;
        const float* arow = S.A1 + (size_t)grow * K;
        const uint32_t aB = aBuf0 + (uint32_t)buf * 16384;
#pragma unroll
        for (int i = 0; i < 4; i++) {
            const int cc = acb + i * 8;
            float x[8];
#pragma unroll
            for (int j = 0; j < 8; j++) x[j] = 0.0f;
            if (grow < M && (k0 + cc) < K) {
                float4 v0 = *(const float4*)(arow + k0 + cc);
                float4 v1 = *(const float4*)(arow + k0 + cc + 4);
                x[0] = v0.x; x[1] = v0.y; x[2] = v0.z; x[3] = v0.w;
                x[4] = v1.x; x[5] = v1.y; x[6] = v1.z; x[7] = v1.w;
            }
            uint32_t h4[4];
#pragma unroll
            for (int j = 0; j < 4; j++) h4[j] = pack_h2(x[2 * j], x[2 * j + 1]);
            const uint32_t off = SWZ(ar * 128 + cc * 2);
            asm volatile("st.shared.v4.b32 [%0], {%1, %2, %3, %4};" :: "r"(aB + off), "r"(h4[0]), "r"(h4[1]), "r"(h4[2]), "r"(h4[3]) : "memory");
        }
    };

    // prologue: stage chunk 0
    if (AHALF) issueA(0, 0);
    issueB(0, 0);
    CPA_COMMIT();

    for (int c = 0; c < nch; c++) {
        if (c) __syncthreads();   // all warps done with compute(c-1); buffers (c+1)&1 free

        if (!AHALF) stageA_sync(c, c & 1);

        if (c + 1 < nch) {
            if (AHALF) issueA(c + 1, (c + 1) & 1);
            issueB(c + 1, (c + 1) & 1);
            CPA_COMMIT();
            CPA_WAIT1();   // staging(c) complete; staging(c+1) in flight
        } else {
            CPA_WAIT0();
        }
        __syncthreads();

        // ---- compute(c) ----
        const uint32_t aC = aBuf0 + (uint32_t)(c & 1) * 16384;
        const uint32_t bC = bBuf0 + (uint32_t)(c & 1) * 16384;
#pragma unroll
        for (int ks = 0; ks < 4; ks++) {
            const uint32_t akb = ((uint32_t)(ks * 32) + a_khalf) ^ a_xm;
            uint32_t ah[2][4];
            ldm4(ah[0], aC + a_off0 + akb);
            ldm4(ah[1], aC + a_off1 + akb);
            const uint32_t bkb = ((uint32_t)(ks * 32) + b_khalf) ^ b_xm;
#pragma unroll
            for (int j = 0; j < 4; j++) {
                uint32_t bh[4];
                const uint32_t boff = b_rowbase + (uint32_t)j * 2048;
                ldm4(bh, bC + boff + bkb);
#pragma unroll
                for (int mt = 0; mt < 2; mt++) {
                    mma_fp16(acc[mt][2 * j],     ah[mt], bh[0], bh[1]);
                    mma_fp16(acc[mt][2 * j + 1], ah[mt], bh[2], bh[3]);
                }
            }
        }
    }

    // ---- epilogue ----
    const int rq = lane >> 2;
    const int cq = (lane & 3) * 2;

    if (S.bias) {
#pragma unroll
        for (int nt = 0; nt < 8; nt++) {
            float2 bv = __ldg((const float2*)(S.bias + wn * 64 + nt * 8 + cq));
#pragma unroll
            for (int mt = 0; mt < 2; mt++) {
                acc[mt][nt][0] += bv.x; acc[mt][nt][1] += bv.y;
                acc[mt][nt][2] += bv.x; acc[mt][nt][3] += bv.y;
            }
        }
    }
    if (DO_LN) {
        float s1[2][2], s2[2][2];
#pragma unroll
        for (int mt = 0; mt < 2; mt++)
#pragma unroll
            for (int h = 0; h < 2; h++) { s1[mt][h] = 0.f; s2[mt][h] = 0.f; }
#pragma unroll
        for (int mt = 0; mt < 2; mt++)
#pragma unroll
            for (int nt = 0; nt < 8; nt++) {
                s1[mt][0] += acc[mt][nt][0] + acc[mt][nt][1];
                s2[mt][0] += acc[mt][nt][0] * acc[mt][nt][0] + acc[mt][nt][1] * acc[mt][nt][1];
                s1[mt][1] += acc[mt][nt][2] + acc[mt][nt][3];
                s2[mt][1] += acc[mt][nt][2] * acc[mt][nt][2] + acc[mt][nt][3] * acc[mt][nt][3];
            }
#pragma unroll
        for (int o = 1; o < 4; o <<= 1) {
#pragma unroll
            for (int mt = 0; mt < 2; mt++)
#pragma unroll
                for (int h = 0; h < 2; h++) {
                    s1[mt][h] += __shfl_xor_sync(0xFFFFFFFFu, s1[mt][h], o);
                    s2[mt][h] += __shfl_xor_sync(0xFFFFFFFFu, s2[mt][h], o);
                }
        }
        float* sc = (float*)smem;
        __syncthreads();
        if ((lane & 3) == 0) {
#pragma unroll
            for (int mt = 0; mt < 2; mt++)
#pragma unroll
                for (int h = 0; h < 2; h++) {
                    int rl = wm * 32 + mt * 16 + h * 8 + rq;
                    sc[wn * 128 + rl] = s1[mt][h];
                    sc[256 + wn * 128 + rl] = s2[mt][h];
                }
        }
        __syncthreads();
#pragma unroll
        for (int mt = 0; mt < 2; mt++)
#pragma unroll
            for (int h = 0; h < 2; h++) {
                int rl = wm * 32 + mt * 16 + h * 8 + rq;
                float S1 = sc[rl] + sc[128 + rl];
                float S2 = sc[256 + rl] + sc[384 + rl];
                float mean = S1 * (1.0f / 128.0f);
                float var = S2 * (1.0f / 128.0f) - mean * mean;
                float rstd = rsqrtf(var + 1e-5f);
                s1[mt][h] = mean;
                s2[mt][h] = rstd;
            }
#pragma unroll
        for (int nt = 0; nt < 8; nt++) {
            float2 g = __ldg((const float2*)(S.gamma + wn * 64 + nt * 8 + cq));
            float2 b = __ldg((const float2*)(S.beta + wn * 64 + nt * 8 + cq));
#pragma unroll
            for (int mt = 0; mt < 2; mt++) {
                acc[mt][nt][0] = (acc[mt][nt][0] - s1[mt][0]) * s2[mt][0] * g.x + b.x;
                acc[mt][nt][1] = (acc[mt][nt][1] - s1[mt][0]) * s2[mt][0] * g.y + b.y;
                acc[mt][nt][2] = (acc[mt][nt][2] - s1[mt][1]) * s2[mt][1] * g.x + b.x;
                acc[mt][nt][3] = (acc[mt][nt][3] - s1[mt][1]) * s2[mt][1] * g.y + b.y;
            }
        }
    }
    if (DO_RELU) {
#pragma unroll
        for (int mt = 0; mt < 2; mt++)
#pragma unroll
            for (int nt = 0; nt < 8; nt++)
#pragma unroll
                for (int j = 0; j < 4; j++) acc[mt][nt][j] = fmaxf(acc[mt][nt][j], 0.0f);
    }
    if (SPLIT) {
        __half* dst = wn ? S.outh2 : S.outh;
#pragma unroll
        for (int mt = 0; mt < 2; mt++)
#pragma unroll
            for (int h = 0; h < 2; h++) {
                int row = r0 + wm * 32 + mt * 16 + h * 8 + rq;
                if (row < M) {
#pragma unroll
                    for (int nt = 0; nt < 8; nt++)
                        *(uint32_t*)(dst + (size_t)row * 64 + nt * 8 + cq) =
                            pack_h2(acc[mt][nt][2 * h], acc[mt][nt][2 * h + 1]);
                }
            }
    } else {
#pragma unroll
        for (int mt = 0; mt < 2; mt++)
#pragma unroll
            for (int h = 0; h < 2; h++) {
                int row = r0 + wm * 32 + mt * 16 + h * 8 + rq;
                if (row < M) {
#pragma unroll
                    for (int nt = 0; nt < 8; nt++)
                        *(uint32_t*)(S.outh + (size_t)row * BN + wn * 64 + nt * 8 + cq) =
                            pack_h2(acc[mt][nt][2 * h], acc[mt][nt][2 * h + 1]);
                }
            }
    }
}

// ---------------- host launcher ----------------
extern "C" void kernel_launch(void* const* d_in, const int* in_sizes, int n_in,
                              void* d_out, int out_size) {
    const float* x_user = (const float*)d_in[0];
    const float* x_item = (const float*)d_in[1];
    const int* edge_ui = (const int*)d_in[2];
    const int* edge_iu = (const int*)d_in[3];
    const float* Wp_u = (const float*)d_in[4];
    const float* bp_u = (const float*)d_in[5];
    const float* Wp_i = (const float*)d_in[6];
    const float* bp_i = (const float*)d_in[7];
    const float* Wl0_ui = (const float*)d_in[8];
    const float* bl0_ui = (const float*)d_in[9];
    const float* Wr0_ui = (const float*)d_in[10];
    const float* Wl0_iu = (const float*)d_in[11];
    const float* bl0_iu = (const float*)d_in[12];
    const float* Wr0_iu = (const float*)d_in[13];
    const float* g0_u = (const float*)d_in[14];
    const float* b0_u = (const float*)d_in[15];
    const float* g0_i = (const float*)d_in[16];
    const float* b0_i = (const float*)d_in[17];
    const float* Wl1_ui = (const float*)d_in[18];
    const float* bl1_ui = (const float*)d_in[19];
    const float* Wr1_ui = (const float*)d_in[20];
    const float* Wl1_iu = (const float*)d_in[21];
    const float* bl1_iu = (const float*)d_in[22];
    const float* Wr1_iu = (const float*)d_in[23];
    const float* g1_u = (const float*)d_in[24];
    const float* b1_u = (const float*)d_in[25];
    const float* g1_i = (const float*)d_in[26];
    const float* b1_i = (const float*)d_in[27];

    const int E = in_sizes[2] / 2;

    __half *hu, *hi, *agg_u, *agg_i, *hu1, *hi1, *proj_u, *root_u, *proj_i, *root_i;
    int *cnt, *off, *pos, *csr_iu, *csr_ui, *part;
    cudaGetSymbolAddress((void**)&hu, g_hu);
    cudaGetSymbolAddress((void**)&hi, g_hi);
    cudaGetSymbolAddress((void**)&agg_u, g_agg_u);
    cudaGetSymbolAddress((void**)&agg_i, g_agg_i);
    cudaGetSymbolAddress((void**)&hu1, g_hu1);
    cudaGetSymbolAddress((void**)&hi1, g_hi1);
    cudaGetSymbolAddress((void**)&proj_u, g_proj_u);
    cudaGetSymbolAddress((void**)&root_u, g_root_u);
    cudaGetSymbolAddress((void**)&proj_i, g_proj_i);
    cudaGetSymbolAddress((void**)&root_i, g_root_i);
    cudaGetSymbolAddress((void**)&cnt, g_cnt);
    cudaGetSymbolAddress((void**)&off, g_off);
    cudaGetSymbolAddress((void**)&pos, g_pos);
    cudaGetSymbolAddress((void**)&csr_iu, g_csr_iu);
    cudaGetSymbolAddress((void**)&csr_ui, g_csr_ui);
    cudaGetSymbolAddress((void**)&part, g_part);

    __half *wpu, *wpi, *wl0ui, *wr0ui, *wl0iu, *wr0iu, *w1u, *w1i;
    cudaGetSymbolAddress((void**)&wpu, g_wpu);
    cudaGetSymbolAddress((void**)&wpi, g_wpi);
    cudaGetSymbolAddress((void**)&wl0ui, g_wl0ui);
    cudaGetSymbolAddress((void**)&wr0ui, g_wr0ui);
    cudaGetSymbolAddress((void**)&wl0iu, g_wl0iu);
    cudaGetSymbolAddress((void**)&wr0iu, g_wr0iu);
    cudaGetSymbolAddress((void**)&w1u, g_w1u);
    cudaGetSymbolAddress((void**)&w1i, g_w1i);

    float* out_u = (float*)d_out;
    float* out_i = (float*)d_out + (size_t)NN * OD;

    const int SM = 65536;   // A 2x16KB + B 2x16KB
    cudaFuncSetAttribute(mma_gemm<false, false, false, false, true>, cudaFuncAttributeMaxDynamicSharedMemorySize, SM);
    cudaFuncSetAttribute(mma_gemm<true, true, false, true, true>, cudaFuncAttributeMaxDynamicSharedMemorySize, SM);
    cudaFuncSetAttribute(mma_gemm<false, true, true, false, false>, cudaFuncAttributeMaxDynamicSharedMemorySize, SM);

    const int GM = (NN + 127) / 128;

    // fork a side stream for the non-proj weight converts + CSR chain
    cudaStream_t sB;
    cudaEvent_t eFork, eJoin;
    cudaStreamCreateWithFlags(&sB, cudaStreamNonBlocking);
    cudaEventCreateWithFlags(&eFork, cudaEventDisableTiming);
    cudaEventCreateWithFlags(&eJoin, cudaEventDisableTiming);

    cudaEventRecord(eFork, 0);
    cudaStreamWaitEvent(sB, eFork, 0);

    // side stream: 8-slice weight convert (hidden under proj GEMM) + degree + CSR build
    {
        WCon10 P8;
        P8.s[0] = { Wl0_ui, wl0ui, HD, HD, 128 };
        P8.s[1] = { Wr0_ui, wr0ui, HD, HD, 128 };
        P8.s[2] = { Wl0_iu, wl0iu, HD, HD, 128 };
        P8.s[3] = { Wr0_iu, wr0iu, HD, HD, 128 };
        P8.s[4] = { Wl1_ui, w1u,            HD, OD, 128 };
        P8.s[5] = { Wr1_iu, w1u + 64 * 128, HD, OD, 128 };
        P8.s[6] = { Wl1_iu, w1i,            HD, OD, 128 };
        P8.s[7] = { Wr1_ui, w1i + 64 * 128, HD, OD, 128 };
        P8.s[8] = P8.s[0]; P8.s[9] = P8.s[0];
        dim3 g((128 * 128 + 255) / 256, 8);
        wconv_kernel<<<g, 256, 0, sB>>>(P8);

        dim3 ge((E + 255) / 256, 2);
        zero_cnt_kernel<<<(2 * NN + 255) / 256, 256, 0, sB>>>(cnt);
        count_kernel<<<ge, 256, 0, sB>>>(edge_iu + E, edge_ui + E, E, cnt);
        scan_part_kernel<<<dim3(NBLK, 2), 256, 0, sB>>>(cnt, part);
        scan_partials_kernel<<<dim3(1, 2), 512, 0, sB>>>(part, NBLK);
        scan_final_kernel<<<dim3(NBLK, 2), 256, 0, sB>>>(cnt, part, off, pos);
        build_csr_kernel<<<ge, 256, 0, sB>>>(edge_iu, edge_ui, E, pos, csr_iu, csr_ui);
        cudaEventRecord(eJoin, sB);
    }

    // main stream: proj weight convert (2 slices) + projection GEMM pair
    {
        WCon10 P2;
        P2.s[0] = { Wp_u, wpu, FU, HD, 128 };
        P2.s[1] = { Wp_i, wpi, FI, HD, 192 };
        P2.s[2] = P2.s[0]; P2.s[3] = P2.s[0]; P2.s[4] = P2.s[0];
        P2.s[5] = P2.s[0]; P2.s[6] = P2.s[0]; P2.s[7] = P2.s[0];
        P2.s[8] = P2.s[0]; P2.s[9] = P2.s[0];
        dim3 g((192 * 128 + 255) / 256, 2);
        wconv_kernel<<<g, 256>>>(P2);
    }
    {
        GSide su = { x_user, nullptr, nullptr, wpu, FU, 128, nullptr, 0,
                     bp_u, nullptr, nullptr, hu, nullptr };
        GSide si = { x_item, nullptr, nullptr, wpi, FI, 192, nullptr, 0,
                     bp_i, nullptr, nullptr, hi, nullptr };
        mma_gemm<false, false, false, false, true><<<dim3(GM, 2), 256, SM>>>(su, si, NN);
    }

    // join: gather needs CSR + proj outputs; layer0 GEMM needs side-stream weights
    cudaStreamWaitEvent(0, eJoin, 0);

    // layer 0 aggregation (fp16 in/out). t=0: agg_u <- hi via csr_iu; t=1: agg_i <- hu via csr_ui
    {
        const long tot = (long)NN * 32;
        dim3 gg((unsigned)((tot + 255) / 256), 2);
        gather_mean_kernel<<<gg, 256>>>(hi, csr_iu, agg_u, hu, csr_ui, agg_i, off, cnt);
    }

    // layer 0 fused dual-GEMM + bias + LN + ReLU -> fp16 h1 planes (A1=agg fp16, A2=root fp16)
    {
        GSide si = { nullptr, agg_i, hi, wl0ui, HD, 128, wr0ui, 128,
                     bl0_ui, g0_i, b0_i, hi1, nullptr };
        GSide su = { nullptr, agg_u, hu, wl0iu, HD, 128, wr0iu, 128,
                     bl0_iu, g0_u, b0_u, hu1, nullptr };
        mma_gemm<true, true, false, true, true><<<dim3(GM, 2), 256, SM>>>(si, su, NN);
    }

    // layer 1 combined GEMM pair: [proj|root] = h1 @ [Wl1 | Wr1], fp16 A plane, split fp16 outputs
    {
        GSide su = { nullptr, hu1, nullptr, w1u, HD, 128, nullptr, 0,
                     nullptr, nullptr, nullptr, proj_u, root_u };
        GSide si = { nullptr, hi1, nullptr, w1i, HD, 128, nullptr, 0,
                     nullptr, nullptr, nullptr, proj_i, root_i };
        mma_gemm<false, true, true, false, false><<<dim3(GM, 2), 256, SM>>>(su, si, NN);
    }

    // fused layer-1 gather + final LN (fp16 proj/root)
    {
        FSide fu = { proj_i, root_u, csr_iu, bl1_iu, g1_u, b1_u, out_u };
        FSide fi = { proj_u, root_i, csr_ui, bl1_ui, g1_i, b1_i, out_i };
        dim3 gf((NN + 7) / 8, 2);
        final_fused_kernel<<<gf, 256>>>(fu, fi, off, cnt);
    }

    (void)n_in; (void)out_size; (void)in_sizes;
}

// round 15
// speedup vs baseline: 1.9116x; 1.0675x over previous
#include <cuda_runtime.h>
#include <cuda_fp16.h>
#include <cstdint>

// ---------------- problem constants ----------------
#define NU 100000
#define NI 100000
#define NN 100000   // NU == NI
#define FU 96
#define FI 160
#define HD 128
#define OD 64
#define EMAX 600000
#define NBLK 391   // ceil(100000/256)

// ---------------- scratch (device globals) ----------------
__device__ __half g_hu   [NN * HD];   // fp16 proj planes (gather input + layer0 root)
__device__ __half g_hi   [NN * HD];
__device__ __half g_agg_u[NN * HD];   // fp16 agg planes (gather output = layer0 A)
__device__ __half g_agg_i[NN * HD];
__device__ __half g_proj_u[NN * OD];  // fp16 layer-1 outputs
__device__ __half g_root_u[NN * OD];
__device__ __half g_proj_i[NN * OD];
__device__ __half g_root_i[NN * OD];
__device__ int    g_cnt [2 * NN];
__device__ int    g_off [2 * NN];
__device__ int    g_pos [2 * NN];
__device__ int    g_csr_iu[EMAX];
__device__ int    g_csr_ui[EMAX];
__device__ int    g_part[2 * 512];

// transposed fp16 weights: layout [N rows, Kpad cols], zero padded
__device__ __half g_wpu[128 * 128];
__device__ __half g_wpi[128 * 192];
__device__ __half g_wl0ui[128 * 128];
__device__ __half g_wr0ui[128 * 128];
__device__ __half g_wl0iu[128 * 128];
__device__ __half g_wr0iu[128 * 128];
__device__ __half g_w1u[128 * 128];   // [Wl1_ui | Wr1_iu]
__device__ __half g_w1i[128 * 128];   // [Wl1_iu | Wr1_ui]

// ---------------- helpers ----------------
__device__ __forceinline__ uint32_t smem_u32(const void* p) {
    uint32_t a;
    asm("{ .reg .u64 t; cvta.to.shared.u64 t, %1; cvt.u32.u64 %0, t; }" : "=r"(a) : "l"(p));
    return a;
}
#define SWZ(x) ((x) ^ (((x) >> 3) & 0x70))

#define CPA16(dst, src) \
    asm volatile("cp.async.ca.shared.global [%0], [%1], 16;" :: "r"(dst), "l"(src) : "memory")
#define CPA_COMMIT() asm volatile("cp.async.commit_group;" ::: "memory")
#define CPA_WAIT1()  asm volatile("cp.async.wait_group 1;" ::: "memory")
#define CPA_WAIT0()  asm volatile("cp.async.wait_group 0;" ::: "memory")

__device__ __forceinline__ void ldm4(uint32_t* r, uint32_t addr) {
    asm volatile("ldmatrix.sync.aligned.m8n8.x4.shared.b16 {%0,%1,%2,%3}, [%4];"
        : "=r"(r[0]), "=r"(r[1]), "=r"(r[2]), "=r"(r[3]) : "r"(addr));
}
__device__ __forceinline__ void mma_fp16(float* c, const uint32_t* a, uint32_t b0, uint32_t b1) {
    asm volatile("mma.sync.aligned.m16n8k16.row.col.f32.f16.f16.f32 "
        "{%0,%1,%2,%3}, {%4,%5,%6,%7}, {%8,%9}, {%0,%1,%2,%3};"
        : "+f"(c[0]), "+f"(c[1]), "+f"(c[2]), "+f"(c[3])
        : "r"(a[0]), "r"(a[1]), "r"(a[2]), "r"(a[3]), "r"(b0), "r"(b1));
}
__device__ __forceinline__ uint32_t pack_h2(float x0, float x1) {
    __half2 h = __floats2half2_rn(x0, x1);
    return *reinterpret_cast<uint32_t*>(&h);
}

// ---------------- CSR build chain ----------------
__global__ void zero_cnt_kernel(int* __restrict__ cnt) {
    int i = blockIdx.x * blockDim.x + threadIdx.x;
    if (i < 2 * NN) cnt[i] = 0;
}

__global__ void count_kernel(const int* __restrict__ dst0, const int* __restrict__ dst1,
                             int E, int* __restrict__ cnt) {
    int t = blockIdx.y;
    const int* dst = t ? dst1 : dst0;
    int* c = cnt + t * NN;
    int e = blockIdx.x * blockDim.x + threadIdx.x;
    if (e < E) atomicAdd(&c[dst[e]], 1);
}

__global__ void scan_part_kernel(const int* __restrict__ cnt, int* __restrict__ part) {
    __shared__ int sh[256];
    const int* c = cnt + blockIdx.y * NN;
    int* p = part + blockIdx.y * 512;
    int i = blockIdx.x * 256 + threadIdx.x;
    sh[threadIdx.x] = (i < NN) ? c[i] : 0;
    __syncthreads();
    for (int s = 128; s > 0; s >>= 1) {
        if (threadIdx.x < s) sh[threadIdx.x] += sh[threadIdx.x + s];
        __syncthreads();
    }
    if (threadIdx.x == 0) p[blockIdx.x] = sh[0];
}

__global__ void scan_partials_kernel(int* __restrict__ part, int nb) {
    __shared__ int sh[512];
    int* p = part + blockIdx.y * 512;
    int t = threadIdx.x;
    int v = (t < nb) ? p[t] : 0;
    sh[t] = v;
    __syncthreads();
    for (int o = 1; o < 512; o <<= 1) {
        int x = (t >= o) ? sh[t - o] : 0;
        __syncthreads();
        sh[t] += x;
        __syncthreads();
    }
    if (t < nb) p[t] = sh[t] - v;  // exclusive
}

__global__ void scan_final_kernel(const int* __restrict__ cnt, const int* __restrict__ part,
                                  int* __restrict__ off, int* __restrict__ pos) {
    __shared__ int sh[256];
    const int* c = cnt + blockIdx.y * NN;
    const int* p = part + blockIdx.y * 512;
    int* of = off + blockIdx.y * NN;
    int* ps = pos + blockIdx.y * NN;
    int t = threadIdx.x;
    int i = blockIdx.x * 256 + t;
    int v = (i < NN) ? c[i] : 0;
    sh[t] = v;
    __syncthreads();
    for (int o = 1; o < 256; o <<= 1) {
        int x = (t >= o) ? sh[t - o] : 0;
        __syncthreads();
        sh[t] += x;
        __syncthreads();
    }
    if (i < NN) {
        int e = sh[t] - v + p[blockIdx.x];
        of[i] = e;
        ps[i] = e;
    }
}

__global__ void build_csr_kernel(const int* __restrict__ e0, const int* __restrict__ e1,
                                 int E, int* __restrict__ pos,
                                 int* __restrict__ c0, int* __restrict__ c1) {
    int t = blockIdx.y;
    const int* edge = t ? e1 : e0;
    int* ps = pos + t * NN;
    int* csr = t ? c1 : c0;
    int e = blockIdx.x * blockDim.x + threadIdx.x;
    if (e < E) {
        int s = edge[e];
        int d = edge[E + e];
        int idx = atomicAdd(&ps[d], 1);
        csr[idx] = s;
    }
}

// ---------------- gather-mean aggregation (layer 0, C=128), fp16 in / fp16 out ----------------
__global__ void gather_mean_kernel(const __half* __restrict__ fA, const int* __restrict__ csrA, __half* __restrict__ oA,
                                   const __half* __restrict__ fB, const int* __restrict__ csrB, __half* __restrict__ oB,
                                   const int* __restrict__ off, const int* __restrict__ cnt) {
    constexpr int G = 32;
    const int t = blockIdx.y;
    const __half* feat = t ? fB : fA;
    const int* csr = t ? csrB : csrA;
    __half* out = t ? oB : oA;
    const int* of = off + t * NN;
    const int* cn = cnt + t * NN;

    int gid = (int)((blockIdx.x * (size_t)blockDim.x + threadIdx.x) / G);
    if (gid >= NN) return;
    const int c4 = (threadIdx.x & (G - 1)) * 4;
    const int beg = __ldg(&of[gid]);
    const int deg = __ldg(&cn[gid]);

    float4 a0 = make_float4(0.f, 0.f, 0.f, 0.f);
    float4 a1 = make_float4(0.f, 0.f, 0.f, 0.f);
    float4 a2 = make_float4(0.f, 0.f, 0.f, 0.f);
    float4 a3 = make_float4(0.f, 0.f, 0.f, 0.f);
    int e = 0;
    for (; e + 3 < deg; e += 4) {
        int s0 = __ldg(&csr[beg + e]);
        int s1 = __ldg(&csr[beg + e + 1]);
        int s2 = __ldg(&csr[beg + e + 2]);
        int s3 = __ldg(&csr[beg + e + 3]);
        const __half2* p0 = (const __half2*)(feat + (size_t)s0 * HD + c4);
        const __half2* p1 = (const __half2*)(feat + (size_t)s1 * HD + c4);
        const __half2* p2 = (const __half2*)(feat + (size_t)s2 * HD + c4);
        const __half2* p3 = (const __half2*)(feat + (size_t)s3 * HD + c4);
        float2 u0 = __half22float2(p0[0]), w0 = __half22float2(p0[1]);
        float2 u1 = __half22float2(p1[0]), w1 = __half22float2(p1[1]);
        float2 u2 = __half22float2(p2[0]), w2 = __half22float2(p2[1]);
        float2 u3 = __half22float2(p3[0]), w3 = __half22float2(p3[1]);
        a0.x += u0.x; a0.y += u0.y; a0.z += w0.x; a0.w += w0.y;
        a1.x += u1.x; a1.y += u1.y; a1.z += w1.x; a1.w += w1.y;
        a2.x += u2.x; a2.y += u2.y; a2.z += w2.x; a2.w += w2.y;
        a3.x += u3.x; a3.y += u3.y; a3.z += w3.x; a3.w += w3.y;
    }
    for (; e < deg; e++) {
        int s0 = __ldg(&csr[beg + e]);
        const __half2* p0 = (const __half2*)(feat + (size_t)s0 * HD + c4);
        float2 u0 = __half22float2(p0[0]), w0 = __half22float2(p0[1]);
        a0.x += u0.x; a0.y += u0.y; a0.z += w0.x; a0.w += w0.y;
    }
    const float sc = 1.0f / fmaxf((float)deg, 1.0f);
    uint2 r;
    r.x = pack_h2((a0.x + a1.x + a2.x + a3.x) * sc, (a0.y + a1.y + a2.y + a3.y) * sc);
    r.y = pack_h2((a0.z + a1.z + a2.z + a3.z) * sc, (a0.w + a1.w + a2.w + a3.w) * sc);
    *(uint2*)(out + (size_t)gid * HD + c4) = r;
}

// ---------------- fused layer-1 gather + final LN (fp16 proj/root inputs) ----------------
struct FSide { const __half* proj_src; const __half* root; const int* csr;
               const float* bias; const float* g; const float* b; float* out; };
__global__ void final_fused_kernel(FSide f0, FSide f1, const int* __restrict__ off, const int* __restrict__ cnt) {
    const int t = blockIdx.y;
    FSide s = t ? f1 : f0;
    const int* of = off + t * NN;
    const int* cn = cnt + t * NN;
    const int warp = threadIdx.x >> 5;
    const int lane = threadIdx.x & 31;
    const int row = blockIdx.x * 8 + warp;
    if (row >= NN) return;
    const int c = lane * 2;
    const int beg = __ldg(&of[row]);
    const int deg = __ldg(&cn[row]);

    float x0 = 0.f, y0 = 0.f, x1 = 0.f, y1 = 0.f;
    int e = 0;
    for (; e + 1 < deg; e += 2) {
        int s0 = __ldg(&s.csr[beg + e]);
        int s1 = __ldg(&s.csr[beg + e + 1]);
        float2 v0 = __half22float2(*(const __half2*)(s.proj_src + (size_t)s0 * OD + c));
        float2 v1 = __half22float2(*(const __half2*)(s.proj_src + (size_t)s1 * OD + c));
        x0 += v0.x; y0 += v0.y;
        x1 += v1.x; y1 += v1.y;
    }
    if (e < deg) {
        int s0 = __ldg(&s.csr[beg + e]);
        float2 v0 = __half22float2(*(const __half2*)(s.proj_src + (size_t)s0 * OD + c));
        x0 += v0.x; y0 += v0.y;
    }
    const float sc = 1.0f / fmaxf((float)deg, 1.0f);
    float2 rv = __half22float2(*(const __half2*)(s.root + (size_t)row * OD + c));
    float2 bv = __ldg((const float2*)(s.bias + c));
    float v0 = (x0 + x1) * sc + rv.x + bv.x;
    float v1 = (y0 + y1) * sc + rv.y + bv.y;

    float s1v = v0 + v1;
    float s2v = v0 * v0 + v1 * v1;
#pragma unroll
    for (int o = 16; o > 0; o >>= 1) {
        s1v += __shfl_xor_sync(0xFFFFFFFFu, s1v, o);
        s2v += __shfl_xor_sync(0xFFFFFFFFu, s2v, o);
    }
    float mean = s1v * (1.0f / 64.0f);
    float var = s2v * (1.0f / 64.0f) - mean * mean;
    float rstd = rsqrtf(var + 1e-5f);
    float2 gv = __ldg((const float2*)(s.g + c));
    float2 bb = __ldg((const float2*)(s.b + c));
    float2 o2;
    o2.x = (v0 - mean) * rstd * gv.x + bb.x;
    o2.y = (v1 - mean) * rstd * gv.y + bb.y;
    *(float2*)(s.out + (size_t)row * 64 + c) = o2;
}

// weight transpose to fp16: W [K,N] fp32 -> Wt [N,Kpad] fp16, zero pad
struct WCon { const float* w; __half* h; int K, N, Kpad; };
struct WCon10 { WCon s[10]; };
__global__ void wconv_kernel(WCon10 P) {
    WCon w = P.s[blockIdx.y];
    int idx = blockIdx.x * blockDim.x + threadIdx.x;
    if (idx >= w.N * w.Kpad) return;
    int n = idx / w.Kpad, k = idx % w.Kpad;
    float x = (k < w.K) ? w.w[(size_t)k * w.N + n] : 0.0f;
    w.h[idx] = __float2half(x);
}

// ---------------- HMMA fp16 GEMM, BN=128, 4x2 warp tiling, paired via gridDim.y ----------------
// 1-pass fp16, A/B double-buffered prefetch pipeline.
// MEGA: after phase-1 (FUSE2 GEMM + bias + LN + ReLU), pack the 128x128 h1 tile to fp16 in the
// A smem buffers and run a second K=128 GEMM against W3 in-block; split-store fp16 proj/root.
#define BN 128

struct GSide {
    const float* A1; const __half* A1h; const __half* A2h;
    const __half* W1; int K1; int K1pad;
    const __half* W2; int K2pad;
    const __half* W3;
    const float* bias; const float* gamma; const float* beta;
    __half* outh; __half* outh2;
};

template <bool FUSE2, bool AHALF, bool MEGA, bool DO_LN, bool DO_RELU>
__global__ __launch_bounds__(256, 2)
void mma_gemm(GSide s0, GSide s1, int M) {
    const GSide& S = blockIdx.y ? s1 : s0;

    extern __shared__ char smem[];
    const uint32_t sb = smem_u32(smem);
    const uint32_t aBuf0 = sb;              // A: 2 x 16KB
    const uint32_t bBuf0 = sb + 32768;      // B: 2 x 16KB

    const int tid = threadIdx.x;
    const int warp = tid >> 5;
    const int lane = tid & 31;
    const int wm = warp & 3;
    const int wn = warp >> 2;
    const int r0 = blockIdx.x * 128;

    float acc[2][8][4];
#pragma unroll
    for (int mt = 0; mt < 2; mt++)
#pragma unroll
        for (int nt = 0; nt < 8; nt++)
#pragma unroll
            for (int j = 0; j < 4; j++) acc[mt][nt][j] = 0.0f;

    // staging mapping
    const int ar = tid >> 1;
    const int acb = (tid & 1) * 32;
    const int bn = tid >> 1;
    const int bq = tid & 1;

    // compute-phase lane constants
    const uint32_t a_off0 = (uint32_t)(wm * 32 + (lane & 15)) * 128;
    const uint32_t a_off1 = a_off0 + 16 * 128;
    const uint32_t a_xm = (lane & 7) * 16;
    const uint32_t a_khalf = ((lane >> 4) & 1) * 16;
    const uint32_t b_rowbase = (uint32_t)(wn * 64 + (lane & 7) + ((lane >> 4) & 1) * 8) * 128;
    const uint32_t b_xm = (lane & 7) * 16;
    const uint32_t b_khalf = ((lane >> 3) & 1) * 16;

    const int nch1 = S.K1pad >> 6;
    const int nch = nch1 + (FUSE2 ? (S.K2pad >> 6) : 0);

    auto issueB = [&](int c, int buf) {
        const __half* W;
        int k0, Kpad;
        if (!FUSE2 || c < nch1) { W = S.W1; k0 = c * 64; Kpad = S.K1pad; }
        else                    { W = S.W2; k0 = (c - nch1) * 64; Kpad = S.K2pad; }
        const uint32_t bB = bBuf0 + (uint32_t)buf * 16384;
#pragma unroll
        for (int i = 0; i < 4; i++) {
            const int ck = bq * 32 + i * 8;
            const size_t so = (size_t)bn * Kpad + k0 + ck;
            const uint32_t off = SWZ(bn * 128 + ck * 2);
            CPA16(bB + off, W + so);
        }
    };
    auto issueA = [&](int c, int buf) {   // AHALF only
        const __half* base;
        int k0;
        if (!FUSE2 || c < nch1) { base = S.A1h; k0 = c * 64; }
        else                    { base = S.A2h; k0 = (c - nch1) * 64; }
        const int grow = r0 + ar;
        const int srow = (grow < M) ? grow : 0;
        const __half* src = base + (size_t)srow * HD + k0 + acb;
        const uint32_t aB = aBuf0 + (uint32_t)buf * 16384;
#pragma unroll
        for (int i = 0; i < 4; i++) {
            const uint32_t off = SWZ(ar * 128 + (acb + i * 8) * 2);
            CPA16(aB + off, src + i * 8);
        }
    };
    auto stageA_sync = [&](int c, int buf) {   // fp32 convert path
        const int k0 = c * 64;
        const int K = S.K1;
        const int grow = r0 + ar;
        const float* arow = S.A1 + (size_t)grow * K;
        const uint32_t aB = aBuf0 + (uint32_t)buf * 16384;
#pragma unroll
        for (int i = 0; i < 4; i++) {
            const int cc = acb + i * 8;
            float x[8];
#pragma unroll
            for (int j = 0; j < 8; j++) x[j] = 0.0f;
            if (grow < M && (k0 + cc) < K) {
                float4 v0 = *(const float4*)(arow + k0 + cc);
                float4 v1 = *(const float4*)(arow + k0 + cc + 4);
                x[0] = v0.x; x[1] = v0.y; x[2] = v0.z; x[3] = v0.w;
                x[4] = v1.x; x[5] = v1.y; x[6] = v1.z; x[7] = v1.w;
            }
            uint32_t h4[4];
#pragma unroll
            for (int j = 0; j < 4; j++) h4[j] = pack_h2(x[2 * j], x[2 * j + 1]);
            const uint32_t off = SWZ(ar * 128 + cc * 2);
            asm volatile("st.shared.v4.b32 [%0], {%1, %2, %3, %4};" :: "r"(aB + off), "r"(h4[0]), "r"(h4[1]), "r"(h4[2]), "r"(h4[3]) : "memory");
        }
    };

    // prologue: stage chunk 0
    if (AHALF) issueA(0, 0);
    issueB(0, 0);
    CPA_COMMIT();

    for (int c = 0; c < nch; c++) {
        if (c) __syncthreads();

        if (!AHALF) stageA_sync(c, c & 1);

        if (c + 1 < nch) {
            if (AHALF) issueA(c + 1, (c + 1) & 1);
            issueB(c + 1, (c + 1) & 1);
            CPA_COMMIT();
            CPA_WAIT1();
        } else {
            CPA_WAIT0();
        }
        __syncthreads();

        // ---- compute(c) ----
        const uint32_t aC = aBuf0 + (uint32_t)(c & 1) * 16384;
        const uint32_t bC = bBuf0 + (uint32_t)(c & 1) * 16384;
#pragma unroll
        for (int ks = 0; ks < 4; ks++) {
            const uint32_t akb = ((uint32_t)(ks * 32) + a_khalf) ^ a_xm;
            uint32_t ah[2][4];
            ldm4(ah[0], aC + a_off0 + akb);
            ldm4(ah[1], aC + a_off1 + akb);
            const uint32_t bkb = ((uint32_t)(ks * 32) + b_khalf) ^ b_xm;
#pragma unroll
            for (int j = 0; j < 4; j++) {
                uint32_t bh[4];
                const uint32_t boff = b_rowbase + (uint32_t)j * 2048;
                ldm4(bh, bC + boff + bkb);
#pragma unroll
                for (int mt = 0; mt < 2; mt++) {
                    mma_fp16(acc[mt][2 * j],     ah[mt], bh[0], bh[1]);
                    mma_fp16(acc[mt][2 * j + 1], ah[mt], bh[2], bh[3]);
                }
            }
        }
    }

    // MEGA: prefetch phase-2 weights (W3, K=128 -> 2 chunks) while the epilogue runs
    if (MEGA) {
        __syncthreads();   // all warps done reading bBufs
#pragma unroll
        for (int c2 = 0; c2 < 2; c2++) {
            const uint32_t bB = bBuf0 + (uint32_t)c2 * 16384;
#pragma unroll
            for (int i = 0; i < 4; i++) {
                const int ck = bq * 32 + i * 8;
                const size_t so = (size_t)bn * 128 + c2 * 64 + ck;
                const uint32_t off = SWZ(bn * 128 + ck * 2);
                CPA16(bB + off, S.W3 + so);
            }
        }
        CPA_COMMIT();
    }

    // ---- epilogue (phase 1) ----
    const int rq = lane >> 2;
    const int cq = (lane & 3) * 2;

    if (S.bias) {
#pragma unroll
        for (int nt = 0; nt < 8; nt++) {
            float2 bv = __ldg((const float2*)(S.bias + wn * 64 + nt * 8 + cq));
#pragma unroll
            for (int mt = 0; mt < 2; mt++) {
                acc[mt][nt][0] += bv.x; acc[mt][nt][1] += bv.y;
                acc[mt][nt][2] += bv.x; acc[mt][nt][3] += bv.y;
            }
        }
    }
    if (DO_LN) {
        float s1[2][2], s2[2][2];
#pragma unroll
        for (int mt = 0; mt < 2; mt++)
#pragma unroll
            for (int h = 0; h < 2; h++) { s1[mt][h] = 0.f; s2[mt][h] = 0.f; }
#pragma unroll
        for (int mt = 0; mt < 2; mt++)
#pragma unroll
            for (int nt = 0; nt < 8; nt++) {
                s1[mt][0] += acc[mt][nt][0] + acc[mt][nt][1];
                s2[mt][0] += acc[mt][nt][0] * acc[mt][nt][0] + acc[mt][nt][1] * acc[mt][nt][1];
                s1[mt][1] += acc[mt][nt][2] + acc[mt][nt][3];
                s2[mt][1] += acc[mt][nt][2] * acc[mt][nt][2] + acc[mt][nt][3] * acc[mt][nt][3];
            }
#pragma unroll
        for (int o = 1; o < 4; o <<= 1) {
#pragma unroll
            for (int mt = 0; mt < 2; mt++)
#pragma unroll
                for (int h = 0; h < 2; h++) {
                    s1[mt][h] += __shfl_xor_sync(0xFFFFFFFFu, s1[mt][h], o);
                    s2[mt][h] += __shfl_xor_sync(0xFFFFFFFFu, s2[mt][h], o);
                }
        }
        float* sc = (float*)smem;
        __syncthreads();
        if ((lane & 3) == 0) {
#pragma unroll
            for (int mt = 0; mt < 2; mt++)
#pragma unroll
                for (int h = 0; h < 2; h++) {
                    int rl = wm * 32 + mt * 16 + h * 8 + rq;
                    sc[wn * 128 + rl] = s1[mt][h];
                    sc[256 + wn * 128 + rl] = s2[mt][h];
                }
        }
        __syncthreads();
#pragma unroll
        for (int mt = 0; mt < 2; mt++)
#pragma unroll
            for (int h = 0; h < 2; h++) {
                int rl = wm * 32 + mt * 16 + h * 8 + rq;
                float S1 = sc[rl] + sc[128 + rl];
                float S2 = sc[256 + rl] + sc[384 + rl];
                float mean = S1 * (1.0f / 128.0f);
                float var = S2 * (1.0f / 128.0f) - mean * mean;
                float rstd = rsqrtf(var + 1e-5f);
                s1[mt][h] = mean;
                s2[mt][h] = rstd;
            }
#pragma unroll
        for (int nt = 0; nt < 8; nt++) {
            float2 g = __ldg((const float2*)(S.gamma + wn * 64 + nt * 8 + cq));
            float2 b = __ldg((const float2*)(S.beta + wn * 64 + nt * 8 + cq));
#pragma unroll
            for (int mt = 0; mt < 2; mt++) {
                acc[mt][nt][0] = (acc[mt][nt][0] - s1[mt][0]) * s2[mt][0] * g.x + b.x;
                acc[mt][nt][1] = (acc[mt][nt][1] - s1[mt][0]) * s2[mt][0] * g.y + b.y;
                acc[mt][nt][2] = (acc[mt][nt][2] - s1[mt][1]) * s2[mt][1] * g.x + b.x;
                acc[mt][nt][3] = (acc[mt][nt][3] - s1[mt][1]) * s2[mt][1] * g.y + b.y;
            }
        }
    }
    if (DO_RELU) {
#pragma unroll
        for (int mt = 0; mt < 2; mt++)
#pragma unroll
            for (int nt = 0; nt < 8; nt++)
#pragma unroll
                for (int j = 0; j < 4; j++) acc[mt][nt][j] = fmaxf(acc[mt][nt][j], 0.0f);
    }

    if (MEGA) {
        // ---- pack h1 tile (fp16) into A smem buffers: col<64 -> aBuf0, col>=64 -> aBuf1 ----
        __syncthreads();   // protect LN scratch reads before overwrite
        const uint32_t aDst = aBuf0 + (uint32_t)wn * 16384;
#pragma unroll
        for (int mt = 0; mt < 2; mt++)
#pragma unroll
            for (int h = 0; h < 2; h++) {
                const int rl = wm * 32 + mt * 16 + h * 8 + rq;
#pragma unroll
                for (int nt = 0; nt < 8; nt++) {
                    const uint32_t off = SWZ((uint32_t)rl * 128 + (nt * 8 + cq) * 2);
                    asm volatile("st.shared.b32 [%0], %1;"
                        :: "r"(aDst + off), "r"(pack_h2(acc[mt][nt][2 * h], acc[mt][nt][2 * h + 1])) : "memory");
                }
            }
        __syncthreads();
        CPA_WAIT0();   // W3 chunks landed

        // ---- phase 2: [proj|root] = h1_tile @ W3, K=128 (2 chunks) ----
#pragma unroll
        for (int mt = 0; mt < 2; mt++)
#pragma unroll
            for (int nt = 0; nt < 8; nt++)
#pragma unroll
                for (int j = 0; j < 4; j++) acc[mt][nt][j] = 0.0f;
#pragma unroll
        for (int c2 = 0; c2 < 2; c2++) {
            const uint32_t aC = aBuf0 + (uint32_t)c2 * 16384;
            const uint32_t bC = bBuf0 + (uint32_t)c2 * 16384;
#pragma unroll
            for (int ks = 0; ks < 4; ks++) {
                const uint32_t akb = ((uint32_t)(ks * 32) + a_khalf) ^ a_xm;
                uint32_t ah[2][4];
                ldm4(ah[0], aC + a_off0 + akb);
                ldm4(ah[1], aC + a_off1 + akb);
                const uint32_t bkb = ((uint32_t)(ks * 32) + b_khalf) ^ b_xm;
#pragma unroll
                for (int j = 0; j < 4; j++) {
                    uint32_t bh[4];
                    const uint32_t boff = b_rowbase + (uint32_t)j * 2048;
                    ldm4(bh, bC + boff + bkb);
#pragma unroll
                    for (int mt = 0; mt < 2; mt++) {
                        mma_fp16(acc[mt][2 * j],     ah[mt], bh[0], bh[1]);
                        mma_fp16(acc[mt][2 * j + 1], ah[mt], bh[2], bh[3]);
                    }
                }
            }
        }
        // split store: wn==0 -> outh (proj), wn==1 -> outh2 (root); both stride 64
        __half* dst = wn ? S.outh2 : S.outh;
#pragma unroll
        for (int mt = 0; mt < 2; mt++)
#pragma unroll
            for (int h = 0; h < 2; h++) {
                int row = r0 + wm * 32 + mt * 16 + h * 8 + rq;
                if (row < M) {
#pragma unroll
                    for (int nt = 0; nt < 8; nt++)
                        *(uint32_t*)(dst + (size_t)row * 64 + nt * 8 + cq) =
                            pack_h2(acc[mt][nt][2 * h], acc[mt][nt][2 * h + 1]);
                }
            }
    } else {
        // plain fp16 plane store (stride 128)
#pragma unroll
        for (int mt = 0; mt < 2; mt++)
#pragma unroll
            for (int h = 0; h < 2; h++) {
                int row = r0 + wm * 32 + mt * 16 + h * 8 + rq;
                if (row < M) {
#pragma unroll
                    for (int nt = 0; nt < 8; nt++)
                        *(uint32_t*)(S.outh + (size_t)row * BN + wn * 64 + nt * 8 + cq) =
                            pack_h2(acc[mt][nt][2 * h], acc[mt][nt][2 * h + 1]);
                }
            }
    }
}

// ---------------- host launcher ----------------
extern "C" void kernel_launch(void* const* d_in, const int* in_sizes, int n_in,
                              void* d_out, int out_size) {
    const float* x_user = (const float*)d_in[0];
    const float* x_item = (const float*)d_in[1];
    const int* edge_ui = (const int*)d_in[2];
    const int* edge_iu = (const int*)d_in[3];
    const float* Wp_u = (const float*)d_in[4];
    const float* bp_u = (const float*)d_in[5];
    const float* Wp_i = (const float*)d_in[6];
    const float* bp_i = (const float*)d_in[7];
    const float* Wl0_ui = (const float*)d_in[8];
    const float* bl0_ui = (const float*)d_in[9];
    const float* Wr0_ui = (const float*)d_in[10];
    const float* Wl0_iu = (const float*)d_in[11];
    const float* bl0_iu = (const float*)d_in[12];
    const float* Wr0_iu = (const float*)d_in[13];
    const float* g0_u = (const float*)d_in[14];
    const float* b0_u = (const float*)d_in[15];
    const float* g0_i = (const float*)d_in[16];
    const float* b0_i = (const float*)d_in[17];
    const float* Wl1_ui = (const float*)d_in[18];
    const float* bl1_ui = (const float*)d_in[19];
    const float* Wr1_ui = (const float*)d_in[20];
    const float* Wl1_iu = (const float*)d_in[21];
    const float* bl1_iu = (const float*)d_in[22];
    const float* Wr1_iu = (const float*)d_in[23];
    const float* g1_u = (const float*)d_in[24];
    const float* b1_u = (const float*)d_in[25];
    const float* g1_i = (const float*)d_in[26];
    const float* b1_i = (const float*)d_in[27];

    const int E = in_sizes[2] / 2;

    __half *hu, *hi, *agg_u, *agg_i, *proj_u, *root_u, *proj_i, *root_i;
    int *cnt, *off, *pos, *csr_iu, *csr_ui, *part;
    cudaGetSymbolAddress((void**)&hu, g_hu);
    cudaGetSymbolAddress((void**)&hi, g_hi);
    cudaGetSymbolAddress((void**)&agg_u, g_agg_u);
    cudaGetSymbolAddress((void**)&agg_i, g_agg_i);
    cudaGetSymbolAddress((void**)&proj_u, g_proj_u);
    cudaGetSymbolAddress((void**)&root_u, g_root_u);
    cudaGetSymbolAddress((void**)&proj_i, g_proj_i);
    cudaGetSymbolAddress((void**)&root_i, g_root_i);
    cudaGetSymbolAddress((void**)&cnt, g_cnt);
    cudaGetSymbolAddress((void**)&off, g_off);
    cudaGetSymbolAddress((void**)&pos, g_pos);
    cudaGetSymbolAddress((void**)&csr_iu, g_csr_iu);
    cudaGetSymbolAddress((void**)&csr_ui, g_csr_ui);
    cudaGetSymbolAddress((void**)&part, g_part);

    __half *wpu, *wpi, *wl0ui, *wr0ui, *wl0iu, *wr0iu, *w1u, *w1i;
    cudaGetSymbolAddress((void**)&wpu, g_wpu);
    cudaGetSymbolAddress((void**)&wpi, g_wpi);
    cudaGetSymbolAddress((void**)&wl0ui, g_wl0ui);
    cudaGetSymbolAddress((void**)&wr0ui, g_wr0ui);
    cudaGetSymbolAddress((void**)&wl0iu, g_wl0iu);
    cudaGetSymbolAddress((void**)&wr0iu, g_wr0iu);
    cudaGetSymbolAddress((void**)&w1u, g_w1u);
    cudaGetSymbolAddress((void**)&w1i, g_w1i);

    float* out_u = (float*)d_out;
    float* out_i = (float*)d_out + (size_t)NN * OD;

    const int SM = 65536;   // A 2x16KB + B 2x16KB
    cudaFuncSetAttribute(mma_gemm<false, false, false, false, true>, cudaFuncAttributeMaxDynamicSharedMemorySize, SM);
    cudaFuncSetAttribute(mma_gemm<true, true, true, true, true>, cudaFuncAttributeMaxDynamicSharedMemorySize, SM);

    const int GM = (NN + 127) / 128;

    // fork a side stream for the non-proj weight converts + CSR chain
    cudaStream_t sB;
    cudaEvent_t eFork, eJoin;
    cudaStreamCreateWithFlags(&sB, cudaStreamNonBlocking);
    cudaEventCreateWithFlags(&eFork, cudaEventDisableTiming);
    cudaEventCreateWithFlags(&eJoin, cudaEventDisableTiming);

    cudaEventRecord(eFork, 0);
    cudaStreamWaitEvent(sB, eFork, 0);

    // side stream: 8-slice weight convert + degree + CSR build
    {
        WCon10 P8;
        P8.s[0] = { Wl0_ui, wl0ui, HD, HD, 128 };
        P8.s[1] = { Wr0_ui, wr0ui, HD, HD, 128 };
        P8.s[2] = { Wl0_iu, wl0iu, HD, HD, 128 };
        P8.s[3] = { Wr0_iu, wr0iu, HD, HD, 128 };
        P8.s[4] = { Wl1_ui, w1u,            HD, OD, 128 };
        P8.s[5] = { Wr1_iu, w1u + 64 * 128, HD, OD, 128 };
        P8.s[6] = { Wl1_iu, w1i,            HD, OD, 128 };
        P8.s[7] = { Wr1_ui, w1i + 64 * 128, HD, OD, 128 };
        P8.s[8] = P8.s[0]; P8.s[9] = P8.s[0];
        dim3 g((128 * 128 + 255) / 256, 8);
        wconv_kernel<<<g, 256, 0, sB>>>(P8);

        dim3 ge((E + 255) / 256, 2);
        zero_cnt_kernel<<<(2 * NN + 255) / 256, 256, 0, sB>>>(cnt);
        count_kernel<<<ge, 256, 0, sB>>>(edge_iu + E, edge_ui + E, E, cnt);
        scan_part_kernel<<<dim3(NBLK, 2), 256, 0, sB>>>(cnt, part);
        scan_partials_kernel<<<dim3(1, 2), 512, 0, sB>>>(part, NBLK);
        scan_final_kernel<<<dim3(NBLK, 2), 256, 0, sB>>>(cnt, part, off, pos);
        build_csr_kernel<<<ge, 256, 0, sB>>>(edge_iu, edge_ui, E, pos, csr_iu, csr_ui);
        cudaEventRecord(eJoin, sB);
    }

    // main stream: proj weight convert (2 slices) + projection GEMM pair
    {
        WCon10 P2;
        P2.s[0] = { Wp_u, wpu, FU, HD, 128 };
        P2.s[1] = { Wp_i, wpi, FI, HD, 192 };
        P2.s[2] = P2.s[0]; P2.s[3] = P2.s[0]; P2.s[4] = P2.s[0];
        P2.s[5] = P2.s[0]; P2.s[6] = P2.s[0]; P2.s[7] = P2.s[0];
        P2.s[8] = P2.s[0]; P2.s[9] = P2.s[0];
        dim3 g((192 * 128 + 255) / 256, 2);
        wconv_kernel<<<g, 256>>>(P2);
    }
    {
        GSide su = { x_user, nullptr, nullptr, wpu, FU, 128, nullptr, 0, nullptr,
                     bp_u, nullptr, nullptr, hu, nullptr };
        GSide si = { x_item, nullptr, nullptr, wpi, FI, 192, nullptr, 0, nullptr,
                     bp_i, nullptr, nullptr, hi, nullptr };
        mma_gemm<false, false, false, false, true><<<dim3(GM, 2), 256, SM>>>(su, si, NN);
    }

    // join: gather needs CSR + proj outputs; MEGA needs side-stream weights
    cudaStreamWaitEvent(0, eJoin, 0);

    // layer 0 aggregation (fp16 in/out). t=0: agg_u <- hi via csr_iu; t=1: agg_i <- hu via csr_ui
    {
        const long tot = (long)NN * 32;
        dim3 gg((unsigned)((tot + 255) / 256), 2);
        gather_mean_kernel<<<gg, 256>>>(hi, csr_iu, agg_u, hu, csr_ui, agg_i, off, cnt);
    }

    // MEGA: layer-0 fused dual-GEMM + bias + LN + ReLU, then in-block layer-1 GEMM -> proj/root fp16
    {
        GSide si = { nullptr, agg_i, hi, wl0ui, HD, 128, wr0ui, 128, w1i,
                     bl0_ui, g0_i, b0_i, proj_i, root_i };
        GSide su = { nullptr, agg_u, hu, wl0iu, HD, 128, wr0iu, 128, w1u,
                     bl0_iu, g0_u, b0_u, proj_u, root_u };
        mma_gemm<true, true, true, true, true><<<dim3(GM, 2), 256, SM>>>(si, su, NN);
    }

    // fused layer-1 gather + final LN (fp16 proj/root)
    {
        FSide fu = { proj_i, root_u, csr_iu, bl1_iu, g1_u, b1_u, out_u };
        FSide fi = { proj_u, root_i, csr_ui, bl1_ui, g1_i, b1_i, out_i };
        dim3 gf((NN + 7) / 8, 2);
        final_fused_kernel<<<gf, 256>>>(fu, fi, off, cnt);
    }

    (void)n_in; (void)out_size; (void)in_sizes;
}